// round 6
// baseline (speedup 1.0000x reference)
#include <cuda_runtime.h>
#include <cuda_bf16.h>
#include <math.h>
#include <stdint.h>

// Problem constants
#define BB   2
#define SS   2048
#define DD   1024
#define HH   16
#define DHD  64
#define MR   (BB*SS)        // 4096
#define NC   (HH*DHD)       // 1024
#define WN   (HH*DD*DHD)    // 1048576

// ---------------------------------------------------------------- helpers
__device__ __forceinline__ uint32_t smem_u32(const void* p) {
    uint32_t a;
    asm("{ .reg .u64 t; cvta.to.shared.u64 t, %1; cvt.u32.u64 %0, t; }" : "=r"(a) : "l"(p));
    return a;
}

#define CP_ASYNC16(dst, src) asm volatile("cp.async.cg.shared.global [%0], [%1], 16;" :: "r"(dst), "l"(src))
#define CP_COMMIT()  asm volatile("cp.async.commit_group;" ::: "memory")
#define CP_WAIT1()   asm volatile("cp.async.wait_group 1;" ::: "memory")
#define CP_WAIT0()   asm volatile("cp.async.wait_group 0;" ::: "memory")

#define LDSM_X4(r0, r1, r2, r3, addr) \
    asm volatile("ldmatrix.sync.aligned.m8n8.x4.shared.b16 {%0,%1,%2,%3}, [%4];" \
                 : "=r"(r0), "=r"(r1), "=r"(r2), "=r"(r3) : "r"(addr))

#define MMA_BF16(c, a, b0, b1) \
    asm volatile("mma.sync.aligned.m16n8k16.row.col.f32.bf16.bf16.f32 " \
                 "{%0,%1,%2,%3}, {%4,%5,%6,%7}, {%8,%9}, {%0,%1,%2,%3};" \
                 : "+f"((c)[0]), "+f"((c)[1]), "+f"((c)[2]), "+f"((c)[3]) \
                 : "r"((a)[0]), "r"((a)[1]), "r"((a)[2]), "r"((a)[3]), "r"(b0), "r"(b1))

// ---------------------------------------------------------------- scratch
__device__ unsigned g_amax[6];
__device__ __nv_bfloat16 g_Wqh[DD*NC], g_Wql[DD*NC];
__device__ __nv_bfloat16 g_Wkh[DD*NC], g_Wkl[DD*NC];
__device__ __nv_bfloat16 g_Wvh[DD*NC], g_Wvl[DD*NC];
__device__ __nv_bfloat16 g_Woh[NC*DD], g_Wol[NC*DD];
__device__ __nv_bfloat16 g_Xqh[(size_t)MR*DD], g_Xql[(size_t)MR*DD];
__device__ __nv_bfloat16 g_Xkh[(size_t)MR*DD], g_Xkl[(size_t)MR*DD];
__device__ __nv_bfloat16 g_Xvh[(size_t)MR*DD], g_Xvl[(size_t)MR*DD];
__device__ __nv_bfloat16 g_zh[(size_t)MR*NC],  g_zl[(size_t)MR*NC];
__device__ float g_bq[NC], g_bk[NC], g_bv[NC];
__device__ float g_q[(size_t)MR*NC], g_k[(size_t)MR*NC], g_v[(size_t)MR*NC], g_z[(size_t)MR*NC];
__device__ float g_sin[SS*32], g_cos[SS*32];

// ---------------------------------------------------------------- qdq
__device__ __forceinline__ float qdq(float w, float amax) {
    float scale = 448.0f / fmaxf(amax, 1e-12f);
    float v = w * scale;
    float a = fabsf(v);
    int ex;
    frexpf(fmaxf(a, 1e-30f), &ex);
    float e = fminf(fmaxf((float)(ex - 1), -6.0f), 8.0f);
    float step = exp2f(e - 3.0f);
    float q = rintf(v / step) * step;
    q = fminf(fmaxf(q, -448.0f), 448.0f);
    return q / scale;
}

__global__ void reset_kernel() {
    if (threadIdx.x < 6) g_amax[threadIdx.x] = 0u;
}

__global__ void amax_kernel(const float4* __restrict__ x, int n4, int slot) {
    __shared__ float red[256];
    float m = 0.0f;
    for (int i = blockIdx.x * blockDim.x + threadIdx.x; i < n4; i += gridDim.x * blockDim.x) {
        float4 v = x[i];
        m = fmaxf(m, fmaxf(fmaxf(fabsf(v.x), fabsf(v.y)), fmaxf(fabsf(v.z), fabsf(v.w))));
    }
    red[threadIdx.x] = m;
    __syncthreads();
    for (int s = 128; s > 0; s >>= 1) {
        if (threadIdx.x < s) red[threadIdx.x] = fmaxf(red[threadIdx.x], red[threadIdx.x + s]);
        __syncthreads();
    }
    if (threadIdx.x == 0) atomicMax(&g_amax[slot], __float_as_uint(red[0]));
}

__device__ __forceinline__ void split_bf16(float x, __nv_bfloat16& h, __nv_bfloat16& l) {
    h = __float2bfloat16(x);
    l = __float2bfloat16(x - __bfloat162float(h));
}

// qdq + transpose W[h,d,e] -> B[n=h*64+e][k=d], split into hi/lo bf16
__global__ void quant_w_t_kernel(const float* __restrict__ W,
                                 __nv_bfloat16* __restrict__ Bh, __nv_bfloat16* __restrict__ Bl,
                                 int slot) {
    __shared__ float t[32][33];
    float amax = __uint_as_float(g_amax[slot]);
    int h = blockIdx.z;
    int d = blockIdx.x * 32 + threadIdx.y;
    int e = blockIdx.y * 32 + threadIdx.x;
    t[threadIdx.y][threadIdx.x] = qdq(W[(size_t)h * DD * DHD + d * DHD + e], amax);
    __syncthreads();
    int n = h * DHD + blockIdx.y * 32 + threadIdx.y;
    int k = blockIdx.x * 32 + threadIdx.x;
    __nv_bfloat16 hi, lo;
    split_bf16(t[threadIdx.x][threadIdx.y], hi, lo);
    Bh[(size_t)n * DD + k] = hi;
    Bl[(size_t)n * DD + k] = lo;
}

// transpose WO[he][d] -> B[n=d][k=he], split (no qdq)
__global__ void wo_t_kernel(const float* __restrict__ W,
                            __nv_bfloat16* __restrict__ Bh, __nv_bfloat16* __restrict__ Bl) {
    __shared__ float t[32][33];
    int he = blockIdx.y * 32 + threadIdx.y;
    int d  = blockIdx.x * 32 + threadIdx.x;
    t[threadIdx.y][threadIdx.x] = W[(size_t)he * DD + d];
    __syncthreads();
    int n = blockIdx.x * 32 + threadIdx.y;   // d
    int k = blockIdx.y * 32 + threadIdx.x;   // he
    __nv_bfloat16 hi, lo;
    split_bf16(t[threadIdx.x][threadIdx.y], hi, lo);
    Bh[(size_t)n * NC + k] = hi;
    Bl[(size_t)n * NC + k] = lo;
}

__global__ void quant_b_kernel(const float* __restrict__ b, float* __restrict__ bt, int slot) {
    int idx = blockIdx.x * 256 + threadIdx.x;
    if (idx >= NC) return;
    float amax = __uint_as_float(g_amax[slot]);
    bt[idx] = qdq(b[idx], amax);
}

// fp32 -> bf16 hi/lo split (vectorized)
__global__ void split_kernel(const float4* __restrict__ x,
                             __nv_bfloat162* __restrict__ hi, __nv_bfloat162* __restrict__ lo,
                             int n4) {
    int i = blockIdx.x * 256 + threadIdx.x;
    if (i >= n4) return;
    float4 v = x[i];
    __nv_bfloat16 h0, h1, h2, h3, l0, l1, l2, l3;
    split_bf16(v.x, h0, l0);
    split_bf16(v.y, h1, l1);
    split_bf16(v.z, h2, l2);
    split_bf16(v.w, h3, l3);
    hi[2*i]   = __nv_bfloat162(h0, h1);
    hi[2*i+1] = __nv_bfloat162(h2, h3);
    lo[2*i]   = __nv_bfloat162(l0, l1);
    lo[2*i+1] = __nv_bfloat162(l2, l3);
}

// ---------------------------------------------------------------- rotary
__global__ void sincos_kernel() {
    int idx = blockIdx.x * 256 + threadIdx.x;
    if (idx >= SS * 32) return;
    int pos = idx >> 5, i = idx & 31;
    float invf = (float)pow(10000.0, -(double)i / 32.0);
    float ang  = (float)pos * invf;
    g_sin[idx] = (float)sin((double)ang);
    g_cos[idx] = (float)cos((double)ang);
}

__global__ void rotary_kernel(float* __restrict__ buf, float outscale) {
    int idx = blockIdx.x * 256 + threadIdx.x;
    if (idx >= MR * HH * 32) return;
    int bs  = idx / (HH * 32);
    int rem = idx % (HH * 32);
    int h = rem >> 5, i = rem & 31;
    int pos = bs & (SS - 1);
    size_t base = (size_t)bs * NC + h * DHD;
    float x0 = buf[base + i], x1 = buf[base + i + 32];
    float c = g_cos[pos * 32 + i], s = g_sin[pos * 32 + i];
    buf[base + i]      = (x0 * c - x1 * s) * outscale;
    buf[base + i + 32] = (x1 * c + x0 * s) * outscale;
}

// ---------------------------------------------------------------- HMMA GEMM
// C[M,N] = (Ah+Al)[M,K] * (Bh+Bl)[N,K]^T + bias[N]   (split-bf16, 3 passes)
// Tile 128x128, KC=32, double-buffered cp.async, mma.sync m16n8k16 bf16.
#define KC 32
#define PK 40                       // padded k stride (bf16) -> 80B rows, LDSM conflict-free
#define TILE_B (128 * PK * 2)       // 10240 bytes per operand tile
#define STAGE_B (4 * TILE_B)        // Ah, Al, Bh, Bl
#define GEMM_SMEM (2 * STAGE_B)     // 81920

__global__ void __launch_bounds__(256) tgemm_kernel(
        const __nv_bfloat16* __restrict__ Ah, const __nv_bfloat16* __restrict__ Al,
        const __nv_bfloat16* __restrict__ Bh, const __nv_bfloat16* __restrict__ Bl,
        const float* __restrict__ bias, float* __restrict__ C,
        int M, int N, int K) {
    extern __shared__ char sm[];
    uint32_t sb = smem_u32(sm);
    int tid = threadIdx.x;
    int lane = tid & 31, wid = tid >> 5;
    int wm = wid & 3, wn = wid >> 2;
    int bm = blockIdx.y, bn = blockIdx.x;

    const char* srcs[4] = {
        (const char*)(Ah + (size_t)bm * 128 * K),
        (const char*)(Al + (size_t)bm * 128 * K),
        (const char*)(Bh + (size_t)bn * 128 * K),
        (const char*)(Bl + (size_t)bn * 128 * K) };

    auto fill = [&](int s, int kc) {
        uint32_t base = sb + s * STAGE_B;
        size_t koff = (size_t)kc * KC * 2;
#pragma unroll
        for (int t = tid; t < 2048; t += 256) {
            int arr = t >> 9;
            int idx = t & 511;
            int row = idx >> 2, c = idx & 3;
            CP_ASYNC16(base + arr * TILE_B + row * (PK * 2) + c * 16,
                       srcs[arr] + (size_t)row * K * 2 + koff + c * 16);
        }
        CP_COMMIT();
    };

    float acc[2][8][4];
#pragma unroll
    for (int i = 0; i < 2; i++)
#pragma unroll
        for (int j = 0; j < 8; j++)
#pragma unroll
            for (int r = 0; r < 4; r++) acc[i][j][r] = 0.0f;

    // ldmatrix lane address components
    int a_row = (lane & 7) + ((lane >> 3) & 1) * 8;   // row within 16
    int a_k   = (lane >> 4) * 8;                       // k-half
    int b_n   = ((lane >> 4) * 8) + (lane & 7);        // n within 16
    int b_k   = ((lane >> 3) & 1) * 8;                 // k-half

    int nk = K / KC;
    fill(0, 0);
    fill(1, 1);

    for (int c = 0; c < nk; c++) {
        int s = c & 1;
        if (c + 1 < nk) CP_WAIT1(); else CP_WAIT0();
        __syncthreads();

        uint32_t stb = sb + s * STAGE_B;
        uint32_t As_h = stb;
        uint32_t As_l = stb + TILE_B;
        uint32_t Bs_h = stb + 2 * TILE_B;
        uint32_t Bs_l = stb + 3 * TILE_B;

#pragma unroll
        for (int kk = 0; kk < 2; kk++) {
            uint32_t ah[2][4], al[2][4];
#pragma unroll
            for (int i = 0; i < 2; i++) {
                uint32_t off = ((wm * 32 + i * 16 + a_row) * PK + kk * 16 + a_k) * 2;
                LDSM_X4(ah[i][0], ah[i][1], ah[i][2], ah[i][3], As_h + off);
                LDSM_X4(al[i][0], al[i][1], al[i][2], al[i][3], As_l + off);
            }
#pragma unroll
            for (int jj = 0; jj < 4; jj++) {
                uint32_t boff = ((wn * 64 + jj * 16 + b_n) * PK + kk * 16 + b_k) * 2;
                uint32_t bh[4], bl[4];
                LDSM_X4(bh[0], bh[1], bh[2], bh[3], Bs_h + boff);
                LDSM_X4(bl[0], bl[1], bl[2], bl[3], Bs_l + boff);
#pragma unroll
                for (int i = 0; i < 2; i++) {
                    MMA_BF16(acc[i][2 * jj],     ah[i], bh[0], bh[1]);
                    MMA_BF16(acc[i][2 * jj + 1], ah[i], bh[2], bh[3]);
                    MMA_BF16(acc[i][2 * jj],     ah[i], bl[0], bl[1]);
                    MMA_BF16(acc[i][2 * jj + 1], ah[i], bl[2], bl[3]);
                    MMA_BF16(acc[i][2 * jj],     al[i], bh[0], bh[1]);
                    MMA_BF16(acc[i][2 * jj + 1], al[i], bh[2], bh[3]);
                }
            }
        }
        __syncthreads();
        if (c + 2 < nk) fill(s, c + 2);
    }

    // epilogue
#pragma unroll
    for (int i = 0; i < 2; i++) {
        int r0 = bm * 128 + wm * 32 + i * 16 + (lane >> 2);
#pragma unroll
        for (int j = 0; j < 8; j++) {
            int c0 = bn * 128 + wn * 64 + j * 8 + (lane & 3) * 2;
            float bx = bias[c0], by = bias[c0 + 1];
            float2 v0 = make_float2(acc[i][j][0] + bx, acc[i][j][1] + by);
            float2 v1 = make_float2(acc[i][j][2] + bx, acc[i][j][3] + by);
            *(float2*)&C[(size_t)r0 * N + c0] = v0;
            *(float2*)&C[(size_t)(r0 + 8) * N + c0] = v1;
        }
    }
}

// ---------------------------------------------------------------- flash attention fp32
#define PADW 68
__global__ void __launch_bounds__(256) attn_kernel(
        const float* __restrict__ Q, const float* __restrict__ K,
        const float* __restrict__ V, float* __restrict__ Z) {
    extern __shared__ float smf[];
    float* Qs = smf;
    float* Ks = Qs + 64 * PADW;
    float* Vs = Ks + 64 * PADW;
    float* Ps = Vs + 64 * PADW;

    int qt = blockIdx.x, h = blockIdx.y, b = blockIdx.z;
    int tid = threadIdx.x;
    int tx = tid & 15, ty = tid >> 4;
    int q0 = qt * 64;

    const float* Qb = Q + ((size_t)b * SS + q0) * NC + h * DHD;
    for (int t = tid; t < 64 * 64; t += 256) {
        int r = t >> 6, e = t & 63;
        Qs[e * PADW + r] = Qb[(size_t)r * NC + e];
    }

    float m_i[4], l_i[4], acc[4][4];
#pragma unroll
    for (int i = 0; i < 4; i++) {
        m_i[i] = -INFINITY;
        l_i[i] = 0.0f;
#pragma unroll
        for (int j = 0; j < 4; j++) acc[i][j] = 0.0f;
    }
    __syncthreads();

    int nk = (qt + 1) * 64;
    for (int k0 = 0; k0 < nk; k0 += 64) {
        const float* Kb = K + ((size_t)b * SS + k0) * NC + h * DHD;
        const float* Vb = V + ((size_t)b * SS + k0) * NC + h * DHD;
        for (int t = tid; t < 64 * 64; t += 256) {
            int r = t >> 6, e = t & 63;
            Ks[e * PADW + r] = Kb[(size_t)r * NC + e];
            Vs[r * PADW + e] = Vb[(size_t)r * NC + e];
        }
        __syncthreads();

        float s[4][4];
#pragma unroll
        for (int i = 0; i < 4; i++)
#pragma unroll
            for (int j = 0; j < 4; j++) s[i][j] = 0.0f;

        for (int kk = 0; kk < 64; kk++) {
            float qv[4], kv[4];
            *(float4*)qv = *(const float4*)&Qs[kk * PADW + ty * 4];
            *(float4*)kv = *(const float4*)&Ks[kk * PADW + tx * 4];
#pragma unroll
            for (int i = 0; i < 4; i++)
#pragma unroll
                for (int j = 0; j < 4; j++) s[i][j] += qv[i] * kv[j];
        }

        bool diag = (k0 + 63 > q0);
        if (diag) {
#pragma unroll
            for (int i = 0; i < 4; i++) {
                int qg = q0 + ty * 4 + i;
#pragma unroll
                for (int j = 0; j < 4; j++) {
                    int kg = k0 + tx * 4 + j;
                    if (kg > qg) s[i][j] = -1000.0f;
                }
            }
        }

#pragma unroll
        for (int i = 0; i < 4; i++) {
            float rm = fmaxf(fmaxf(s[i][0], s[i][1]), fmaxf(s[i][2], s[i][3]));
#pragma unroll
            for (int off = 8; off >= 1; off >>= 1)
                rm = fmaxf(rm, __shfl_xor_sync(0xffffffffu, rm, off));
            float mnew = fmaxf(m_i[i], rm);
            float corr = expf(m_i[i] - mnew);
            float rs = 0.0f;
#pragma unroll
            for (int j = 0; j < 4; j++) {
                float p = expf(s[i][j] - mnew);
                s[i][j] = p;
                rs += p;
            }
#pragma unroll
            for (int off = 8; off >= 1; off >>= 1)
                rs += __shfl_xor_sync(0xffffffffu, rs, off);
            l_i[i] = l_i[i] * corr + rs;
            m_i[i] = mnew;
#pragma unroll
            for (int j = 0; j < 4; j++) acc[i][j] *= corr;
        }

#pragma unroll
        for (int i = 0; i < 4; i++)
#pragma unroll
            for (int j = 0; j < 4; j++)
                Ps[(ty * 4 + i) * PADW + tx * 4 + j] = s[i][j];
        __syncthreads();

        for (int kk = 0; kk < 64; kk++) {
            float vv[4];
            *(float4*)vv = *(const float4*)&Vs[kk * PADW + tx * 4];
            float pv[4];
#pragma unroll
            for (int i = 0; i < 4; i++) pv[i] = Ps[(ty * 4 + i) * PADW + kk];
#pragma unroll
            for (int i = 0; i < 4; i++)
#pragma unroll
                for (int j = 0; j < 4; j++) acc[i][j] += pv[i] * vv[j];
        }
        __syncthreads();
    }

    float* Zb = Z + ((size_t)b * SS + q0) * NC + h * DHD;
#pragma unroll
    for (int i = 0; i < 4; i++) {
        float inv = 1.0f / l_i[i];
#pragma unroll
        for (int j = 0; j < 4; j++)
            Zb[(size_t)(ty * 4 + i) * NC + tx * 4 + j] = acc[i][j] * inv;
    }
}

// ---------------------------------------------------------------- launch
extern "C" void kernel_launch(void* const* d_in, const int* in_sizes, int n_in,
                              void* d_out, int out_size) {
    const float* Xq  = (const float*)d_in[0];
    const float* Xk  = (const float*)d_in[1];
    const float* Xv  = (const float*)d_in[2];
    const float* WQ  = (const float*)d_in[3];
    const float* WK  = (const float*)d_in[4];
    const float* WV  = (const float*)d_in[5];
    const float* WO  = (const float*)d_in[6];
    const float* bQ  = (const float*)d_in[7];
    const float* bK  = (const float*)d_in[8];
    const float* bV  = (const float*)d_in[9];
    const float* bO  = (const float*)d_in[10];
    float* out = (float*)d_out;

    static bool init = false;
    static __nv_bfloat16 *pWqh, *pWql, *pWkh, *pWkl, *pWvh, *pWvl, *pWoh, *pWol;
    static __nv_bfloat16 *pXqh, *pXql, *pXkh, *pXkl, *pXvh, *pXvl, *pzh, *pzl;
    static float *pbq, *pbk, *pbv, *pq, *pk, *pv, *pz;
    if (!init) {
        cudaGetSymbolAddress((void**)&pWqh, g_Wqh); cudaGetSymbolAddress((void**)&pWql, g_Wql);
        cudaGetSymbolAddress((void**)&pWkh, g_Wkh); cudaGetSymbolAddress((void**)&pWkl, g_Wkl);
        cudaGetSymbolAddress((void**)&pWvh, g_Wvh); cudaGetSymbolAddress((void**)&pWvl, g_Wvl);
        cudaGetSymbolAddress((void**)&pWoh, g_Woh); cudaGetSymbolAddress((void**)&pWol, g_Wol);
        cudaGetSymbolAddress((void**)&pXqh, g_Xqh); cudaGetSymbolAddress((void**)&pXql, g_Xql);
        cudaGetSymbolAddress((void**)&pXkh, g_Xkh); cudaGetSymbolAddress((void**)&pXkl, g_Xkl);
        cudaGetSymbolAddress((void**)&pXvh, g_Xvh); cudaGetSymbolAddress((void**)&pXvl, g_Xvl);
        cudaGetSymbolAddress((void**)&pzh,  g_zh);  cudaGetSymbolAddress((void**)&pzl,  g_zl);
        cudaGetSymbolAddress((void**)&pbq, g_bq); cudaGetSymbolAddress((void**)&pbk, g_bk);
        cudaGetSymbolAddress((void**)&pbv, g_bv);
        cudaGetSymbolAddress((void**)&pq, g_q); cudaGetSymbolAddress((void**)&pk, g_k);
        cudaGetSymbolAddress((void**)&pv, g_v); cudaGetSymbolAddress((void**)&pz, g_z);
        cudaFuncSetAttribute(attn_kernel, cudaFuncAttributeMaxDynamicSharedMemorySize,
                             4 * 64 * PADW * (int)sizeof(float));
        cudaFuncSetAttribute(tgemm_kernel, cudaFuncAttributeMaxDynamicSharedMemorySize, GEMM_SMEM);
        init = true;
    }

    // 1) amax reductions
    reset_kernel<<<1, 32>>>();
    amax_kernel<<<512, 256>>>((const float4*)WQ, WN / 4, 0);
    amax_kernel<<<512, 256>>>((const float4*)WK, WN / 4, 1);
    amax_kernel<<<512, 256>>>((const float4*)WV, WN / 4, 2);
    amax_kernel<<<2, 256>>>((const float4*)bQ, NC / 4, 3);
    amax_kernel<<<2, 256>>>((const float4*)bK, NC / 4, 4);
    amax_kernel<<<2, 256>>>((const float4*)bV, NC / 4, 5);

    // 2) weight qdq + transpose + split to bf16 hi/lo
    dim3 wt_grid(DD / 32, DHD / 32, HH);
    dim3 wt_blk(32, 32);
    quant_w_t_kernel<<<wt_grid, wt_blk>>>(WQ, pWqh, pWql, 0);
    quant_w_t_kernel<<<wt_grid, wt_blk>>>(WK, pWkh, pWkl, 1);
    quant_w_t_kernel<<<wt_grid, wt_blk>>>(WV, pWvh, pWvl, 2);
    wo_t_kernel<<<dim3(DD / 32, NC / 32), wt_blk>>>(WO, pWoh, pWol);
    quant_b_kernel<<<4, 256>>>(bQ, pbq, 3);
    quant_b_kernel<<<4, 256>>>(bK, pbk, 4);
    quant_b_kernel<<<4, 256>>>(bV, pbv, 5);

    // 3) input split fp32 -> bf16 hi/lo
    int n4 = (MR * DD) / 4;
    split_kernel<<<(n4 + 255) / 256, 256>>>((const float4*)Xq, (__nv_bfloat162*)pXqh, (__nv_bfloat162*)pXql, n4);
    split_kernel<<<(n4 + 255) / 256, 256>>>((const float4*)Xk, (__nv_bfloat162*)pXkh, (__nv_bfloat162*)pXkl, n4);
    split_kernel<<<(n4 + 255) / 256, 256>>>((const float4*)Xv, (__nv_bfloat162*)pXvh, (__nv_bfloat162*)pXvl, n4);

    // 4) rotary table
    sincos_kernel<<<SS * 32 / 256, 256>>>();

    // 5) projections on tensor cores (split-bf16, fp32 accumulate)
    dim3 gg(NC / 128, MR / 128);
    tgemm_kernel<<<gg, 256, GEMM_SMEM>>>(pXqh, pXql, pWqh, pWql, pbq, pq, MR, NC, DD);
    tgemm_kernel<<<gg, 256, GEMM_SMEM>>>(pXkh, pXkl, pWkh, pWkl, pbk, pk, MR, NC, DD);
    tgemm_kernel<<<gg, 256, GEMM_SMEM>>>(pXvh, pXvl, pWvh, pWvl, pbv, pv, MR, NC, DD);

    // 6) rotary (q gets 1/sqrt(Dh)=0.125 folded in)
    int rot_grid = (MR * HH * 32) / 256;
    rotary_kernel<<<rot_grid, 256>>>(pq, 0.125f);
    rotary_kernel<<<rot_grid, 256>>>(pk, 1.0f);

    // 7) causal flash attention (fp32)
    dim3 ag(SS / 64, HH, BB);
    attn_kernel<<<ag, 256, 4 * 64 * PADW * (int)sizeof(float)>>>(pq, pk, pv, pz);

    // 8) z split + output projection on tensor cores
    split_kernel<<<(n4 + 255) / 256, 256>>>((const float4*)pz, (__nv_bfloat162*)pzh, (__nv_bfloat162*)pzl, n4);
    tgemm_kernel<<<gg, 256, GEMM_SMEM>>>(pzh, pzl, pWoh, pWol, bO, out, MR, DD, NC);
}

// round 7
// speedup vs baseline: 1.5971x; 1.5971x over previous
#include <cuda_runtime.h>
#include <cuda_bf16.h>
#include <math.h>
#include <stdint.h>

// Problem constants
#define BB   2
#define SS   2048
#define DD   1024
#define HH   16
#define DHD  64
#define MR   (BB*SS)        // 4096
#define NC   (HH*DHD)       // 1024
#define WN   (HH*DD*DHD)    // 1048576

// ---------------------------------------------------------------- helpers
__device__ __forceinline__ uint32_t smem_u32(const void* p) {
    uint32_t a;
    asm("{ .reg .u64 t; cvta.to.shared.u64 t, %1; cvt.u32.u64 %0, t; }" : "=r"(a) : "l"(p));
    return a;
}

#define CP_ASYNC16(dst, src) asm volatile("cp.async.cg.shared.global [%0], [%1], 16;" :: "r"(dst), "l"(src))
#define CP_COMMIT()  asm volatile("cp.async.commit_group;" ::: "memory")
#define CP_WAIT1()   asm volatile("cp.async.wait_group 1;" ::: "memory")
#define CP_WAIT0()   asm volatile("cp.async.wait_group 0;" ::: "memory")

#define LDSM_X4(r0, r1, r2, r3, addr) \
    asm volatile("ldmatrix.sync.aligned.m8n8.x4.shared.b16 {%0,%1,%2,%3}, [%4];" \
                 : "=r"(r0), "=r"(r1), "=r"(r2), "=r"(r3) : "r"(addr))

#define LDSM_X4_T(r0, r1, r2, r3, addr) \
    asm volatile("ldmatrix.sync.aligned.m8n8.x4.trans.shared.b16 {%0,%1,%2,%3}, [%4];" \
                 : "=r"(r0), "=r"(r1), "=r"(r2), "=r"(r3) : "r"(addr))

#define MMA_BF16(c, a, b0, b1) \
    asm volatile("mma.sync.aligned.m16n8k16.row.col.f32.bf16.bf16.f32 " \
                 "{%0,%1,%2,%3}, {%4,%5,%6,%7}, {%8,%9}, {%0,%1,%2,%3};" \
                 : "+f"((c)[0]), "+f"((c)[1]), "+f"((c)[2]), "+f"((c)[3]) \
                 : "r"((a)[0]), "r"((a)[1]), "r"((a)[2]), "r"((a)[3]), "r"(b0), "r"(b1))

// MMA with A given as raw regs (for P fragments built in registers)
#define MMA_BF16_R(c, a0, a1, a2, a3, b0, b1) \
    asm volatile("mma.sync.aligned.m16n8k16.row.col.f32.bf16.bf16.f32 " \
                 "{%0,%1,%2,%3}, {%4,%5,%6,%7}, {%8,%9}, {%0,%1,%2,%3};" \
                 : "+f"((c)[0]), "+f"((c)[1]), "+f"((c)[2]), "+f"((c)[3]) \
                 : "r"(a0), "r"(a1), "r"(a2), "r"(a3), "r"(b0), "r"(b1))

// ---------------------------------------------------------------- scratch
__device__ unsigned g_amax[6];
__device__ __nv_bfloat16 g_Wqh[DD*NC], g_Wql[DD*NC];
__device__ __nv_bfloat16 g_Wkh[DD*NC], g_Wkl[DD*NC];
__device__ __nv_bfloat16 g_Wvh[DD*NC], g_Wvl[DD*NC];
__device__ __nv_bfloat16 g_Woh[NC*DD], g_Wol[NC*DD];
__device__ __nv_bfloat16 g_Xqh[(size_t)MR*DD], g_Xql[(size_t)MR*DD];
__device__ __nv_bfloat16 g_Xkh[(size_t)MR*DD], g_Xkl[(size_t)MR*DD];
__device__ __nv_bfloat16 g_Xvh[(size_t)MR*DD], g_Xvl[(size_t)MR*DD];
__device__ __nv_bfloat16 g_qh[(size_t)MR*NC], g_ql[(size_t)MR*NC];
__device__ __nv_bfloat16 g_kh[(size_t)MR*NC], g_kl[(size_t)MR*NC];
__device__ __nv_bfloat16 g_vh[(size_t)MR*NC], g_vl[(size_t)MR*NC];
__device__ __nv_bfloat16 g_zh[(size_t)MR*NC],  g_zl[(size_t)MR*NC];
__device__ float g_bq[NC], g_bk[NC], g_bv[NC];
__device__ float g_q[(size_t)MR*NC], g_k[(size_t)MR*NC], g_v[(size_t)MR*NC];
__device__ float g_sin[SS*32], g_cos[SS*32];

// ---------------------------------------------------------------- qdq
__device__ __forceinline__ float qdq(float w, float amax) {
    float scale = 448.0f / fmaxf(amax, 1e-12f);
    float v = w * scale;
    float a = fabsf(v);
    int ex;
    frexpf(fmaxf(a, 1e-30f), &ex);
    float e = fminf(fmaxf((float)(ex - 1), -6.0f), 8.0f);
    float step = exp2f(e - 3.0f);
    float q = rintf(v / step) * step;
    q = fminf(fmaxf(q, -448.0f), 448.0f);
    return q / scale;
}

__global__ void reset_kernel() {
    if (threadIdx.x < 6) g_amax[threadIdx.x] = 0u;
}

__global__ void amax_kernel(const float4* __restrict__ x, int n4, int slot) {
    __shared__ float red[256];
    float m = 0.0f;
    for (int i = blockIdx.x * blockDim.x + threadIdx.x; i < n4; i += gridDim.x * blockDim.x) {
        float4 v = x[i];
        m = fmaxf(m, fmaxf(fmaxf(fabsf(v.x), fabsf(v.y)), fmaxf(fabsf(v.z), fabsf(v.w))));
    }
    red[threadIdx.x] = m;
    __syncthreads();
    for (int s = 128; s > 0; s >>= 1) {
        if (threadIdx.x < s) red[threadIdx.x] = fmaxf(red[threadIdx.x], red[threadIdx.x + s]);
        __syncthreads();
    }
    if (threadIdx.x == 0) atomicMax(&g_amax[slot], __float_as_uint(red[0]));
}

__device__ __forceinline__ void split_bf16(float x, __nv_bfloat16& h, __nv_bfloat16& l) {
    h = __float2bfloat16(x);
    l = __float2bfloat16(x - __bfloat162float(h));
}

// qdq + transpose W[h,d,e] -> B[n=h*64+e][k=d], split into hi/lo bf16
__global__ void quant_w_t_kernel(const float* __restrict__ W,
                                 __nv_bfloat16* __restrict__ Bh, __nv_bfloat16* __restrict__ Bl,
                                 int slot) {
    __shared__ float t[32][33];
    float amax = __uint_as_float(g_amax[slot]);
    int h = blockIdx.z;
    int d = blockIdx.x * 32 + threadIdx.y;
    int e = blockIdx.y * 32 + threadIdx.x;
    t[threadIdx.y][threadIdx.x] = qdq(W[(size_t)h * DD * DHD + d * DHD + e], amax);
    __syncthreads();
    int n = h * DHD + blockIdx.y * 32 + threadIdx.y;
    int k = blockIdx.x * 32 + threadIdx.x;
    __nv_bfloat16 hi, lo;
    split_bf16(t[threadIdx.x][threadIdx.y], hi, lo);
    Bh[(size_t)n * DD + k] = hi;
    Bl[(size_t)n * DD + k] = lo;
}

// transpose WO[he][d] -> B[n=d][k=he], split (no qdq)
__global__ void wo_t_kernel(const float* __restrict__ W,
                            __nv_bfloat16* __restrict__ Bh, __nv_bfloat16* __restrict__ Bl) {
    __shared__ float t[32][33];
    int he = blockIdx.y * 32 + threadIdx.y;
    int d  = blockIdx.x * 32 + threadIdx.x;
    t[threadIdx.y][threadIdx.x] = W[(size_t)he * DD + d];
    __syncthreads();
    int n = blockIdx.x * 32 + threadIdx.y;   // d
    int k = blockIdx.y * 32 + threadIdx.x;   // he
    __nv_bfloat16 hi, lo;
    split_bf16(t[threadIdx.x][threadIdx.y], hi, lo);
    Bh[(size_t)n * NC + k] = hi;
    Bl[(size_t)n * NC + k] = lo;
}

__global__ void quant_b_kernel(const float* __restrict__ b, float* __restrict__ bt, int slot) {
    int idx = blockIdx.x * 256 + threadIdx.x;
    if (idx >= NC) return;
    float amax = __uint_as_float(g_amax[slot]);
    bt[idx] = qdq(b[idx], amax);
}

// fp32 -> bf16 hi/lo split (vectorized)
__global__ void split_kernel(const float4* __restrict__ x,
                             __nv_bfloat162* __restrict__ hi, __nv_bfloat162* __restrict__ lo,
                             int n4) {
    int i = blockIdx.x * 256 + threadIdx.x;
    if (i >= n4) return;
    float4 v = x[i];
    __nv_bfloat16 h0, h1, h2, h3, l0, l1, l2, l3;
    split_bf16(v.x, h0, l0);
    split_bf16(v.y, h1, l1);
    split_bf16(v.z, h2, l2);
    split_bf16(v.w, h3, l3);
    hi[2*i]   = __nv_bfloat162(h0, h1);
    hi[2*i+1] = __nv_bfloat162(h2, h3);
    lo[2*i]   = __nv_bfloat162(l0, l1);
    lo[2*i+1] = __nv_bfloat162(l2, l3);
}

// ---------------------------------------------------------------- rotary
__global__ void sincos_kernel() {
    int idx = blockIdx.x * 256 + threadIdx.x;
    if (idx >= SS * 32) return;
    int pos = idx >> 5, i = idx & 31;
    float invf = (float)pow(10000.0, -(double)i / 32.0);
    float ang  = (float)pos * invf;
    g_sin[idx] = (float)sin((double)ang);
    g_cos[idx] = (float)cos((double)ang);
}

// rotary + split fp32 -> bf16 hi/lo (outscale folds 1/sqrt(Dh) into q)
__global__ void rotary_split_kernel(const float* __restrict__ in,
                                    __nv_bfloat16* __restrict__ oh, __nv_bfloat16* __restrict__ ol,
                                    float outscale) {
    int idx = blockIdx.x * 256 + threadIdx.x;
    if (idx >= MR * HH * 32) return;
    int bs  = idx / (HH * 32);
    int rem = idx % (HH * 32);
    int h = rem >> 5, i = rem & 31;
    int pos = bs & (SS - 1);
    size_t base = (size_t)bs * NC + h * DHD;
    float x0 = in[base + i], x1 = in[base + i + 32];
    float c = g_cos[pos * 32 + i], s = g_sin[pos * 32 + i];
    float y0 = (x0 * c - x1 * s) * outscale;
    float y1 = (x1 * c + x0 * s) * outscale;
    __nv_bfloat16 h0, l0, h1, l1;
    split_bf16(y0, h0, l0);
    split_bf16(y1, h1, l1);
    oh[base + i] = h0;      ol[base + i] = l0;
    oh[base + i + 32] = h1; ol[base + i + 32] = l1;
}

// ---------------------------------------------------------------- HMMA GEMM
// C[M,N] = (Ah+Al)[M,K] * (Bh+Bl)[N,K]^T + bias[N]   (split-bf16, 3 passes)
#define KC 32
#define PK 40
#define TILE_B (128 * PK * 2)
#define STAGE_B (4 * TILE_B)
#define GEMM_SMEM (2 * STAGE_B)

__global__ void __launch_bounds__(256) tgemm_kernel(
        const __nv_bfloat16* __restrict__ Ah, const __nv_bfloat16* __restrict__ Al,
        const __nv_bfloat16* __restrict__ Bh, const __nv_bfloat16* __restrict__ Bl,
        const float* __restrict__ bias, float* __restrict__ C,
        int M, int N, int K) {
    extern __shared__ char sm[];
    uint32_t sb = smem_u32(sm);
    int tid = threadIdx.x;
    int lane = tid & 31, wid = tid >> 5;
    int wm = wid & 3, wn = wid >> 2;
    int bm = blockIdx.y, bn = blockIdx.x;

    const char* srcs[4] = {
        (const char*)(Ah + (size_t)bm * 128 * K),
        (const char*)(Al + (size_t)bm * 128 * K),
        (const char*)(Bh + (size_t)bn * 128 * K),
        (const char*)(Bl + (size_t)bn * 128 * K) };

    auto fill = [&](int s, int kc) {
        uint32_t base = sb + s * STAGE_B;
        size_t koff = (size_t)kc * KC * 2;
#pragma unroll
        for (int t = tid; t < 2048; t += 256) {
            int arr = t >> 9;
            int idx = t & 511;
            int row = idx >> 2, c = idx & 3;
            CP_ASYNC16(base + arr * TILE_B + row * (PK * 2) + c * 16,
                       srcs[arr] + (size_t)row * K * 2 + koff + c * 16);
        }
        CP_COMMIT();
    };

    float acc[2][8][4];
#pragma unroll
    for (int i = 0; i < 2; i++)
#pragma unroll
        for (int j = 0; j < 8; j++)
#pragma unroll
            for (int r = 0; r < 4; r++) acc[i][j][r] = 0.0f;

    int a_row = (lane & 7) + ((lane >> 3) & 1) * 8;
    int a_k   = (lane >> 4) * 8;
    int b_n   = ((lane >> 4) * 8) + (lane & 7);
    int b_k   = ((lane >> 3) & 1) * 8;

    int nk = K / KC;
    fill(0, 0);
    fill(1, 1);

    for (int c = 0; c < nk; c++) {
        int s = c & 1;
        if (c + 1 < nk) CP_WAIT1(); else CP_WAIT0();
        __syncthreads();

        uint32_t stb = sb + s * STAGE_B;
        uint32_t As_h = stb;
        uint32_t As_l = stb + TILE_B;
        uint32_t Bs_h = stb + 2 * TILE_B;
        uint32_t Bs_l = stb + 3 * TILE_B;

#pragma unroll
        for (int kk = 0; kk < 2; kk++) {
            uint32_t ah[2][4], al[2][4];
#pragma unroll
            for (int i = 0; i < 2; i++) {
                uint32_t off = ((wm * 32 + i * 16 + a_row) * PK + kk * 16 + a_k) * 2;
                LDSM_X4(ah[i][0], ah[i][1], ah[i][2], ah[i][3], As_h + off);
                LDSM_X4(al[i][0], al[i][1], al[i][2], al[i][3], As_l + off);
            }
#pragma unroll
            for (int jj = 0; jj < 4; jj++) {
                uint32_t boff = ((wn * 64 + jj * 16 + b_n) * PK + kk * 16 + b_k) * 2;
                uint32_t bh[4], bl[4];
                LDSM_X4(bh[0], bh[1], bh[2], bh[3], Bs_h + boff);
                LDSM_X4(bl[0], bl[1], bl[2], bl[3], Bs_l + boff);
#pragma unroll
                for (int i = 0; i < 2; i++) {
                    MMA_BF16(acc[i][2 * jj],     ah[i], bh[0], bh[1]);
                    MMA_BF16(acc[i][2 * jj + 1], ah[i], bh[2], bh[3]);
                    MMA_BF16(acc[i][2 * jj],     ah[i], bl[0], bl[1]);
                    MMA_BF16(acc[i][2 * jj + 1], ah[i], bl[2], bl[3]);
                    MMA_BF16(acc[i][2 * jj],     al[i], bh[0], bh[1]);
                    MMA_BF16(acc[i][2 * jj + 1], al[i], bh[2], bh[3]);
                }
            }
        }
        __syncthreads();
        if (c + 2 < nk) fill(s, c + 2);
    }

#pragma unroll
    for (int i = 0; i < 2; i++) {
        int r0 = bm * 128 + wm * 32 + i * 16 + (lane >> 2);
#pragma unroll
        for (int j = 0; j < 8; j++) {
            int c0 = bn * 128 + wn * 64 + j * 8 + (lane & 3) * 2;
            float bx = bias[c0], by = bias[c0 + 1];
            float2 v0 = make_float2(acc[i][j][0] + bx, acc[i][j][1] + by);
            float2 v1 = make_float2(acc[i][j][2] + bx, acc[i][j][3] + by);
            *(float2*)&C[(size_t)r0 * N + c0] = v0;
            *(float2*)&C[(size_t)(r0 + 8) * N + c0] = v1;
        }
    }
}

// ---------------------------------------------------------------- tensor-core flash attention
// BM=128 q rows, BKV=64 kv rows, 8 warps (16 q rows each), split-bf16 both MMAs.
#define APD 72                        // padded row (bf16): 144B rows, LDSM conflict-free
#define QT_B (128 * APD * 2)          // 18432 B per Q array
#define KT_B (64 * APD * 2)           // 9216 B per KV array
#define AT_SMEM (2 * QT_B + 2 * 4 * KT_B)   // 110592

__global__ void __launch_bounds__(256) attn_tc_kernel(
        const __nv_bfloat16* __restrict__ Qh, const __nv_bfloat16* __restrict__ Ql,
        const __nv_bfloat16* __restrict__ Kh, const __nv_bfloat16* __restrict__ Kl,
        const __nv_bfloat16* __restrict__ Vh, const __nv_bfloat16* __restrict__ Vl,
        __nv_bfloat16* __restrict__ Zh, __nv_bfloat16* __restrict__ Zl) {
    extern __shared__ char sm[];
    uint32_t sb = smem_u32(sm);
    int tid = threadIdx.x, lane = tid & 31, wid = tid >> 5;

    int qt = (SS / 128 - 1) - blockIdx.x;   // heavy tiles first
    int h = blockIdx.y, b = blockIdx.z;
    int q0 = qt * 128;
    int nt = qt * 2 + 2;                    // kv tiles

    const char* gQ[2] = {
        (const char*)(Qh + ((size_t)b * SS + q0) * NC + h * DHD),
        (const char*)(Ql + ((size_t)b * SS + q0) * NC + h * DHD) };
    const char* gKV[4] = {
        (const char*)(Kh + (size_t)b * SS * NC + h * DHD),
        (const char*)(Kl + (size_t)b * SS * NC + h * DHD),
        (const char*)(Vh + (size_t)b * SS * NC + h * DHD),
        (const char*)(Vl + (size_t)b * SS * NC + h * DHD) };

    auto fillKV = [&](int s, int kt) {
        uint32_t base = sb + 2 * QT_B + s * 4 * KT_B;
        size_t roff = (size_t)(kt * 64) * (NC * 2);
#pragma unroll
        for (int t = tid; t < 2048; t += 256) {
            int arr = t >> 9, idx = t & 511;
            int row = idx >> 3, c = idx & 7;
            CP_ASYNC16(base + arr * KT_B + row * 144 + c * 16,
                       gKV[arr] + roff + (size_t)row * (NC * 2) + c * 16);
        }
        CP_COMMIT();
    };

    // load Q tile + KV tile 0
#pragma unroll
    for (int t = tid; t < 2048; t += 256) {
        int arr = t >> 10, idx = t & 1023;
        int row = idx >> 3, c = idx & 7;
        CP_ASYNC16(sb + arr * QT_B + row * 144 + c * 16,
                   gQ[arr] + (size_t)row * (NC * 2) + c * 16);
    }
    fillKV(0, 0);   // commits both

    float zacc[8][4];
#pragma unroll
    for (int j = 0; j < 8; j++)
#pragma unroll
        for (int r = 0; r < 4; r++) zacc[j][r] = 0.0f;
    float m0 = -1e30f, m1 = -1e30f, l0 = 0.0f, l1 = 0.0f;

    int a_row = (lane & 7) + ((lane >> 3) & 1) * 8;
    int a_k   = (lane >> 4) * 8;
    int b_n   = ((lane >> 4) * 8) + (lane & 7);
    int b_k   = ((lane >> 3) & 1) * 8;
    int v_r   = lane & 15;
    int v_c   = (lane >> 4) * 8;

    CP_WAIT0();
    __syncthreads();

    // Q fragments resident in registers (reused across all kv tiles)
    uint32_t qh_f[4][4], ql_f[4][4];
#pragma unroll
    for (int kc = 0; kc < 4; kc++) {
        uint32_t off = (wid * 16 + a_row) * 144 + (kc * 16 + a_k) * 2;
        LDSM_X4(qh_f[kc][0], qh_f[kc][1], qh_f[kc][2], qh_f[kc][3], sb + off);
        LDSM_X4(ql_f[kc][0], ql_f[kc][1], ql_f[kc][2], ql_f[kc][3], sb + QT_B + off);
    }

    int rbase = q0 + wid * 16 + (lane >> 2);

    for (int t = 0; t < nt; t++) {
        if (t + 1 < nt) fillKV((t + 1) & 1, t + 1);

        uint32_t sbK = sb + 2 * QT_B + (t & 1) * 4 * KT_B;
        int k0 = t * 64;

        // ---- S = Q K^T (3-pass split)
        float s[8][4];
#pragma unroll
        for (int j = 0; j < 8; j++)
#pragma unroll
            for (int r = 0; r < 4; r++) s[j][r] = 0.0f;

#pragma unroll
        for (int kc = 0; kc < 4; kc++) {
#pragma unroll
            for (int jj = 0; jj < 4; jj++) {
                uint32_t boff = (jj * 16 + b_n) * 144 + (kc * 16 + b_k) * 2;
                uint32_t kh[4], kl[4];
                LDSM_X4(kh[0], kh[1], kh[2], kh[3], sbK + boff);
                LDSM_X4(kl[0], kl[1], kl[2], kl[3], sbK + KT_B + boff);
                MMA_BF16(s[2 * jj],     qh_f[kc], kh[0], kh[1]);
                MMA_BF16(s[2 * jj + 1], qh_f[kc], kh[2], kh[3]);
                MMA_BF16(s[2 * jj],     qh_f[kc], kl[0], kl[1]);
                MMA_BF16(s[2 * jj + 1], qh_f[kc], kl[2], kl[3]);
                MMA_BF16(s[2 * jj],     ql_f[kc], kh[0], kh[1]);
                MMA_BF16(s[2 * jj + 1], ql_f[kc], kh[2], kh[3]);
            }
        }

        // ---- causal mask
        if (k0 + 63 > q0 + wid * 16) {
#pragma unroll
            for (int j = 0; j < 8; j++) {
                int kg = k0 + j * 8 + (lane & 3) * 2;
                if (kg > rbase)         s[j][0] = -1e30f;
                if (kg + 1 > rbase)     s[j][1] = -1e30f;
                if (kg > rbase + 8)     s[j][2] = -1e30f;
                if (kg + 1 > rbase + 8) s[j][3] = -1e30f;
            }
        }

        // ---- online softmax
        float rm0 = -1e30f, rm1 = -1e30f;
#pragma unroll
        for (int j = 0; j < 8; j++) {
            rm0 = fmaxf(rm0, fmaxf(s[j][0], s[j][1]));
            rm1 = fmaxf(rm1, fmaxf(s[j][2], s[j][3]));
        }
        rm0 = fmaxf(rm0, __shfl_xor_sync(0xffffffffu, rm0, 1));
        rm0 = fmaxf(rm0, __shfl_xor_sync(0xffffffffu, rm0, 2));
        rm1 = fmaxf(rm1, __shfl_xor_sync(0xffffffffu, rm1, 1));
        rm1 = fmaxf(rm1, __shfl_xor_sync(0xffffffffu, rm1, 2));
        float mn0 = fmaxf(m0, rm0), mn1 = fmaxf(m1, rm1);
        float cr0 = expf(m0 - mn0), cr1 = expf(m1 - mn1);
        float rs0 = 0.0f, rs1 = 0.0f;
#pragma unroll
        for (int j = 0; j < 8; j++) {
            s[j][0] = expf(s[j][0] - mn0);
            s[j][1] = expf(s[j][1] - mn0);
            s[j][2] = expf(s[j][2] - mn1);
            s[j][3] = expf(s[j][3] - mn1);
            rs0 += s[j][0] + s[j][1];
            rs1 += s[j][2] + s[j][3];
        }
        rs0 += __shfl_xor_sync(0xffffffffu, rs0, 1);
        rs0 += __shfl_xor_sync(0xffffffffu, rs0, 2);
        rs1 += __shfl_xor_sync(0xffffffffu, rs1, 1);
        rs1 += __shfl_xor_sync(0xffffffffu, rs1, 2);
        l0 = l0 * cr0 + rs0; l1 = l1 * cr1 + rs1;
        m0 = mn0; m1 = mn1;
#pragma unroll
        for (int j = 0; j < 8; j++) {
            zacc[j][0] *= cr0; zacc[j][1] *= cr0;
            zacc[j][2] *= cr1; zacc[j][3] *= cr1;
        }

        // ---- P -> bf16 hi/lo A-fragments (register-resident)
        uint32_t ph[4][4], pl[4][4];
#pragma unroll
        for (int kc = 0; kc < 4; kc++) {
#pragma unroll
            for (int half = 0; half < 2; half++) {   // half 0: j=2kc (a0,a1), half 1: j=2kc+1 (a2,a3)
                int j = 2 * kc + half;
                float p0 = s[j][0], p1 = s[j][1], p2 = s[j][2], p3 = s[j][3];
                __nv_bfloat16 h0, lo0, h1, lo1, h2, lo2, h3, lo3;
                split_bf16(p0, h0, lo0); split_bf16(p1, h1, lo1);
                split_bf16(p2, h2, lo2); split_bf16(p3, h3, lo3);
                __nv_bfloat162 H01(h0, h1), H23(h2, h3), L01(lo0, lo1), L23(lo2, lo3);
                ph[kc][half * 2]     = *(uint32_t*)&H01;
                ph[kc][half * 2 + 1] = *(uint32_t*)&H23;
                pl[kc][half * 2]     = *(uint32_t*)&L01;
                pl[kc][half * 2 + 1] = *(uint32_t*)&L23;
            }
        }

        // ---- Z += P V (3-pass split)
#pragma unroll
        for (int kc = 0; kc < 4; kc++) {
#pragma unroll
            for (int jj = 0; jj < 4; jj++) {
                uint32_t voff = (kc * 16 + v_r) * 144 + (jj * 16 + v_c) * 2;
                uint32_t vh[4], vl[4];
                LDSM_X4_T(vh[0], vh[1], vh[2], vh[3], sbK + 2 * KT_B + voff);
                LDSM_X4_T(vl[0], vl[1], vl[2], vl[3], sbK + 3 * KT_B + voff);
                MMA_BF16(zacc[2 * jj],     ph[kc], vh[0], vh[1]);
                MMA_BF16(zacc[2 * jj + 1], ph[kc], vh[2], vh[3]);
                MMA_BF16(zacc[2 * jj],     ph[kc], vl[0], vl[1]);
                MMA_BF16(zacc[2 * jj + 1], ph[kc], vl[2], vl[3]);
                MMA_BF16(zacc[2 * jj],     pl[kc], vh[0], vh[1]);
                MMA_BF16(zacc[2 * jj + 1], pl[kc], vh[2], vh[3]);
            }
        }

        if (t + 1 < nt) {
            CP_WAIT0();
            __syncthreads();
        }
    }

    // ---- epilogue: z / l, split to bf16 hi/lo
    float inv0 = 1.0f / l0, inv1 = 1.0f / l1;
    size_t row0 = (size_t)b * SS + q0 + wid * 16 + (lane >> 2);
#pragma unroll
    for (int j = 0; j < 8; j++) {
        int col = h * DHD + j * 8 + (lane & 3) * 2;
        float z0 = zacc[j][0] * inv0, z1 = zacc[j][1] * inv0;
        float z2 = zacc[j][2] * inv1, z3 = zacc[j][3] * inv1;
        __nv_bfloat16 h0, lo0, h1, lo1, h2, lo2, h3, lo3;
        split_bf16(z0, h0, lo0); split_bf16(z1, h1, lo1);
        split_bf16(z2, h2, lo2); split_bf16(z3, h3, lo3);
        __nv_bfloat162 H01(h0, h1), L01(lo0, lo1), H23(h2, h3), L23(lo2, lo3);
        *(uint32_t*)&Zh[row0 * NC + col]       = *(uint32_t*)&H01;
        *(uint32_t*)&Zl[row0 * NC + col]       = *(uint32_t*)&L01;
        *(uint32_t*)&Zh[(row0 + 8) * NC + col] = *(uint32_t*)&H23;
        *(uint32_t*)&Zl[(row0 + 8) * NC + col] = *(uint32_t*)&L23;
    }
}

// ---------------------------------------------------------------- launch
extern "C" void kernel_launch(void* const* d_in, const int* in_sizes, int n_in,
                              void* d_out, int out_size) {
    const float* Xq  = (const float*)d_in[0];
    const float* Xk  = (const float*)d_in[1];
    const float* Xv  = (const float*)d_in[2];
    const float* WQ  = (const float*)d_in[3];
    const float* WK  = (const float*)d_in[4];
    const float* WV  = (const float*)d_in[5];
    const float* WO  = (const float*)d_in[6];
    const float* bQ  = (const float*)d_in[7];
    const float* bK  = (const float*)d_in[8];
    const float* bV  = (const float*)d_in[9];
    const float* bO  = (const float*)d_in[10];
    float* out = (float*)d_out;

    static bool init = false;
    static __nv_bfloat16 *pWqh, *pWql, *pWkh, *pWkl, *pWvh, *pWvl, *pWoh, *pWol;
    static __nv_bfloat16 *pXqh, *pXql, *pXkh, *pXkl, *pXvh, *pXvl, *pzh, *pzl;
    static __nv_bfloat16 *pqh, *pql, *pkh, *pkl, *pvh, *pvl;
    static float *pbq, *pbk, *pbv, *pq, *pk, *pv;
    if (!init) {
        cudaGetSymbolAddress((void**)&pWqh, g_Wqh); cudaGetSymbolAddress((void**)&pWql, g_Wql);
        cudaGetSymbolAddress((void**)&pWkh, g_Wkh); cudaGetSymbolAddress((void**)&pWkl, g_Wkl);
        cudaGetSymbolAddress((void**)&pWvh, g_Wvh); cudaGetSymbolAddress((void**)&pWvl, g_Wvl);
        cudaGetSymbolAddress((void**)&pWoh, g_Woh); cudaGetSymbolAddress((void**)&pWol, g_Wol);
        cudaGetSymbolAddress((void**)&pXqh, g_Xqh); cudaGetSymbolAddress((void**)&pXql, g_Xql);
        cudaGetSymbolAddress((void**)&pXkh, g_Xkh); cudaGetSymbolAddress((void**)&pXkl, g_Xkl);
        cudaGetSymbolAddress((void**)&pXvh, g_Xvh); cudaGetSymbolAddress((void**)&pXvl, g_Xvl);
        cudaGetSymbolAddress((void**)&pzh,  g_zh);  cudaGetSymbolAddress((void**)&pzl,  g_zl);
        cudaGetSymbolAddress((void**)&pqh, g_qh);   cudaGetSymbolAddress((void**)&pql, g_ql);
        cudaGetSymbolAddress((void**)&pkh, g_kh);   cudaGetSymbolAddress((void**)&pkl, g_kl);
        cudaGetSymbolAddress((void**)&pvh, g_vh);   cudaGetSymbolAddress((void**)&pvl, g_vl);
        cudaGetSymbolAddress((void**)&pbq, g_bq); cudaGetSymbolAddress((void**)&pbk, g_bk);
        cudaGetSymbolAddress((void**)&pbv, g_bv);
        cudaGetSymbolAddress((void**)&pq, g_q); cudaGetSymbolAddress((void**)&pk, g_k);
        cudaGetSymbolAddress((void**)&pv, g_v);
        cudaFuncSetAttribute(tgemm_kernel, cudaFuncAttributeMaxDynamicSharedMemorySize, GEMM_SMEM);
        cudaFuncSetAttribute(attn_tc_kernel, cudaFuncAttributeMaxDynamicSharedMemorySize, AT_SMEM);
        init = true;
    }

    // 1) amax reductions
    reset_kernel<<<1, 32>>>();
    amax_kernel<<<512, 256>>>((const float4*)WQ, WN / 4, 0);
    amax_kernel<<<512, 256>>>((const float4*)WK, WN / 4, 1);
    amax_kernel<<<512, 256>>>((const float4*)WV, WN / 4, 2);
    amax_kernel<<<2, 256>>>((const float4*)bQ, NC / 4, 3);
    amax_kernel<<<2, 256>>>((const float4*)bK, NC / 4, 4);
    amax_kernel<<<2, 256>>>((const float4*)bV, NC / 4, 5);

    // 2) weight qdq + transpose + split
    dim3 wt_grid(DD / 32, DHD / 32, HH);
    dim3 wt_blk(32, 32);
    quant_w_t_kernel<<<wt_grid, wt_blk>>>(WQ, pWqh, pWql, 0);
    quant_w_t_kernel<<<wt_grid, wt_blk>>>(WK, pWkh, pWkl, 1);
    quant_w_t_kernel<<<wt_grid, wt_blk>>>(WV, pWvh, pWvl, 2);
    wo_t_kernel<<<dim3(DD / 32, NC / 32), wt_blk>>>(WO, pWoh, pWol);
    quant_b_kernel<<<4, 256>>>(bQ, pbq, 3);
    quant_b_kernel<<<4, 256>>>(bK, pbk, 4);
    quant_b_kernel<<<4, 256>>>(bV, pbv, 5);

    // 3) input split
    int n4 = (MR * DD) / 4;
    split_kernel<<<(n4 + 255) / 256, 256>>>((const float4*)Xq, (__nv_bfloat162*)pXqh, (__nv_bfloat162*)pXql, n4);
    split_kernel<<<(n4 + 255) / 256, 256>>>((const float4*)Xk, (__nv_bfloat162*)pXkh, (__nv_bfloat162*)pXkl, n4);
    split_kernel<<<(n4 + 255) / 256, 256>>>((const float4*)Xv, (__nv_bfloat162*)pXvh, (__nv_bfloat162*)pXvl, n4);

    // 4) rotary table
    sincos_kernel<<<SS * 32 / 256, 256>>>();

    // 5) projections (tensor cores)
    dim3 gg(NC / 128, MR / 128);
    tgemm_kernel<<<gg, 256, GEMM_SMEM>>>(pXqh, pXql, pWqh, pWql, pbq, pq, MR, NC, DD);
    tgemm_kernel<<<gg, 256, GEMM_SMEM>>>(pXkh, pXkl, pWkh, pWkl, pbk, pk, MR, NC, DD);
    tgemm_kernel<<<gg, 256, GEMM_SMEM>>>(pXvh, pXvl, pWvh, pWvl, pbv, pv, MR, NC, DD);

    // 6) rotary + split to bf16 hi/lo (q gets 0.125 attention scale)
    int rot_grid = (MR * HH * 32) / 256;
    rotary_split_kernel<<<rot_grid, 256>>>(pq, pqh, pql, 0.125f);
    rotary_split_kernel<<<rot_grid, 256>>>(pk, pkh, pkl, 1.0f);
    int vn4 = (MR * NC) / 4;
    split_kernel<<<(vn4 + 255) / 256, 256>>>((const float4*)pv, (__nv_bfloat162*)pvh, (__nv_bfloat162*)pvl, vn4);

    // 7) tensor-core flash attention -> z hi/lo
    dim3 ag(SS / 128, HH, BB);
    attn_tc_kernel<<<ag, 256, AT_SMEM>>>(pqh, pql, pkh, pkl, pvh, pvl, pzh, pzl);

    // 8) output projection (tensor cores)
    tgemm_kernel<<<gg, 256, GEMM_SMEM>>>(pzh, pzl, pWoh, pWol, bO, out, MR, DD, NC);
}

// round 8
// speedup vs baseline: 1.6049x; 1.0049x over previous
#include <cuda_runtime.h>
#include <cuda_bf16.h>
#include <math.h>
#include <stdint.h>

// Problem constants
#define BB   2
#define SS   2048
#define DD   1024
#define HH   16
#define DHD  64
#define MR   (BB*SS)        // 4096
#define NC   (HH*DHD)       // 1024
#define WN   (HH*DD*DHD)    // 1048576
#define LOG2E 1.4426950408889634f

// ---------------------------------------------------------------- helpers
__device__ __forceinline__ uint32_t smem_u32(const void* p) {
    uint32_t a;
    asm("{ .reg .u64 t; cvta.to.shared.u64 t, %1; cvt.u32.u64 %0, t; }" : "=r"(a) : "l"(p));
    return a;
}

#define CP_ASYNC16(dst, src) asm volatile("cp.async.cg.shared.global [%0], [%1], 16;" :: "r"(dst), "l"(src))
#define CP_COMMIT()  asm volatile("cp.async.commit_group;" ::: "memory")
#define CP_WAIT1()   asm volatile("cp.async.wait_group 1;" ::: "memory")
#define CP_WAIT0()   asm volatile("cp.async.wait_group 0;" ::: "memory")

#define LDSM_X4(r0, r1, r2, r3, addr) \
    asm volatile("ldmatrix.sync.aligned.m8n8.x4.shared.b16 {%0,%1,%2,%3}, [%4];" \
                 : "=r"(r0), "=r"(r1), "=r"(r2), "=r"(r3) : "r"(addr))

#define LDSM_X4_T(r0, r1, r2, r3, addr) \
    asm volatile("ldmatrix.sync.aligned.m8n8.x4.trans.shared.b16 {%0,%1,%2,%3}, [%4];" \
                 : "=r"(r0), "=r"(r1), "=r"(r2), "=r"(r3) : "r"(addr))

#define MMA_BF16(c, a, b0, b1) \
    asm volatile("mma.sync.aligned.m16n8k16.row.col.f32.bf16.bf16.f32 " \
                 "{%0,%1,%2,%3}, {%4,%5,%6,%7}, {%8,%9}, {%0,%1,%2,%3};" \
                 : "+f"((c)[0]), "+f"((c)[1]), "+f"((c)[2]), "+f"((c)[3]) \
                 : "r"((a)[0]), "r"((a)[1]), "r"((a)[2]), "r"((a)[3]), "r"(b0), "r"(b1))

// ---------------------------------------------------------------- scratch
__device__ unsigned g_amax[6];
__device__ __nv_bfloat16 g_Wqh[DD*NC], g_Wql[DD*NC];
__device__ __nv_bfloat16 g_Wkh[DD*NC], g_Wkl[DD*NC];
__device__ __nv_bfloat16 g_Wvh[DD*NC], g_Wvl[DD*NC];
__device__ __nv_bfloat16 g_Woh[NC*DD], g_Wol[NC*DD];
__device__ __nv_bfloat16 g_Xqh[(size_t)MR*DD], g_Xql[(size_t)MR*DD];
__device__ __nv_bfloat16 g_Xkh[(size_t)MR*DD], g_Xkl[(size_t)MR*DD];
__device__ __nv_bfloat16 g_Xvh[(size_t)MR*DD], g_Xvl[(size_t)MR*DD];
__device__ __nv_bfloat16 g_qh[(size_t)MR*NC], g_ql[(size_t)MR*NC];
__device__ __nv_bfloat16 g_kh[(size_t)MR*NC], g_kl[(size_t)MR*NC];
__device__ __nv_bfloat16 g_vh[(size_t)MR*NC], g_vl[(size_t)MR*NC];
__device__ __nv_bfloat16 g_zh[(size_t)MR*NC], g_zl[(size_t)MR*NC];
__device__ float g_bq[NC], g_bk[NC], g_bv[NC];
__device__ float g_sin[SS*32], g_cos[SS*32];

// ---------------------------------------------------------------- qdq
__device__ __forceinline__ float qdq(float w, float amax) {
    float scale = 448.0f / fmaxf(amax, 1e-12f);
    float v = w * scale;
    float a = fabsf(v);
    int ex;
    frexpf(fmaxf(a, 1e-30f), &ex);
    float e = fminf(fmaxf((float)(ex - 1), -6.0f), 8.0f);
    float step = exp2f(e - 3.0f);
    float q = rintf(v / step) * step;
    q = fminf(fmaxf(q, -448.0f), 448.0f);
    return q / scale;
}

__global__ void reset_kernel() {
    if (threadIdx.x < 6) g_amax[threadIdx.x] = 0u;
}

// batched amax over 3 arrays (slot = slot0 + blockIdx.y)
__global__ void amax3_kernel(const float4* __restrict__ a, const float4* __restrict__ b,
                             const float4* __restrict__ c, int n4, int slot0) {
    __shared__ float red[256];
    const float4* x = (blockIdx.y == 0) ? a : (blockIdx.y == 1) ? b : c;
    float m = 0.0f;
    for (int i = blockIdx.x * blockDim.x + threadIdx.x; i < n4; i += gridDim.x * blockDim.x) {
        float4 v = x[i];
        m = fmaxf(m, fmaxf(fmaxf(fabsf(v.x), fabsf(v.y)), fmaxf(fabsf(v.z), fabsf(v.w))));
    }
    red[threadIdx.x] = m;
    __syncthreads();
    for (int s = 128; s > 0; s >>= 1) {
        if (threadIdx.x < s) red[threadIdx.x] = fmaxf(red[threadIdx.x], red[threadIdx.x + s]);
        __syncthreads();
    }
    if (threadIdx.x == 0) atomicMax(&g_amax[slot0 + blockIdx.y], __float_as_uint(red[0]));
}

__device__ __forceinline__ void split_bf16(float x, __nv_bfloat16& h, __nv_bfloat16& l) {
    h = __float2bfloat16(x);
    l = __float2bfloat16(x - __bfloat162float(h));
}

// batched: qdq + transpose W[h,d,e] -> B[n=h*64+e][k=d], split hi/lo. op = blockIdx.y>>1
__global__ void quant_w_t3_kernel(const float* __restrict__ W0, const float* __restrict__ W1,
                                  const float* __restrict__ W2,
                                  __nv_bfloat16* __restrict__ Bh0, __nv_bfloat16* __restrict__ Bl0,
                                  __nv_bfloat16* __restrict__ Bh1, __nv_bfloat16* __restrict__ Bl1,
                                  __nv_bfloat16* __restrict__ Bh2, __nv_bfloat16* __restrict__ Bl2) {
    __shared__ float t[32][33];
    int op = blockIdx.y >> 1;
    int ey = blockIdx.y & 1;
    const float* W = (op == 0) ? W0 : (op == 1) ? W1 : W2;
    __nv_bfloat16* Bh = (op == 0) ? Bh0 : (op == 1) ? Bh1 : Bh2;
    __nv_bfloat16* Bl = (op == 0) ? Bl0 : (op == 1) ? Bl1 : Bl2;
    float amax = __uint_as_float(g_amax[op]);
    int h = blockIdx.z;
    int d = blockIdx.x * 32 + threadIdx.y;
    int e = ey * 32 + threadIdx.x;
    t[threadIdx.y][threadIdx.x] = qdq(W[(size_t)h * DD * DHD + d * DHD + e], amax);
    __syncthreads();
    int n = h * DHD + ey * 32 + threadIdx.y;
    int k = blockIdx.x * 32 + threadIdx.x;
    __nv_bfloat16 hi, lo;
    split_bf16(t[threadIdx.x][threadIdx.y], hi, lo);
    Bh[(size_t)n * DD + k] = hi;
    Bl[(size_t)n * DD + k] = lo;
}

// transpose WO[he][d] -> B[n=d][k=he], split (no qdq)
__global__ void wo_t_kernel(const float* __restrict__ W,
                            __nv_bfloat16* __restrict__ Bh, __nv_bfloat16* __restrict__ Bl) {
    __shared__ float t[32][33];
    int he = blockIdx.y * 32 + threadIdx.y;
    int d  = blockIdx.x * 32 + threadIdx.x;
    t[threadIdx.y][threadIdx.x] = W[(size_t)he * DD + d];
    __syncthreads();
    int n = blockIdx.x * 32 + threadIdx.y;
    int k = blockIdx.y * 32 + threadIdx.x;
    __nv_bfloat16 hi, lo;
    split_bf16(t[threadIdx.x][threadIdx.y], hi, lo);
    Bh[(size_t)n * NC + k] = hi;
    Bl[(size_t)n * NC + k] = lo;
}

// batched bias qdq (3 biases; slot = 3 + blockIdx.y)
__global__ void quant_b3_kernel(const float* __restrict__ b0, const float* __restrict__ b1,
                                const float* __restrict__ b2,
                                float* __restrict__ o0, float* __restrict__ o1, float* __restrict__ o2) {
    int which = blockIdx.y;
    const float* b = (which == 0) ? b0 : (which == 1) ? b1 : b2;
    float* o = (which == 0) ? o0 : (which == 1) ? o1 : o2;
    int idx = blockIdx.x * 256 + threadIdx.x;
    if (idx >= NC) return;
    float amax = __uint_as_float(g_amax[3 + which]);
    o[idx] = qdq(b[idx], amax);
}

// batched fp32 -> bf16 hi/lo split over 3 arrays
__global__ void split3_kernel(const float4* __restrict__ x0, const float4* __restrict__ x1,
                              const float4* __restrict__ x2,
                              __nv_bfloat162* __restrict__ h0, __nv_bfloat162* __restrict__ l0,
                              __nv_bfloat162* __restrict__ h1, __nv_bfloat162* __restrict__ l1,
                              __nv_bfloat162* __restrict__ h2, __nv_bfloat162* __restrict__ l2,
                              int n4) {
    int which = blockIdx.y;
    const float4* x = (which == 0) ? x0 : (which == 1) ? x1 : x2;
    __nv_bfloat162* hi = (which == 0) ? h0 : (which == 1) ? h1 : h2;
    __nv_bfloat162* lo = (which == 0) ? l0 : (which == 1) ? l1 : l2;
    int i = blockIdx.x * 256 + threadIdx.x;
    if (i >= n4) return;
    float4 v = x[i];
    __nv_bfloat16 a0, a1, a2, a3, b0, b1, b2, b3;
    split_bf16(v.x, a0, b0);
    split_bf16(v.y, a1, b1);
    split_bf16(v.z, a2, b2);
    split_bf16(v.w, a3, b3);
    hi[2*i]   = __nv_bfloat162(a0, a1);
    hi[2*i+1] = __nv_bfloat162(a2, a3);
    lo[2*i]   = __nv_bfloat162(b0, b1);
    lo[2*i+1] = __nv_bfloat162(b2, b3);
}

// ---------------------------------------------------------------- rotary table
__global__ void sincos_kernel() {
    int idx = blockIdx.x * 256 + threadIdx.x;
    if (idx >= SS * 32) return;
    int pos = idx >> 5, i = idx & 31;
    float invf = (float)pow(10000.0, -(double)i / 32.0);
    float ang  = (float)pos * invf;
    g_sin[idx] = (float)sin((double)ang);
    g_cos[idx] = (float)cos((double)ang);
}

// ---------------------------------------------------------------- GEMM common
#define KC 32
#define PK 40
#define TILE_B (128 * PK * 2)
#define STAGE_B (4 * TILE_B)
#define GEMM_SMEM (2 * STAGE_B)

__device__ __forceinline__ void store_bf2(__nv_bfloat16* Oh, __nv_bfloat16* Ol,
                                          size_t row, int col, float a, float b) {
    __nv_bfloat16 ha, la, hb, lb;
    split_bf16(a, ha, la);
    split_bf16(b, hb, lb);
    __nv_bfloat162 H(ha, hb), L(la, lb);
    *(uint32_t*)&Oh[row * NC + col] = *(uint32_t*)&H;
    *(uint32_t*)&Ol[row * NC + col] = *(uint32_t*)&L;
}

// ---------------------------------------------------------------- fused QKV GEMM
// op = blockIdx.z: 0=Q (rotary, scale 0.125*log2e), 1=K (rotary), 2=V (plain).
// Epilogue: bias + rotary + split to bf16 hi/lo, written directly.
struct QKVParams {
    const __nv_bfloat16 *Ah[3], *Al[3], *Bh[3], *Bl[3];
    const float* bias[3];
    __nv_bfloat16 *Oh[3], *Ol[3];
};

__global__ void __launch_bounds__(256) qkv_gemm_kernel(QKVParams P) {
    extern __shared__ char sm[];
    uint32_t sb = smem_u32(sm);
    int tid = threadIdx.x;
    int lane = tid & 31, wid = tid >> 5;
    int wm = wid & 3, wn = wid >> 2;
    int bm = blockIdx.y, bn = blockIdx.x;
    int op = blockIdx.z;

    const char* srcs[4] = {
        (const char*)(P.Ah[op] + (size_t)bm * 128 * DD),
        (const char*)(P.Al[op] + (size_t)bm * 128 * DD),
        (const char*)(P.Bh[op] + (size_t)bn * 128 * DD),
        (const char*)(P.Bl[op] + (size_t)bn * 128 * DD) };

    auto fill = [&](int s, int kc) {
        uint32_t base = sb + s * STAGE_B;
        size_t koff = (size_t)kc * KC * 2;
#pragma unroll
        for (int t = tid; t < 2048; t += 256) {
            int arr = t >> 9;
            int idx = t & 511;
            int row = idx >> 2, c = idx & 3;
            CP_ASYNC16(base + arr * TILE_B + row * (PK * 2) + c * 16,
                       srcs[arr] + (size_t)row * DD * 2 + koff + c * 16);
        }
        CP_COMMIT();
    };

    float acc[2][8][4];
#pragma unroll
    for (int i = 0; i < 2; i++)
#pragma unroll
        for (int j = 0; j < 8; j++)
#pragma unroll
            for (int r = 0; r < 4; r++) acc[i][j][r] = 0.0f;

    int a_row = (lane & 7) + ((lane >> 3) & 1) * 8;
    int a_k   = (lane >> 4) * 8;
    int b_n   = ((lane >> 4) * 8) + (lane & 7);
    int b_k   = ((lane >> 3) & 1) * 8;

    const int nk = DD / KC;
    fill(0, 0);
    fill(1, 1);

    for (int c = 0; c < nk; c++) {
        int s = c & 1;
        if (c + 1 < nk) CP_WAIT1(); else CP_WAIT0();
        __syncthreads();

        uint32_t stb = sb + s * STAGE_B;
        uint32_t As_h = stb;
        uint32_t As_l = stb + TILE_B;
        uint32_t Bs_h = stb + 2 * TILE_B;
        uint32_t Bs_l = stb + 3 * TILE_B;

#pragma unroll
        for (int kk = 0; kk < 2; kk++) {
            uint32_t ah[2][4], al[2][4];
#pragma unroll
            for (int i = 0; i < 2; i++) {
                uint32_t off = ((wm * 32 + i * 16 + a_row) * PK + kk * 16 + a_k) * 2;
                LDSM_X4(ah[i][0], ah[i][1], ah[i][2], ah[i][3], As_h + off);
                LDSM_X4(al[i][0], al[i][1], al[i][2], al[i][3], As_l + off);
            }
#pragma unroll
            for (int jj = 0; jj < 4; jj++) {
                uint32_t boff = ((wn * 64 + jj * 16 + b_n) * PK + kk * 16 + b_k) * 2;
                uint32_t bh[4], bl[4];
                LDSM_X4(bh[0], bh[1], bh[2], bh[3], Bs_h + boff);
                LDSM_X4(bl[0], bl[1], bl[2], bl[3], Bs_l + boff);
#pragma unroll
                for (int i = 0; i < 2; i++) {
                    MMA_BF16(acc[i][2 * jj],     ah[i], bh[0], bh[1]);
                    MMA_BF16(acc[i][2 * jj + 1], ah[i], bh[2], bh[3]);
                    MMA_BF16(acc[i][2 * jj],     ah[i], bl[0], bl[1]);
                    MMA_BF16(acc[i][2 * jj + 1], ah[i], bl[2], bl[3]);
                    MMA_BF16(acc[i][2 * jj],     al[i], bh[0], bh[1]);
                    MMA_BF16(acc[i][2 * jj + 1], al[i], bh[2], bh[3]);
                }
            }
        }
        __syncthreads();
        if (c + 2 < nk) fill(s, c + 2);
    }

    const float* bias = P.bias[op];
    __nv_bfloat16* Oh = P.Oh[op];
    __nv_bfloat16* Ol = P.Ol[op];

    if (op < 2) {
        // rotary + scale + split. Warp col tile (64) == one head; pair (e, e+32) = (j, j+4).
        float osc = (op == 0) ? 0.125f * LOG2E : 1.0f;
#pragma unroll
        for (int i = 0; i < 2; i++) {
            int r0 = bm * 128 + wm * 32 + i * 16 + (lane >> 2);
            int pos = r0 & (SS - 1);
#pragma unroll
            for (int j = 0; j < 4; j++) {
                int e = j * 8 + (lane & 3) * 2;             // 0..30
                int n0 = bn * 128 + wn * 64 + e;
                float bx0 = bias[n0],      bx1 = bias[n0 + 1];
                float bx2 = bias[n0 + 32], bx3 = bias[n0 + 33];
                float2 c0 = *(const float2*)&g_cos[pos * 32 + e];
                float2 s0 = *(const float2*)&g_sin[pos * 32 + e];
                float2 c8 = *(const float2*)&g_cos[(pos + 8) * 32 + e];
                float2 s8 = *(const float2*)&g_sin[(pos + 8) * 32 + e];
                // row r0
                float x0  = acc[i][j][0] + bx0,     x0b = acc[i][j][1] + bx1;
                float x1  = acc[i][j + 4][0] + bx2, x1b = acc[i][j + 4][1] + bx3;
                store_bf2(Oh, Ol, (size_t)r0, n0,
                          (x0 * c0.x - x1 * s0.x) * osc, (x0b * c0.y - x1b * s0.y) * osc);
                store_bf2(Oh, Ol, (size_t)r0, n0 + 32,
                          (x1 * c0.x + x0 * s0.x) * osc, (x1b * c0.y + x0b * s0.y) * osc);
                // row r0 + 8
                float u0  = acc[i][j][2] + bx0,     u0b = acc[i][j][3] + bx1;
                float u1  = acc[i][j + 4][2] + bx2, u1b = acc[i][j + 4][3] + bx3;
                store_bf2(Oh, Ol, (size_t)(r0 + 8), n0,
                          (u0 * c8.x - u1 * s8.x) * osc, (u0b * c8.y - u1b * s8.y) * osc);
                store_bf2(Oh, Ol, (size_t)(r0 + 8), n0 + 32,
                          (u1 * c8.x + u0 * s8.x) * osc, (u1b * c8.y + u0b * s8.y) * osc);
            }
        }
    } else {
#pragma unroll
        for (int i = 0; i < 2; i++) {
            int r0 = bm * 128 + wm * 32 + i * 16 + (lane >> 2);
#pragma unroll
            for (int j = 0; j < 8; j++) {
                int n0 = bn * 128 + wn * 64 + j * 8 + (lane & 3) * 2;
                float bx = bias[n0], by = bias[n0 + 1];
                store_bf2(Oh, Ol, (size_t)r0,       n0, acc[i][j][0] + bx, acc[i][j][1] + by);
                store_bf2(Oh, Ol, (size_t)(r0 + 8), n0, acc[i][j][2] + bx, acc[i][j][3] + by);
            }
        }
    }
}

// ---------------------------------------------------------------- output GEMM (fp32 out)
__global__ void __launch_bounds__(256) tgemm_kernel(
        const __nv_bfloat16* __restrict__ Ah, const __nv_bfloat16* __restrict__ Al,
        const __nv_bfloat16* __restrict__ Bh, const __nv_bfloat16* __restrict__ Bl,
        const float* __restrict__ bias, float* __restrict__ C,
        int M, int N, int K) {
    extern __shared__ char sm[];
    uint32_t sb = smem_u32(sm);
    int tid = threadIdx.x;
    int lane = tid & 31, wid = tid >> 5;
    int wm = wid & 3, wn = wid >> 2;
    int bm = blockIdx.y, bn = blockIdx.x;

    const char* srcs[4] = {
        (const char*)(Ah + (size_t)bm * 128 * K),
        (const char*)(Al + (size_t)bm * 128 * K),
        (const char*)(Bh + (size_t)bn * 128 * K),
        (const char*)(Bl + (size_t)bn * 128 * K) };

    auto fill = [&](int s, int kc) {
        uint32_t base = sb + s * STAGE_B;
        size_t koff = (size_t)kc * KC * 2;
#pragma unroll
        for (int t = tid; t < 2048; t += 256) {
            int arr = t >> 9;
            int idx = t & 511;
            int row = idx >> 2, c = idx & 3;
            CP_ASYNC16(base + arr * TILE_B + row * (PK * 2) + c * 16,
                       srcs[arr] + (size_t)row * K * 2 + koff + c * 16);
        }
        CP_COMMIT();
    };

    float acc[2][8][4];
#pragma unroll
    for (int i = 0; i < 2; i++)
#pragma unroll
        for (int j = 0; j < 8; j++)
#pragma unroll
            for (int r = 0; r < 4; r++) acc[i][j][r] = 0.0f;

    int a_row = (lane & 7) + ((lane >> 3) & 1) * 8;
    int a_k   = (lane >> 4) * 8;
    int b_n   = ((lane >> 4) * 8) + (lane & 7);
    int b_k   = ((lane >> 3) & 1) * 8;

    int nk = K / KC;
    fill(0, 0);
    fill(1, 1);

    for (int c = 0; c < nk; c++) {
        int s = c & 1;
        if (c + 1 < nk) CP_WAIT1(); else CP_WAIT0();
        __syncthreads();

        uint32_t stb = sb + s * STAGE_B;
        uint32_t As_h = stb;
        uint32_t As_l = stb + TILE_B;
        uint32_t Bs_h = stb + 2 * TILE_B;
        uint32_t Bs_l = stb + 3 * TILE_B;

#pragma unroll
        for (int kk = 0; kk < 2; kk++) {
            uint32_t ah[2][4], al[2][4];
#pragma unroll
            for (int i = 0; i < 2; i++) {
                uint32_t off = ((wm * 32 + i * 16 + a_row) * PK + kk * 16 + a_k) * 2;
                LDSM_X4(ah[i][0], ah[i][1], ah[i][2], ah[i][3], As_h + off);
                LDSM_X4(al[i][0], al[i][1], al[i][2], al[i][3], As_l + off);
            }
#pragma unroll
            for (int jj = 0; jj < 4; jj++) {
                uint32_t boff = ((wn * 64 + jj * 16 + b_n) * PK + kk * 16 + b_k) * 2;
                uint32_t bh[4], bl[4];
                LDSM_X4(bh[0], bh[1], bh[2], bh[3], Bs_h + boff);
                LDSM_X4(bl[0], bl[1], bl[2], bl[3], Bs_l + boff);
#pragma unroll
                for (int i = 0; i < 2; i++) {
                    MMA_BF16(acc[i][2 * jj],     ah[i], bh[0], bh[1]);
                    MMA_BF16(acc[i][2 * jj + 1], ah[i], bh[2], bh[3]);
                    MMA_BF16(acc[i][2 * jj],     ah[i], bl[0], bl[1]);
                    MMA_BF16(acc[i][2 * jj + 1], ah[i], bl[2], bl[3]);
                    MMA_BF16(acc[i][2 * jj],     al[i], bh[0], bh[1]);
                    MMA_BF16(acc[i][2 * jj + 1], al[i], bh[2], bh[3]);
                }
            }
        }
        __syncthreads();
        if (c + 2 < nk) fill(s, c + 2);
    }

#pragma unroll
    for (int i = 0; i < 2; i++) {
        int r0 = bm * 128 + wm * 32 + i * 16 + (lane >> 2);
#pragma unroll
        for (int j = 0; j < 8; j++) {
            int c0 = bn * 128 + wn * 64 + j * 8 + (lane & 3) * 2;
            float bx = bias[c0], by = bias[c0 + 1];
            float2 v0 = make_float2(acc[i][j][0] + bx, acc[i][j][1] + by);
            float2 v1 = make_float2(acc[i][j][2] + bx, acc[i][j][3] + by);
            *(float2*)&C[(size_t)r0 * N + c0] = v0;
            *(float2*)&C[(size_t)(r0 + 8) * N + c0] = v1;
        }
    }
}

// ---------------------------------------------------------------- tensor-core flash attention
// q pre-scaled by 0.125*log2e -> use exp2.
#define APD 72
#define QT_B (128 * APD * 2)
#define KT_B (64 * APD * 2)
#define AT_SMEM (2 * QT_B + 2 * 4 * KT_B)

__global__ void __launch_bounds__(256) attn_tc_kernel(
        const __nv_bfloat16* __restrict__ Qh, const __nv_bfloat16* __restrict__ Ql,
        const __nv_bfloat16* __restrict__ Kh, const __nv_bfloat16* __restrict__ Kl,
        const __nv_bfloat16* __restrict__ Vh, const __nv_bfloat16* __restrict__ Vl,
        __nv_bfloat16* __restrict__ Zh, __nv_bfloat16* __restrict__ Zl) {
    extern __shared__ char sm[];
    uint32_t sb = smem_u32(sm);
    int tid = threadIdx.x, lane = tid & 31, wid = tid >> 5;

    int qt = (SS / 128 - 1) - blockIdx.x;   // heavy tiles first
    int h = blockIdx.y, b = blockIdx.z;
    int q0 = qt * 128;
    int nt = qt * 2 + 2;

    const char* gQ[2] = {
        (const char*)(Qh + ((size_t)b * SS + q0) * NC + h * DHD),
        (const char*)(Ql + ((size_t)b * SS + q0) * NC + h * DHD) };
    const char* gKV[4] = {
        (const char*)(Kh + (size_t)b * SS * NC + h * DHD),
        (const char*)(Kl + (size_t)b * SS * NC + h * DHD),
        (const char*)(Vh + (size_t)b * SS * NC + h * DHD),
        (const char*)(Vl + (size_t)b * SS * NC + h * DHD) };

    auto fillKV = [&](int s, int kt) {
        uint32_t base = sb + 2 * QT_B + s * 4 * KT_B;
        size_t roff = (size_t)(kt * 64) * (NC * 2);
#pragma unroll
        for (int t = tid; t < 2048; t += 256) {
            int arr = t >> 9, idx = t & 511;
            int row = idx >> 3, c = idx & 7;
            CP_ASYNC16(base + arr * KT_B + row * 144 + c * 16,
                       gKV[arr] + roff + (size_t)row * (NC * 2) + c * 16);
        }
        CP_COMMIT();
    };

#pragma unroll
    for (int t = tid; t < 2048; t += 256) {
        int arr = t >> 10, idx = t & 1023;
        int row = idx >> 3, c = idx & 7;
        CP_ASYNC16(sb + arr * QT_B + row * 144 + c * 16,
                   gQ[arr] + (size_t)row * (NC * 2) + c * 16);
    }
    fillKV(0, 0);

    float zacc[8][4];
#pragma unroll
    for (int j = 0; j < 8; j++)
#pragma unroll
        for (int r = 0; r < 4; r++) zacc[j][r] = 0.0f;
    float m0 = -1e30f, m1 = -1e30f, l0 = 0.0f, l1 = 0.0f;

    int a_row = (lane & 7) + ((lane >> 3) & 1) * 8;
    int a_k   = (lane >> 4) * 8;
    int b_n   = ((lane >> 4) * 8) + (lane & 7);
    int b_k   = ((lane >> 3) & 1) * 8;
    int v_r   = lane & 15;
    int v_c   = (lane >> 4) * 8;

    CP_WAIT0();
    __syncthreads();

    uint32_t qh_f[4][4], ql_f[4][4];
#pragma unroll
    for (int kc = 0; kc < 4; kc++) {
        uint32_t off = (wid * 16 + a_row) * 144 + (kc * 16 + a_k) * 2;
        LDSM_X4(qh_f[kc][0], qh_f[kc][1], qh_f[kc][2], qh_f[kc][3], sb + off);
        LDSM_X4(ql_f[kc][0], ql_f[kc][1], ql_f[kc][2], ql_f[kc][3], sb + QT_B + off);
    }

    int rbase = q0 + wid * 16 + (lane >> 2);

    for (int t = 0; t < nt; t++) {
        if (t + 1 < nt) fillKV((t + 1) & 1, t + 1);

        uint32_t sbK = sb + 2 * QT_B + (t & 1) * 4 * KT_B;
        int k0 = t * 64;

        float s[8][4];
#pragma unroll
        for (int j = 0; j < 8; j++)
#pragma unroll
            for (int r = 0; r < 4; r++) s[j][r] = 0.0f;

#pragma unroll
        for (int kc = 0; kc < 4; kc++) {
#pragma unroll
            for (int jj = 0; jj < 4; jj++) {
                uint32_t boff = (jj * 16 + b_n) * 144 + (kc * 16 + b_k) * 2;
                uint32_t kh[4], kl[4];
                LDSM_X4(kh[0], kh[1], kh[2], kh[3], sbK + boff);
                LDSM_X4(kl[0], kl[1], kl[2], kl[3], sbK + KT_B + boff);
                MMA_BF16(s[2 * jj],     qh_f[kc], kh[0], kh[1]);
                MMA_BF16(s[2 * jj + 1], qh_f[kc], kh[2], kh[3]);
                MMA_BF16(s[2 * jj],     qh_f[kc], kl[0], kl[1]);
                MMA_BF16(s[2 * jj + 1], qh_f[kc], kl[2], kl[3]);
                MMA_BF16(s[2 * jj],     ql_f[kc], kh[0], kh[1]);
                MMA_BF16(s[2 * jj + 1], ql_f[kc], kh[2], kh[3]);
            }
        }

        if (k0 + 63 > q0 + wid * 16) {
#pragma unroll
            for (int j = 0; j < 8; j++) {
                int kg = k0 + j * 8 + (lane & 3) * 2;
                if (kg > rbase)         s[j][0] = -1e30f;
                if (kg + 1 > rbase)     s[j][1] = -1e30f;
                if (kg > rbase + 8)     s[j][2] = -1e30f;
                if (kg + 1 > rbase + 8) s[j][3] = -1e30f;
            }
        }

        float rm0 = -1e30f, rm1 = -1e30f;
#pragma unroll
        for (int j = 0; j < 8; j++) {
            rm0 = fmaxf(rm0, fmaxf(s[j][0], s[j][1]));
            rm1 = fmaxf(rm1, fmaxf(s[j][2], s[j][3]));
        }
        rm0 = fmaxf(rm0, __shfl_xor_sync(0xffffffffu, rm0, 1));
        rm0 = fmaxf(rm0, __shfl_xor_sync(0xffffffffu, rm0, 2));
        rm1 = fmaxf(rm1, __shfl_xor_sync(0xffffffffu, rm1, 1));
        rm1 = fmaxf(rm1, __shfl_xor_sync(0xffffffffu, rm1, 2));
        float mn0 = fmaxf(m0, rm0), mn1 = fmaxf(m1, rm1);
        float cr0 = exp2f(m0 - mn0), cr1 = exp2f(m1 - mn1);
        float rs0 = 0.0f, rs1 = 0.0f;
#pragma unroll
        for (int j = 0; j < 8; j++) {
            s[j][0] = exp2f(s[j][0] - mn0);
            s[j][1] = exp2f(s[j][1] - mn0);
            s[j][2] = exp2f(s[j][2] - mn1);
            s[j][3] = exp2f(s[j][3] - mn1);
            rs0 += s[j][0] + s[j][1];
            rs1 += s[j][2] + s[j][3];
        }
        rs0 += __shfl_xor_sync(0xffffffffu, rs0, 1);
        rs0 += __shfl_xor_sync(0xffffffffu, rs0, 2);
        rs1 += __shfl_xor_sync(0xffffffffu, rs1, 1);
        rs1 += __shfl_xor_sync(0xffffffffu, rs1, 2);
        l0 = l0 * cr0 + rs0; l1 = l1 * cr1 + rs1;
        m0 = mn0; m1 = mn1;
#pragma unroll
        for (int j = 0; j < 8; j++) {
            zacc[j][0] *= cr0; zacc[j][1] *= cr0;
            zacc[j][2] *= cr1; zacc[j][3] *= cr1;
        }

        uint32_t ph[4][4], pl[4][4];
#pragma unroll
        for (int kc = 0; kc < 4; kc++) {
#pragma unroll
            for (int half = 0; half < 2; half++) {
                int j = 2 * kc + half;
                __nv_bfloat16 h0, lo0, h1, lo1, h2, lo2, h3, lo3;
                split_bf16(s[j][0], h0, lo0); split_bf16(s[j][1], h1, lo1);
                split_bf16(s[j][2], h2, lo2); split_bf16(s[j][3], h3, lo3);
                __nv_bfloat162 H01(h0, h1), H23(h2, h3), L01(lo0, lo1), L23(lo2, lo3);
                ph[kc][half * 2]     = *(uint32_t*)&H01;
                ph[kc][half * 2 + 1] = *(uint32_t*)&H23;
                pl[kc][half * 2]     = *(uint32_t*)&L01;
                pl[kc][half * 2 + 1] = *(uint32_t*)&L23;
            }
        }

#pragma unroll
        for (int kc = 0; kc < 4; kc++) {
#pragma unroll
            for (int jj = 0; jj < 4; jj++) {
                uint32_t voff = (kc * 16 + v_r) * 144 + (jj * 16 + v_c) * 2;
                uint32_t vh[4], vl[4];
                LDSM_X4_T(vh[0], vh[1], vh[2], vh[3], sbK + 2 * KT_B + voff);
                LDSM_X4_T(vl[0], vl[1], vl[2], vl[3], sbK + 3 * KT_B + voff);
                MMA_BF16(zacc[2 * jj],     ph[kc], vh[0], vh[1]);
                MMA_BF16(zacc[2 * jj + 1], ph[kc], vh[2], vh[3]);
                MMA_BF16(zacc[2 * jj],     ph[kc], vl[0], vl[1]);
                MMA_BF16(zacc[2 * jj + 1], ph[kc], vl[2], vl[3]);
                MMA_BF16(zacc[2 * jj],     pl[kc], vh[0], vh[1]);
                MMA_BF16(zacc[2 * jj + 1], pl[kc], vh[2], vh[3]);
            }
        }

        if (t + 1 < nt) {
            CP_WAIT0();
            __syncthreads();
        }
    }

    float inv0 = 1.0f / l0, inv1 = 1.0f / l1;
    size_t row0 = (size_t)b * SS + q0 + wid * 16 + (lane >> 2);
#pragma unroll
    for (int j = 0; j < 8; j++) {
        int col = h * DHD + j * 8 + (lane & 3) * 2;
        store_bf2(Zh, Zl, row0,     col, zacc[j][0] * inv0, zacc[j][1] * inv0);
        store_bf2(Zh, Zl, row0 + 8, col, zacc[j][2] * inv1, zacc[j][3] * inv1);
    }
}

// ---------------------------------------------------------------- launch
extern "C" void kernel_launch(void* const* d_in, const int* in_sizes, int n_in,
                              void* d_out, int out_size) {
    const float* Xq  = (const float*)d_in[0];
    const float* Xk  = (const float*)d_in[1];
    const float* Xv  = (const float*)d_in[2];
    const float* WQ  = (const float*)d_in[3];
    const float* WK  = (const float*)d_in[4];
    const float* WV  = (const float*)d_in[5];
    const float* WO  = (const float*)d_in[6];
    const float* bQ  = (const float*)d_in[7];
    const float* bK  = (const float*)d_in[8];
    const float* bV  = (const float*)d_in[9];
    const float* bO  = (const float*)d_in[10];
    float* out = (float*)d_out;

    static bool init = false;
    static __nv_bfloat16 *pWqh, *pWql, *pWkh, *pWkl, *pWvh, *pWvl, *pWoh, *pWol;
    static __nv_bfloat16 *pXqh, *pXql, *pXkh, *pXkl, *pXvh, *pXvl, *pzh, *pzl;
    static __nv_bfloat16 *pqh, *pql, *pkh, *pkl, *pvh, *pvl;
    static float *pbq, *pbk, *pbv;
    if (!init) {
        cudaGetSymbolAddress((void**)&pWqh, g_Wqh); cudaGetSymbolAddress((void**)&pWql, g_Wql);
        cudaGetSymbolAddress((void**)&pWkh, g_Wkh); cudaGetSymbolAddress((void**)&pWkl, g_Wkl);
        cudaGetSymbolAddress((void**)&pWvh, g_Wvh); cudaGetSymbolAddress((void**)&pWvl, g_Wvl);
        cudaGetSymbolAddress((void**)&pWoh, g_Woh); cudaGetSymbolAddress((void**)&pWol, g_Wol);
        cudaGetSymbolAddress((void**)&pXqh, g_Xqh); cudaGetSymbolAddress((void**)&pXql, g_Xql);
        cudaGetSymbolAddress((void**)&pXkh, g_Xkh); cudaGetSymbolAddress((void**)&pXkl, g_Xkl);
        cudaGetSymbolAddress((void**)&pXvh, g_Xvh); cudaGetSymbolAddress((void**)&pXvl, g_Xvl);
        cudaGetSymbolAddress((void**)&pzh,  g_zh);  cudaGetSymbolAddress((void**)&pzl,  g_zl);
        cudaGetSymbolAddress((void**)&pqh, g_qh);   cudaGetSymbolAddress((void**)&pql, g_ql);
        cudaGetSymbolAddress((void**)&pkh, g_kh);   cudaGetSymbolAddress((void**)&pkl, g_kl);
        cudaGetSymbolAddress((void**)&pvh, g_vh);   cudaGetSymbolAddress((void**)&pvl, g_vl);
        cudaGetSymbolAddress((void**)&pbq, g_bq); cudaGetSymbolAddress((void**)&pbk, g_bk);
        cudaGetSymbolAddress((void**)&pbv, g_bv);
        cudaFuncSetAttribute(tgemm_kernel, cudaFuncAttributeMaxDynamicSharedMemorySize, GEMM_SMEM);
        cudaFuncSetAttribute(qkv_gemm_kernel, cudaFuncAttributeMaxDynamicSharedMemorySize, GEMM_SMEM);
        cudaFuncSetAttribute(attn_tc_kernel, cudaFuncAttributeMaxDynamicSharedMemorySize, AT_SMEM);
        init = true;
    }

    // 1) amax (batched)
    reset_kernel<<<1, 32>>>();
    amax3_kernel<<<dim3(256, 3), 256>>>((const float4*)WQ, (const float4*)WK, (const float4*)WV, WN / 4, 0);
    amax3_kernel<<<dim3(1, 3), 256>>>((const float4*)bQ, (const float4*)bK, (const float4*)bV, NC / 4, 3);

    // 2) rotary table (needed by QKV epilogue)
    sincos_kernel<<<SS * 32 / 256, 256>>>();

    // 3) weight qdq + transpose + split (batched), WO transpose, bias qdq (batched)
    quant_w_t3_kernel<<<dim3(DD / 32, 6, HH), dim3(32, 32)>>>(
        WQ, WK, WV, pWqh, pWql, pWkh, pWkl, pWvh, pWvl);
    wo_t_kernel<<<dim3(DD / 32, NC / 32), dim3(32, 32)>>>(WO, pWoh, pWol);
    quant_b3_kernel<<<dim3(4, 3), 256>>>(bQ, bK, bV, pbq, pbk, pbv);

    // 4) input split (batched)
    int n4 = (MR * DD) / 4;
    split3_kernel<<<dim3((n4 + 255) / 256, 3), 256>>>(
        (const float4*)Xq, (const float4*)Xk, (const float4*)Xv,
        (__nv_bfloat162*)pXqh, (__nv_bfloat162*)pXql,
        (__nv_bfloat162*)pXkh, (__nv_bfloat162*)pXkl,
        (__nv_bfloat162*)pXvh, (__nv_bfloat162*)pXvl, n4);

    // 5) fused QKV projection + bias + rotary + split (one launch, 768 CTAs)
    QKVParams P;
    P.Ah[0] = pXqh; P.Al[0] = pXql; P.Bh[0] = pWqh; P.Bl[0] = pWql; P.bias[0] = pbq; P.Oh[0] = pqh; P.Ol[0] = pql;
    P.Ah[1] = pXkh; P.Al[1] = pXkl; P.Bh[1] = pWkh; P.Bl[1] = pWkl; P.bias[1] = pbk; P.Oh[1] = pkh; P.Ol[1] = pkl;
    P.Ah[2] = pXvh; P.Al[2] = pXvl; P.Bh[2] = pWvh; P.Bl[2] = pWvl; P.bias[2] = pbv; P.Oh[2] = pvh; P.Ol[2] = pvl;
    qkv_gemm_kernel<<<dim3(NC / 128, MR / 128, 3), 256, GEMM_SMEM>>>(P);

    // 6) tensor-core flash attention (exp2 path) -> z hi/lo
    dim3 ag(SS / 128, HH, BB);
    attn_tc_kernel<<<ag, 256, AT_SMEM>>>(pqh, pql, pkh, pkl, pvh, pvl, pzh, pzl);

    // 7) output projection
    dim3 gg(DD / 128, MR / 128);
    tgemm_kernel<<<gg, 256, GEMM_SMEM>>>(pzh, pzl, pWoh, pWol, bO, out, MR, DD, NC);
}

// round 11
// speedup vs baseline: 1.6698x; 1.0404x over previous
#include <cuda_runtime.h>
#include <cuda_bf16.h>
#include <math.h>
#include <stdint.h>

// Problem constants
#define BB   2
#define SS   2048
#define DD   1024
#define HH   16
#define DHD  64
#define MR   (BB*SS)        // 4096
#define NC   (HH*DHD)       // 1024
#define WN   (HH*DD*DHD)    // 1048576
#define LOG2E 1.4426950408889634f

// ---------------------------------------------------------------- helpers
__device__ __forceinline__ uint32_t smem_u32(const void* p) {
    uint32_t a;
    asm("{ .reg .u64 t; cvta.to.shared.u64 t, %1; cvt.u32.u64 %0, t; }" : "=r"(a) : "l"(p));
    return a;
}

#define CP_ASYNC16(dst, src) asm volatile("cp.async.cg.shared.global [%0], [%1], 16;" :: "r"(dst), "l"(src))
#define CP_COMMIT()  asm volatile("cp.async.commit_group;" ::: "memory")
#define CP_WAIT1()   asm volatile("cp.async.wait_group 1;" ::: "memory")
#define CP_WAIT0()   asm volatile("cp.async.wait_group 0;" ::: "memory")

#define LDSM_X4(r0, r1, r2, r3, addr) \
    asm volatile("ldmatrix.sync.aligned.m8n8.x4.shared.b16 {%0,%1,%2,%3}, [%4];" \
                 : "=r"(r0), "=r"(r1), "=r"(r2), "=r"(r3) : "r"(addr))

#define LDSM_X4_T(r0, r1, r2, r3, addr) \
    asm volatile("ldmatrix.sync.aligned.m8n8.x4.trans.shared.b16 {%0,%1,%2,%3}, [%4];" \
                 : "=r"(r0), "=r"(r1), "=r"(r2), "=r"(r3) : "r"(addr))

#define MMA_BF16(c, a, b0, b1) \
    asm volatile("mma.sync.aligned.m16n8k16.row.col.f32.bf16.bf16.f32 " \
                 "{%0,%1,%2,%3}, {%4,%5,%6,%7}, {%8,%9}, {%0,%1,%2,%3};" \
                 : "+f"((c)[0]), "+f"((c)[1]), "+f"((c)[2]), "+f"((c)[3]) \
                 : "r"((a)[0]), "r"((a)[1]), "r"((a)[2]), "r"((a)[3]), "r"(b0), "r"(b1))

// fast exp2 (args <= 0 in our use; -1e30 underflows to 0)
__device__ __forceinline__ float ex2a(float x) {
    float y;
    asm("ex2.approx.ftz.f32 %0, %1;" : "=f"(y) : "f"(x));
    return y;
}

// ---------------------------------------------------------------- scratch
__device__ unsigned g_amax[6];
__device__ double g_invf[32];
__device__ __nv_bfloat16 g_Wqh[DD*NC], g_Wql[DD*NC];
__device__ __nv_bfloat16 g_Wkh[DD*NC], g_Wkl[DD*NC];
__device__ __nv_bfloat16 g_Wvh[DD*NC], g_Wvl[DD*NC];
__device__ __nv_bfloat16 g_Woh[NC*DD], g_Wol[NC*DD];
__device__ __nv_bfloat16 g_Xqh[(size_t)MR*DD], g_Xql[(size_t)MR*DD];
__device__ __nv_bfloat16 g_Xkh[(size_t)MR*DD], g_Xkl[(size_t)MR*DD];
__device__ __nv_bfloat16 g_Xvh[(size_t)MR*DD], g_Xvl[(size_t)MR*DD];
__device__ __nv_bfloat16 g_qh[(size_t)MR*NC], g_ql[(size_t)MR*NC];
__device__ __nv_bfloat16 g_kh[(size_t)MR*NC], g_kl[(size_t)MR*NC];
__device__ __nv_bfloat16 g_vh[(size_t)MR*NC], g_vl[(size_t)MR*NC];
__device__ __nv_bfloat16 g_zh[(size_t)MR*NC], g_zl[(size_t)MR*NC];
__device__ float g_bq[NC], g_bk[NC], g_bv[NC];
__device__ float g_sin[SS*32], g_cos[SS*32];

// ---------------------------------------------------------------- qdq
__device__ __forceinline__ float qdq(float w, float amax) {
    float scale = 448.0f / fmaxf(amax, 1e-12f);
    float v = w * scale;
    float a = fabsf(v);
    int ex;
    frexpf(fmaxf(a, 1e-30f), &ex);
    float e = fminf(fmaxf((float)(ex - 1), -6.0f), 8.0f);
    float step = exp2f(e - 3.0f);
    float q = rintf(v / step) * step;
    q = fminf(fmaxf(q, -448.0f), 448.0f);
    return q / scale;
}

__global__ void reset_kernel() {
    if (threadIdx.x < 6) g_amax[threadIdx.x] = 0u;
    if (threadIdx.x < 32)
        g_invf[threadIdx.x] = pow(10000.0, -(double)threadIdx.x / 32.0);
}

// batched amax over 3 arrays (slot = slot0 + blockIdx.y)
__global__ void amax3_kernel(const float4* __restrict__ a, const float4* __restrict__ b,
                             const float4* __restrict__ c, int n4, int slot0) {
    __shared__ float red[256];
    const float4* x = (blockIdx.y == 0) ? a : (blockIdx.y == 1) ? b : c;
    float m = 0.0f;
    for (int i = blockIdx.x * blockDim.x + threadIdx.x; i < n4; i += gridDim.x * blockDim.x) {
        float4 v = x[i];
        m = fmaxf(m, fmaxf(fmaxf(fabsf(v.x), fabsf(v.y)), fmaxf(fabsf(v.z), fabsf(v.w))));
    }
    red[threadIdx.x] = m;
    __syncthreads();
    for (int s = 128; s > 0; s >>= 1) {
        if (threadIdx.x < s) red[threadIdx.x] = fmaxf(red[threadIdx.x], red[threadIdx.x + s]);
        __syncthreads();
    }
    if (threadIdx.x == 0) atomicMax(&g_amax[slot0 + blockIdx.y], __float_as_uint(red[0]));
}

__device__ __forceinline__ void split_bf16(float x, __nv_bfloat16& h, __nv_bfloat16& l) {
    h = __float2bfloat16(x);
    l = __float2bfloat16(x - __bfloat162float(h));
}

// batched: qdq + transpose W[h,d,e] -> B[n=h*64+e][k=d], split hi/lo. op = blockIdx.y>>1
__global__ void quant_w_t3_kernel(const float* __restrict__ W0, const float* __restrict__ W1,
                                  const float* __restrict__ W2,
                                  __nv_bfloat16* __restrict__ Bh0, __nv_bfloat16* __restrict__ Bl0,
                                  __nv_bfloat16* __restrict__ Bh1, __nv_bfloat16* __restrict__ Bl1,
                                  __nv_bfloat16* __restrict__ Bh2, __nv_bfloat16* __restrict__ Bl2) {
    __shared__ float t[32][33];
    int op = blockIdx.y >> 1;
    int ey = blockIdx.y & 1;
    const float* W = (op == 0) ? W0 : (op == 1) ? W1 : W2;
    __nv_bfloat16* Bh = (op == 0) ? Bh0 : (op == 1) ? Bh1 : Bh2;
    __nv_bfloat16* Bl = (op == 0) ? Bl0 : (op == 1) ? Bl1 : Bl2;
    float amax = __uint_as_float(g_amax[op]);
    int h = blockIdx.z;
    int d = blockIdx.x * 32 + threadIdx.y;
    int e = ey * 32 + threadIdx.x;
    t[threadIdx.y][threadIdx.x] = qdq(W[(size_t)h * DD * DHD + d * DHD + e], amax);
    __syncthreads();
    int n = h * DHD + ey * 32 + threadIdx.y;
    int k = blockIdx.x * 32 + threadIdx.x;
    __nv_bfloat16 hi, lo;
    split_bf16(t[threadIdx.x][threadIdx.y], hi, lo);
    Bh[(size_t)n * DD + k] = hi;
    Bl[(size_t)n * DD + k] = lo;
}

// transpose WO[he][d] -> B[n=d][k=he], split (no qdq)
__global__ void wo_t_kernel(const float* __restrict__ W,
                            __nv_bfloat16* __restrict__ Bh, __nv_bfloat16* __restrict__ Bl) {
    __shared__ float t[32][33];
    int he = blockIdx.y * 32 + threadIdx.y;
    int d  = blockIdx.x * 32 + threadIdx.x;
    t[threadIdx.y][threadIdx.x] = W[(size_t)he * DD + d];
    __syncthreads();
    int n = blockIdx.x * 32 + threadIdx.y;
    int k = blockIdx.y * 32 + threadIdx.x;
    __nv_bfloat16 hi, lo;
    split_bf16(t[threadIdx.x][threadIdx.y], hi, lo);
    Bh[(size_t)n * NC + k] = hi;
    Bl[(size_t)n * NC + k] = lo;
}

// batched bias qdq
__global__ void quant_b3_kernel(const float* __restrict__ b0, const float* __restrict__ b1,
                                const float* __restrict__ b2,
                                float* __restrict__ o0, float* __restrict__ o1, float* __restrict__ o2) {
    int which = blockIdx.y;
    const float* b = (which == 0) ? b0 : (which == 1) ? b1 : b2;
    float* o = (which == 0) ? o0 : (which == 1) ? o1 : o2;
    int idx = blockIdx.x * 256 + threadIdx.x;
    if (idx >= NC) return;
    float amax = __uint_as_float(g_amax[3 + which]);
    o[idx] = qdq(b[idx], amax);
}

// batched fp32 -> bf16 hi/lo split
__global__ void split3_kernel(const float4* __restrict__ x0, const float4* __restrict__ x1,
                              const float4* __restrict__ x2,
                              __nv_bfloat162* __restrict__ h0, __nv_bfloat162* __restrict__ l0,
                              __nv_bfloat162* __restrict__ h1, __nv_bfloat162* __restrict__ l1,
                              __nv_bfloat162* __restrict__ h2, __nv_bfloat162* __restrict__ l2,
                              int n4) {
    int which = blockIdx.y;
    const float4* x = (which == 0) ? x0 : (which == 1) ? x1 : x2;
    __nv_bfloat162* hi = (which == 0) ? h0 : (which == 1) ? h1 : h2;
    __nv_bfloat162* lo = (which == 0) ? l0 : (which == 1) ? l1 : l2;
    int i = blockIdx.x * 256 + threadIdx.x;
    if (i >= n4) return;
    float4 v = x[i];
    __nv_bfloat16 a0, a1, a2, a3, b0, b1, b2, b3;
    split_bf16(v.x, a0, b0);
    split_bf16(v.y, a1, b1);
    split_bf16(v.z, a2, b2);
    split_bf16(v.w, a3, b3);
    hi[2*i]   = __nv_bfloat162(a0, a1);
    hi[2*i+1] = __nv_bfloat162(a2, a3);
    lo[2*i]   = __nv_bfloat162(b0, b1);
    lo[2*i+1] = __nv_bfloat162(b2, b3);
}

// ---------------------------------------------------------------- rotary table
// ang in fp32 (matches ref rounding); exact 2*pi range reduction in double;
// fp32 sin/cos on r in [-pi, pi].
__global__ void sincos_kernel() {
    int idx = blockIdx.x * 256 + threadIdx.x;
    if (idx >= SS * 32) return;
    int pos = idx >> 5, i = idx & 31;
    float invf = (float)g_invf[i];
    float ang  = (float)pos * invf;
    double a = (double)ang;
    double k = rint(a * 0.15915494309189535);         // 1/(2*pi)
    float r = (float)(a - k * 6.283185307179586);
    g_sin[idx] = sinf(r);
    g_cos[idx] = cosf(r);
}

// ---------------------------------------------------------------- GEMM common
// 2-stage cp.async pipeline, PK=40 (80B rows: 16B-aligned, LDSM conflict-free).
#define KC 32
#define PK 40
#define TILE_B (128 * PK * 2)       // 10240
#define STAGE_B (4 * TILE_B)        // 40960
#define GEMM_SMEM (2 * STAGE_B)     // 81920

__device__ __forceinline__ void store_bf2(__nv_bfloat16* Oh, __nv_bfloat16* Ol,
                                          size_t row, int col, float a, float b) {
    __nv_bfloat16 ha, la, hb, lb;
    split_bf16(a, ha, la);
    split_bf16(b, hb, lb);
    __nv_bfloat162 H(ha, hb), L(la, lb);
    *(uint32_t*)&Oh[row * NC + col] = *(uint32_t*)&H;
    *(uint32_t*)&Ol[row * NC + col] = *(uint32_t*)&L;
}

// ---------------------------------------------------------------- fused QKV GEMM
struct QKVParams {
    const __nv_bfloat16 *Ah[3], *Al[3], *Bh[3], *Bl[3];
    const float* bias[3];
    __nv_bfloat16 *Oh[3], *Ol[3];
};

__global__ void __launch_bounds__(256) qkv_gemm_kernel(QKVParams P) {
    extern __shared__ char sm[];
    uint32_t sb = smem_u32(sm);
    int tid = threadIdx.x;
    int lane = tid & 31, wid = tid >> 5;
    int wm = wid & 3, wn = wid >> 2;
    int bm = blockIdx.y, bn = blockIdx.x;
    int op = blockIdx.z;

    const char* srcs[4] = {
        (const char*)(P.Ah[op] + (size_t)bm * 128 * DD),
        (const char*)(P.Al[op] + (size_t)bm * 128 * DD),
        (const char*)(P.Bh[op] + (size_t)bn * 128 * DD),
        (const char*)(P.Bl[op] + (size_t)bn * 128 * DD) };

    auto fill = [&](int s, int kc) {
        uint32_t base = sb + s * STAGE_B;
        size_t koff = (size_t)kc * KC * 2;
#pragma unroll
        for (int t = tid; t < 2048; t += 256) {
            int arr = t >> 9;
            int idx = t & 511;
            int row = idx >> 2, c = idx & 3;
            CP_ASYNC16(base + arr * TILE_B + row * (PK * 2) + c * 16,
                       srcs[arr] + (size_t)row * DD * 2 + koff + c * 16);
        }
        CP_COMMIT();
    };

    float acc[2][8][4];
#pragma unroll
    for (int i = 0; i < 2; i++)
#pragma unroll
        for (int j = 0; j < 8; j++)
#pragma unroll
            for (int r = 0; r < 4; r++) acc[i][j][r] = 0.0f;

    int a_row = (lane & 7) + ((lane >> 3) & 1) * 8;
    int a_k   = (lane >> 4) * 8;
    int b_n   = ((lane >> 4) * 8) + (lane & 7);
    int b_k   = ((lane >> 3) & 1) * 8;

    const int nk = DD / KC;
    fill(0, 0);
    fill(1, 1);

    for (int c = 0; c < nk; c++) {
        int s = c & 1;
        if (c + 1 < nk) CP_WAIT1(); else CP_WAIT0();
        __syncthreads();

        uint32_t stb = sb + s * STAGE_B;
        uint32_t As_h = stb;
        uint32_t As_l = stb + TILE_B;
        uint32_t Bs_h = stb + 2 * TILE_B;
        uint32_t Bs_l = stb + 3 * TILE_B;

#pragma unroll
        for (int kk = 0; kk < 2; kk++) {
            uint32_t ah[2][4], al[2][4];
#pragma unroll
            for (int i = 0; i < 2; i++) {
                uint32_t off = ((wm * 32 + i * 16 + a_row) * PK + kk * 16 + a_k) * 2;
                LDSM_X4(ah[i][0], ah[i][1], ah[i][2], ah[i][3], As_h + off);
                LDSM_X4(al[i][0], al[i][1], al[i][2], al[i][3], As_l + off);
            }
#pragma unroll
            for (int jj = 0; jj < 4; jj++) {
                uint32_t boff = ((wn * 64 + jj * 16 + b_n) * PK + kk * 16 + b_k) * 2;
                uint32_t bh[4], bl[4];
                LDSM_X4(bh[0], bh[1], bh[2], bh[3], Bs_h + boff);
                LDSM_X4(bl[0], bl[1], bl[2], bl[3], Bs_l + boff);
#pragma unroll
                for (int i = 0; i < 2; i++) {
                    MMA_BF16(acc[i][2 * jj],     ah[i], bh[0], bh[1]);
                    MMA_BF16(acc[i][2 * jj + 1], ah[i], bh[2], bh[3]);
                    MMA_BF16(acc[i][2 * jj],     ah[i], bl[0], bl[1]);
                    MMA_BF16(acc[i][2 * jj + 1], ah[i], bl[2], bl[3]);
                    MMA_BF16(acc[i][2 * jj],     al[i], bh[0], bh[1]);
                    MMA_BF16(acc[i][2 * jj + 1], al[i], bh[2], bh[3]);
                }
            }
        }
        __syncthreads();
        if (c + 2 < nk) fill(s, c + 2);
    }

    const float* bias = P.bias[op];
    __nv_bfloat16* Oh = P.Oh[op];
    __nv_bfloat16* Ol = P.Ol[op];

    if (op < 2) {
        float osc = (op == 0) ? 0.125f * LOG2E : 1.0f;
#pragma unroll
        for (int i = 0; i < 2; i++) {
            int r0 = bm * 128 + wm * 32 + i * 16 + (lane >> 2);
            int pos = r0 & (SS - 1);
#pragma unroll
            for (int j = 0; j < 4; j++) {
                int e = j * 8 + (lane & 3) * 2;
                int n0 = bn * 128 + wn * 64 + e;
                float bx0 = bias[n0],      bx1 = bias[n0 + 1];
                float bx2 = bias[n0 + 32], bx3 = bias[n0 + 33];
                float2 c0 = *(const float2*)&g_cos[pos * 32 + e];
                float2 s0 = *(const float2*)&g_sin[pos * 32 + e];
                float2 c8 = *(const float2*)&g_cos[(pos + 8) * 32 + e];
                float2 s8 = *(const float2*)&g_sin[(pos + 8) * 32 + e];
                float x0  = acc[i][j][0] + bx0,     x0b = acc[i][j][1] + bx1;
                float x1  = acc[i][j + 4][0] + bx2, x1b = acc[i][j + 4][1] + bx3;
                store_bf2(Oh, Ol, (size_t)r0, n0,
                          (x0 * c0.x - x1 * s0.x) * osc, (x0b * c0.y - x1b * s0.y) * osc);
                store_bf2(Oh, Ol, (size_t)r0, n0 + 32,
                          (x1 * c0.x + x0 * s0.x) * osc, (x1b * c0.y + x0b * s0.y) * osc);
                float u0  = acc[i][j][2] + bx0,     u0b = acc[i][j][3] + bx1;
                float u1  = acc[i][j + 4][2] + bx2, u1b = acc[i][j + 4][3] + bx3;
                store_bf2(Oh, Ol, (size_t)(r0 + 8), n0,
                          (u0 * c8.x - u1 * s8.x) * osc, (u0b * c8.y - u1b * s8.y) * osc);
                store_bf2(Oh, Ol, (size_t)(r0 + 8), n0 + 32,
                          (u1 * c8.x + u0 * s8.x) * osc, (u1b * c8.y + u0b * s8.y) * osc);
            }
        }
    } else {
#pragma unroll
        for (int i = 0; i < 2; i++) {
            int r0 = bm * 128 + wm * 32 + i * 16 + (lane >> 2);
#pragma unroll
            for (int j = 0; j < 8; j++) {
                int n0 = bn * 128 + wn * 64 + j * 8 + (lane & 3) * 2;
                float bx = bias[n0], by = bias[n0 + 1];
                store_bf2(Oh, Ol, (size_t)r0,       n0, acc[i][j][0] + bx, acc[i][j][1] + by);
                store_bf2(Oh, Ol, (size_t)(r0 + 8), n0, acc[i][j][2] + bx, acc[i][j][3] + by);
            }
        }
    }
}

// ---------------------------------------------------------------- output GEMM (fp32 out)
__global__ void __launch_bounds__(256) tgemm_kernel(
        const __nv_bfloat16* __restrict__ Ah, const __nv_bfloat16* __restrict__ Al,
        const __nv_bfloat16* __restrict__ Bh, const __nv_bfloat16* __restrict__ Bl,
        const float* __restrict__ bias, float* __restrict__ C,
        int M, int N, int K) {
    extern __shared__ char sm[];
    uint32_t sb = smem_u32(sm);
    int tid = threadIdx.x;
    int lane = tid & 31, wid = tid >> 5;
    int wm = wid & 3, wn = wid >> 2;
    int bm = blockIdx.y, bn = blockIdx.x;

    const char* srcs[4] = {
        (const char*)(Ah + (size_t)bm * 128 * K),
        (const char*)(Al + (size_t)bm * 128 * K),
        (const char*)(Bh + (size_t)bn * 128 * K),
        (const char*)(Bl + (size_t)bn * 128 * K) };

    auto fill = [&](int s, int kc) {
        uint32_t base = sb + s * STAGE_B;
        size_t koff = (size_t)kc * KC * 2;
#pragma unroll
        for (int t = tid; t < 2048; t += 256) {
            int arr = t >> 9;
            int idx = t & 511;
            int row = idx >> 2, c = idx & 3;
            CP_ASYNC16(base + arr * TILE_B + row * (PK * 2) + c * 16,
                       srcs[arr] + (size_t)row * K * 2 + koff + c * 16);
        }
        CP_COMMIT();
    };

    float acc[2][8][4];
#pragma unroll
    for (int i = 0; i < 2; i++)
#pragma unroll
        for (int j = 0; j < 8; j++)
#pragma unroll
            for (int r = 0; r < 4; r++) acc[i][j][r] = 0.0f;

    int a_row = (lane & 7) + ((lane >> 3) & 1) * 8;
    int a_k   = (lane >> 4) * 8;
    int b_n   = ((lane >> 4) * 8) + (lane & 7);
    int b_k   = ((lane >> 3) & 1) * 8;

    int nk = K / KC;
    fill(0, 0);
    fill(1, 1);

    for (int c = 0; c < nk; c++) {
        int s = c & 1;
        if (c + 1 < nk) CP_WAIT1(); else CP_WAIT0();
        __syncthreads();

        uint32_t stb = sb + s * STAGE_B;
        uint32_t As_h = stb;
        uint32_t As_l = stb + TILE_B;
        uint32_t Bs_h = stb + 2 * TILE_B;
        uint32_t Bs_l = stb + 3 * TILE_B;

#pragma unroll
        for (int kk = 0; kk < 2; kk++) {
            uint32_t ah[2][4], al[2][4];
#pragma unroll
            for (int i = 0; i < 2; i++) {
                uint32_t off = ((wm * 32 + i * 16 + a_row) * PK + kk * 16 + a_k) * 2;
                LDSM_X4(ah[i][0], ah[i][1], ah[i][2], ah[i][3], As_h + off);
                LDSM_X4(al[i][0], al[i][1], al[i][2], al[i][3], As_l + off);
            }
#pragma unroll
            for (int jj = 0; jj < 4; jj++) {
                uint32_t boff = ((wn * 64 + jj * 16 + b_n) * PK + kk * 16 + b_k) * 2;
                uint32_t bh[4], bl[4];
                LDSM_X4(bh[0], bh[1], bh[2], bh[3], Bs_h + boff);
                LDSM_X4(bl[0], bl[1], bl[2], bl[3], Bs_l + boff);
#pragma unroll
                for (int i = 0; i < 2; i++) {
                    MMA_BF16(acc[i][2 * jj],     ah[i], bh[0], bh[1]);
                    MMA_BF16(acc[i][2 * jj + 1], ah[i], bh[2], bh[3]);
                    MMA_BF16(acc[i][2 * jj],     ah[i], bl[0], bl[1]);
                    MMA_BF16(acc[i][2 * jj + 1], ah[i], bl[2], bl[3]);
                    MMA_BF16(acc[i][2 * jj],     al[i], bh[0], bh[1]);
                    MMA_BF16(acc[i][2 * jj + 1], al[i], bh[2], bh[3]);
                }
            }
        }
        __syncthreads();
        if (c + 2 < nk) fill(s, c + 2);
    }

#pragma unroll
    for (int i = 0; i < 2; i++) {
        int r0 = bm * 128 + wm * 32 + i * 16 + (lane >> 2);
#pragma unroll
        for (int j = 0; j < 8; j++) {
            int c0 = bn * 128 + wn * 64 + j * 8 + (lane & 3) * 2;
            float bx = bias[c0], by = bias[c0 + 1];
            float2 v0 = make_float2(acc[i][j][0] + bx, acc[i][j][1] + by);
            float2 v1 = make_float2(acc[i][j][2] + bx, acc[i][j][3] + by);
            *(float2*)&C[(size_t)r0 * N + c0] = v0;
            *(float2*)&C[(size_t)(r0 + 8) * N + c0] = v1;
        }
    }
}

// ---------------------------------------------------------------- tensor-core flash attention
#define APD 72
#define QT_B (128 * APD * 2)
#define KT_B (64 * APD * 2)
#define AT_SMEM (2 * QT_B + 2 * 4 * KT_B)

__global__ void __launch_bounds__(256) attn_tc_kernel(
        const __nv_bfloat16* __restrict__ Qh, const __nv_bfloat16* __restrict__ Ql,
        const __nv_bfloat16* __restrict__ Kh, const __nv_bfloat16* __restrict__ Kl,
        const __nv_bfloat16* __restrict__ Vh, const __nv_bfloat16* __restrict__ Vl,
        __nv_bfloat16* __restrict__ Zh, __nv_bfloat16* __restrict__ Zl) {
    extern __shared__ char sm[];
    uint32_t sb = smem_u32(sm);
    int tid = threadIdx.x, lane = tid & 31, wid = tid >> 5;

    int qt = (SS / 128 - 1) - blockIdx.x;   // heavy tiles first
    int h = blockIdx.y, b = blockIdx.z;
    int q0 = qt * 128;
    int nt = qt * 2 + 2;

    const char* gQ[2] = {
        (const char*)(Qh + ((size_t)b * SS + q0) * NC + h * DHD),
        (const char*)(Ql + ((size_t)b * SS + q0) * NC + h * DHD) };
    const char* gKV[4] = {
        (const char*)(Kh + (size_t)b * SS * NC + h * DHD),
        (const char*)(Kl + (size_t)b * SS * NC + h * DHD),
        (const char*)(Vh + (size_t)b * SS * NC + h * DHD),
        (const char*)(Vl + (size_t)b * SS * NC + h * DHD) };

    auto fillKV = [&](int s, int kt) {
        uint32_t base = sb + 2 * QT_B + s * 4 * KT_B;
        size_t roff = (size_t)(kt * 64) * (NC * 2);
#pragma unroll
        for (int t = tid; t < 2048; t += 256) {
            int arr = t >> 9, idx = t & 511;
            int row = idx >> 3, c = idx & 7;
            CP_ASYNC16(base + arr * KT_B + row * 144 + c * 16,
                       gKV[arr] + roff + (size_t)row * (NC * 2) + c * 16);
        }
        CP_COMMIT();
    };

#pragma unroll
    for (int t = tid; t < 2048; t += 256) {
        int arr = t >> 10, idx = t & 1023;
        int row = idx >> 3, c = idx & 7;
        CP_ASYNC16(sb + arr * QT_B + row * 144 + c * 16,
                   gQ[arr] + (size_t)row * (NC * 2) + c * 16);
    }
    fillKV(0, 0);

    float zacc[8][4];
#pragma unroll
    for (int j = 0; j < 8; j++)
#pragma unroll
        for (int r = 0; r < 4; r++) zacc[j][r] = 0.0f;
    float m0 = -1e30f, m1 = -1e30f, l0 = 0.0f, l1 = 0.0f;

    int a_row = (lane & 7) + ((lane >> 3) & 1) * 8;
    int a_k   = (lane >> 4) * 8;
    int b_n   = ((lane >> 4) * 8) + (lane & 7);
    int b_k   = ((lane >> 3) & 1) * 8;
    int v_r   = lane & 15;
    int v_c   = (lane >> 4) * 8;

    CP_WAIT0();
    __syncthreads();

    uint32_t qh_f[4][4], ql_f[4][4];
#pragma unroll
    for (int kc = 0; kc < 4; kc++) {
        uint32_t off = (wid * 16 + a_row) * 144 + (kc * 16 + a_k) * 2;
        LDSM_X4(qh_f[kc][0], qh_f[kc][1], qh_f[kc][2], qh_f[kc][3], sb + off);
        LDSM_X4(ql_f[kc][0], ql_f[kc][1], ql_f[kc][2], ql_f[kc][3], sb + QT_B + off);
    }

    int rbase = q0 + wid * 16 + (lane >> 2);

    for (int t = 0; t < nt; t++) {
        if (t + 1 < nt) fillKV((t + 1) & 1, t + 1);

        uint32_t sbK = sb + 2 * QT_B + (t & 1) * 4 * KT_B;
        int k0 = t * 64;

        float s[8][4];
#pragma unroll
        for (int j = 0; j < 8; j++)
#pragma unroll
            for (int r = 0; r < 4; r++) s[j][r] = 0.0f;

#pragma unroll
        for (int kc = 0; kc < 4; kc++) {
#pragma unroll
            for (int jj = 0; jj < 4; jj++) {
                uint32_t boff = (jj * 16 + b_n) * 144 + (kc * 16 + b_k) * 2;
                uint32_t kh[4], kl[4];
                LDSM_X4(kh[0], kh[1], kh[2], kh[3], sbK + boff);
                LDSM_X4(kl[0], kl[1], kl[2], kl[3], sbK + KT_B + boff);
                MMA_BF16(s[2 * jj],     qh_f[kc], kh[0], kh[1]);
                MMA_BF16(s[2 * jj + 1], qh_f[kc], kh[2], kh[3]);
                MMA_BF16(s[2 * jj],     qh_f[kc], kl[0], kl[1]);
                MMA_BF16(s[2 * jj + 1], qh_f[kc], kl[2], kl[3]);
                MMA_BF16(s[2 * jj],     ql_f[kc], kh[0], kh[1]);
                MMA_BF16(s[2 * jj + 1], ql_f[kc], kh[2], kh[3]);
            }
        }

        if (k0 + 63 > q0 + wid * 16) {
#pragma unroll
            for (int j = 0; j < 8; j++) {
                int kg = k0 + j * 8 + (lane & 3) * 2;
                if (kg > rbase)         s[j][0] = -1e30f;
                if (kg + 1 > rbase)     s[j][1] = -1e30f;
                if (kg > rbase + 8)     s[j][2] = -1e30f;
                if (kg + 1 > rbase + 8) s[j][3] = -1e30f;
            }
        }

        float rm0 = -1e30f, rm1 = -1e30f;
#pragma unroll
        for (int j = 0; j < 8; j++) {
            rm0 = fmaxf(rm0, fmaxf(s[j][0], s[j][1]));
            rm1 = fmaxf(rm1, fmaxf(s[j][2], s[j][3]));
        }
        rm0 = fmaxf(rm0, __shfl_xor_sync(0xffffffffu, rm0, 1));
        rm0 = fmaxf(rm0, __shfl_xor_sync(0xffffffffu, rm0, 2));
        rm1 = fmaxf(rm1, __shfl_xor_sync(0xffffffffu, rm1, 1));
        rm1 = fmaxf(rm1, __shfl_xor_sync(0xffffffffu, rm1, 2));
        float mn0 = fmaxf(m0, rm0), mn1 = fmaxf(m1, rm1);
        float cr0 = ex2a(m0 - mn0), cr1 = ex2a(m1 - mn1);
        float rs0 = 0.0f, rs1 = 0.0f;
#pragma unroll
        for (int j = 0; j < 8; j++) {
            s[j][0] = ex2a(s[j][0] - mn0);
            s[j][1] = ex2a(s[j][1] - mn0);
            s[j][2] = ex2a(s[j][2] - mn1);
            s[j][3] = ex2a(s[j][3] - mn1);
            rs0 += s[j][0] + s[j][1];
            rs1 += s[j][2] + s[j][3];
        }
        rs0 += __shfl_xor_sync(0xffffffffu, rs0, 1);
        rs0 += __shfl_xor_sync(0xffffffffu, rs0, 2);
        rs1 += __shfl_xor_sync(0xffffffffu, rs1, 1);
        rs1 += __shfl_xor_sync(0xffffffffu, rs1, 2);
        l0 = l0 * cr0 + rs0; l1 = l1 * cr1 + rs1;
        m0 = mn0; m1 = mn1;
#pragma unroll
        for (int j = 0; j < 8; j++) {
            zacc[j][0] *= cr0; zacc[j][1] *= cr0;
            zacc[j][2] *= cr1; zacc[j][3] *= cr1;
        }

        uint32_t ph[4][4], pl[4][4];
#pragma unroll
        for (int kc = 0; kc < 4; kc++) {
#pragma unroll
            for (int half = 0; half < 2; half++) {
                int j = 2 * kc + half;
                __nv_bfloat16 h0, lo0, h1, lo1, h2, lo2, h3, lo3;
                split_bf16(s[j][0], h0, lo0); split_bf16(s[j][1], h1, lo1);
                split_bf16(s[j][2], h2, lo2); split_bf16(s[j][3], h3, lo3);
                __nv_bfloat162 H01(h0, h1), H23(h2, h3), L01(lo0, lo1), L23(lo2, lo3);
                ph[kc][half * 2]     = *(uint32_t*)&H01;
                ph[kc][half * 2 + 1] = *(uint32_t*)&H23;
                pl[kc][half * 2]     = *(uint32_t*)&L01;
                pl[kc][half * 2 + 1] = *(uint32_t*)&L23;
            }
        }

#pragma unroll
        for (int kc = 0; kc < 4; kc++) {
#pragma unroll
            for (int jj = 0; jj < 4; jj++) {
                uint32_t voff = (kc * 16 + v_r) * 144 + (jj * 16 + v_c) * 2;
                uint32_t vh[4], vl[4];
                LDSM_X4_T(vh[0], vh[1], vh[2], vh[3], sbK + 2 * KT_B + voff);
                LDSM_X4_T(vl[0], vl[1], vl[2], vl[3], sbK + 3 * KT_B + voff);
                MMA_BF16(zacc[2 * jj],     ph[kc], vh[0], vh[1]);
                MMA_BF16(zacc[2 * jj + 1], ph[kc], vh[2], vh[3]);
                MMA_BF16(zacc[2 * jj],     ph[kc], vl[0], vl[1]);
                MMA_BF16(zacc[2 * jj + 1], ph[kc], vl[2], vl[3]);
                MMA_BF16(zacc[2 * jj],     pl[kc], vh[0], vh[1]);
                MMA_BF16(zacc[2 * jj + 1], pl[kc], vh[2], vh[3]);
            }
        }

        if (t + 1 < nt) {
            CP_WAIT0();
            __syncthreads();
        }
    }

    float inv0 = 1.0f / l0, inv1 = 1.0f / l1;
    size_t row0 = (size_t)b * SS + q0 + wid * 16 + (lane >> 2);
#pragma unroll
    for (int j = 0; j < 8; j++) {
        int col = h * DHD + j * 8 + (lane & 3) * 2;
        store_bf2(Zh, Zl, row0,     col, zacc[j][0] * inv0, zacc[j][1] * inv0);
        store_bf2(Zh, Zl, row0 + 8, col, zacc[j][2] * inv1, zacc[j][3] * inv1);
    }
}

// ---------------------------------------------------------------- launch
extern "C" void kernel_launch(void* const* d_in, const int* in_sizes, int n_in,
                              void* d_out, int out_size) {
    const float* Xq  = (const float*)d_in[0];
    const float* Xk  = (const float*)d_in[1];
    const float* Xv  = (const float*)d_in[2];
    const float* WQ  = (const float*)d_in[3];
    const float* WK  = (const float*)d_in[4];
    const float* WV  = (const float*)d_in[5];
    const float* WO  = (const float*)d_in[6];
    const float* bQ  = (const float*)d_in[7];
    const float* bK  = (const float*)d_in[8];
    const float* bV  = (const float*)d_in[9];
    const float* bO  = (const float*)d_in[10];
    float* out = (float*)d_out;

    static bool init = false;
    static __nv_bfloat16 *pWqh, *pWql, *pWkh, *pWkl, *pWvh, *pWvl, *pWoh, *pWol;
    static __nv_bfloat16 *pXqh, *pXql, *pXkh, *pXkl, *pXvh, *pXvl, *pzh, *pzl;
    static __nv_bfloat16 *pqh, *pql, *pkh, *pkl, *pvh, *pvl;
    static float *pbq, *pbk, *pbv;
    if (!init) {
        cudaGetSymbolAddress((void**)&pWqh, g_Wqh); cudaGetSymbolAddress((void**)&pWql, g_Wql);
        cudaGetSymbolAddress((void**)&pWkh, g_Wkh); cudaGetSymbolAddress((void**)&pWkl, g_Wkl);
        cudaGetSymbolAddress((void**)&pWvh, g_Wvh); cudaGetSymbolAddress((void**)&pWvl, g_Wvl);
        cudaGetSymbolAddress((void**)&pWoh, g_Woh); cudaGetSymbolAddress((void**)&pWol, g_Wol);
        cudaGetSymbolAddress((void**)&pXqh, g_Xqh); cudaGetSymbolAddress((void**)&pXql, g_Xql);
        cudaGetSymbolAddress((void**)&pXkh, g_Xkh); cudaGetSymbolAddress((void**)&pXkl, g_Xkl);
        cudaGetSymbolAddress((void**)&pXvh, g_Xvh); cudaGetSymbolAddress((void**)&pXvl, g_Xvl);
        cudaGetSymbolAddress((void**)&pzh,  g_zh);  cudaGetSymbolAddress((void**)&pzl,  g_zl);
        cudaGetSymbolAddress((void**)&pqh, g_qh);   cudaGetSymbolAddress((void**)&pql, g_ql);
        cudaGetSymbolAddress((void**)&pkh, g_kh);   cudaGetSymbolAddress((void**)&pkl, g_kl);
        cudaGetSymbolAddress((void**)&pvh, g_vh);   cudaGetSymbolAddress((void**)&pvl, g_vl);
        cudaGetSymbolAddress((void**)&pbq, g_bq); cudaGetSymbolAddress((void**)&pbk, g_bk);
        cudaGetSymbolAddress((void**)&pbv, g_bv);
        cudaFuncSetAttribute(tgemm_kernel, cudaFuncAttributeMaxDynamicSharedMemorySize, GEMM_SMEM);
        cudaFuncSetAttribute(qkv_gemm_kernel, cudaFuncAttributeMaxDynamicSharedMemorySize, GEMM_SMEM);
        cudaFuncSetAttribute(attn_tc_kernel, cudaFuncAttributeMaxDynamicSharedMemorySize, AT_SMEM);
        init = true;
    }

    // 1) amax + invf table (batched)
    reset_kernel<<<1, 32>>>();
    amax3_kernel<<<dim3(256, 3), 256>>>((const float4*)WQ, (const float4*)WK, (const float4*)WV, WN / 4, 0);
    amax3_kernel<<<dim3(1, 3), 256>>>((const float4*)bQ, (const float4*)bK, (const float4*)bV, NC / 4, 3);

    // 2) rotary table (fast path: cached invf + exact range reduction)
    sincos_kernel<<<SS * 32 / 256, 256>>>();

    // 3) weight qdq + transpose + split (batched), WO transpose, bias qdq (batched)
    quant_w_t3_kernel<<<dim3(DD / 32, 6, HH), dim3(32, 32)>>>(
        WQ, WK, WV, pWqh, pWql, pWkh, pWkl, pWvh, pWvl);
    wo_t_kernel<<<dim3(DD / 32, NC / 32), dim3(32, 32)>>>(WO, pWoh, pWol);
    quant_b3_kernel<<<dim3(4, 3), 256>>>(bQ, bK, bV, pbq, pbk, pbv);

    // 4) input split (batched)
    int n4 = (MR * DD) / 4;
    split3_kernel<<<dim3((n4 + 255) / 256, 3), 256>>>(
        (const float4*)Xq, (const float4*)Xk, (const float4*)Xv,
        (__nv_bfloat162*)pXqh, (__nv_bfloat162*)pXql,
        (__nv_bfloat162*)pXkh, (__nv_bfloat162*)pXkl,
        (__nv_bfloat162*)pXvh, (__nv_bfloat162*)pXvl, n4);

    // 5) fused QKV projection + bias + rotary + split (one launch)
    QKVParams P;
    P.Ah[0] = pXqh; P.Al[0] = pXql; P.Bh[0] = pWqh; P.Bl[0] = pWql; P.bias[0] = pbq; P.Oh[0] = pqh; P.Ol[0] = pql;
    P.Ah[1] = pXkh; P.Al[1] = pXkl; P.Bh[1] = pWkh; P.Bl[1] = pWkl; P.bias[1] = pbk; P.Oh[1] = pkh; P.Ol[1] = pkl;
    P.Ah[2] = pXvh; P.Al[2] = pXvl; P.Bh[2] = pWvh; P.Bl[2] = pWvl; P.bias[2] = pbv; P.Oh[2] = pvh; P.Ol[2] = pvl;
    qkv_gemm_kernel<<<dim3(NC / 128, MR / 128, 3), 256, GEMM_SMEM>>>(P);

    // 6) tensor-core flash attention (ex2.approx path) -> z hi/lo
    dim3 ag(SS / 128, HH, BB);
    attn_tc_kernel<<<ag, 256, AT_SMEM>>>(pqh, pql, pkh, pkl, pvh, pvl, pzh, pzl);

    // 7) output projection
    dim3 gg(DD / 128, MR / 128);
    tgemm_kernel<<<gg, 256, GEMM_SMEM>>>(pzh, pzl, pWoh, pWol, bO, out, MR, DD, NC);
}

// round 12
// speedup vs baseline: 2.0845x; 1.2483x over previous
#include <cuda_runtime.h>
#include <cuda_bf16.h>
#include <math.h>
#include <stdint.h>

// Problem constants
#define BB   2
#define SS   2048
#define DD   1024
#define HH   16
#define DHD  64
#define MR   (BB*SS)        // 4096
#define NC   (HH*DHD)       // 1024
#define WN   (HH*DD*DHD)    // 1048576
#define LOG2E 1.4426950408889634f

// ---------------------------------------------------------------- helpers
__device__ __forceinline__ uint32_t smem_u32(const void* p) {
    uint32_t a;
    asm("{ .reg .u64 t; cvta.to.shared.u64 t, %1; cvt.u32.u64 %0, t; }" : "=r"(a) : "l"(p));
    return a;
}

#define CP_ASYNC16(dst, src) asm volatile("cp.async.cg.shared.global [%0], [%1], 16;" :: "r"(dst), "l"(src))
#define CP_COMMIT()  asm volatile("cp.async.commit_group;" ::: "memory")
#define CP_WAIT2()   asm volatile("cp.async.wait_group 2;" ::: "memory")
#define CP_WAIT1()   asm volatile("cp.async.wait_group 1;" ::: "memory")
#define CP_WAIT0()   asm volatile("cp.async.wait_group 0;" ::: "memory")

#define LDSM_X4(r0, r1, r2, r3, addr) \
    asm volatile("ldmatrix.sync.aligned.m8n8.x4.shared.b16 {%0,%1,%2,%3}, [%4];" \
                 : "=r"(r0), "=r"(r1), "=r"(r2), "=r"(r3) : "r"(addr))

#define LDSM_X4_T(r0, r1, r2, r3, addr) \
    asm volatile("ldmatrix.sync.aligned.m8n8.x4.trans.shared.b16 {%0,%1,%2,%3}, [%4];" \
                 : "=r"(r0), "=r"(r1), "=r"(r2), "=r"(r3) : "r"(addr))

#define MMA_BF16(c, a, b0, b1) \
    asm volatile("mma.sync.aligned.m16n8k16.row.col.f32.bf16.bf16.f32 " \
                 "{%0,%1,%2,%3}, {%4,%5,%6,%7}, {%8,%9}, {%0,%1,%2,%3};" \
                 : "+f"((c)[0]), "+f"((c)[1]), "+f"((c)[2]), "+f"((c)[3]) \
                 : "r"((a)[0]), "r"((a)[1]), "r"((a)[2]), "r"((a)[3]), "r"(b0), "r"(b1))

// fast exp2 (args <= 0 in our use; -1e30 underflows to 0)
__device__ __forceinline__ float ex2a(float x) {
    float y;
    asm("ex2.approx.ftz.f32 %0, %1;" : "=f"(y) : "f"(x));
    return y;
}

// ---------------------------------------------------------------- scratch
__device__ unsigned g_amax[6];
__device__ double g_invf[32];
__device__ __nv_bfloat16 g_Wq[DD*NC];                 // scaled-quantized q values (exact bf16)
__device__ __nv_bfloat16 g_Wk[DD*NC];
__device__ __nv_bfloat16 g_Wv[DD*NC];
__device__ __nv_bfloat16 g_Woh[NC*DD], g_Wol[NC*DD];  // WO split (not quantized)
__device__ __nv_bfloat16 g_Xqh[(size_t)MR*DD], g_Xql[(size_t)MR*DD];
__device__ __nv_bfloat16 g_Xkh[(size_t)MR*DD], g_Xkl[(size_t)MR*DD];
__device__ __nv_bfloat16 g_Xvh[(size_t)MR*DD], g_Xvl[(size_t)MR*DD];
__device__ __nv_bfloat16 g_qh[(size_t)MR*NC], g_ql[(size_t)MR*NC];
__device__ __nv_bfloat16 g_kh[(size_t)MR*NC], g_kl[(size_t)MR*NC];
__device__ __nv_bfloat16 g_vh[(size_t)MR*NC], g_vl[(size_t)MR*NC];
__device__ __nv_bfloat16 g_zh[(size_t)MR*NC], g_zl[(size_t)MR*NC];
__device__ float g_bq[NC], g_bk[NC], g_bv[NC];
__device__ float g_sin[SS*32], g_cos[SS*32];

// ---------------------------------------------------------------- qdq
// full qdq (quantize + dequantize) - used for biases
__device__ __forceinline__ float qdq(float w, float amax) {
    float scale = 448.0f / fmaxf(amax, 1e-12f);
    float v = w * scale;
    float a = fabsf(v);
    int ex;
    frexpf(fmaxf(a, 1e-30f), &ex);
    float e = fminf(fmaxf((float)(ex - 1), -6.0f), 8.0f);
    float step = exp2f(e - 3.0f);
    float q = rintf(v / step) * step;
    q = fminf(fmaxf(q, -448.0f), 448.0f);
    return q / scale;
}

// quantize only (returns q, NOT divided by scale). q has <=4 significant bits
// -> exactly representable in bf16. Caller applies 1/scale = amax/448 later.
__device__ __forceinline__ float quant_q(float w, float amax) {
    float scale = 448.0f / fmaxf(amax, 1e-12f);
    float v = w * scale;
    float a = fabsf(v);
    int ex;
    frexpf(fmaxf(a, 1e-30f), &ex);
    float e = fminf(fmaxf((float)(ex - 1), -6.0f), 8.0f);
    float step = exp2f(e - 3.0f);
    float q = rintf(v / step) * step;
    return fminf(fmaxf(q, -448.0f), 448.0f);
}

__global__ void reset_kernel() {
    if (threadIdx.x < 6) g_amax[threadIdx.x] = 0u;
    if (threadIdx.x < 32)
        g_invf[threadIdx.x] = pow(10000.0, -(double)threadIdx.x / 32.0);
}

// batched amax over 3 arrays (slot = slot0 + blockIdx.y)
__global__ void amax3_kernel(const float4* __restrict__ a, const float4* __restrict__ b,
                             const float4* __restrict__ c, int n4, int slot0) {
    __shared__ float red[256];
    const float4* x = (blockIdx.y == 0) ? a : (blockIdx.y == 1) ? b : c;
    float m = 0.0f;
    for (int i = blockIdx.x * blockDim.x + threadIdx.x; i < n4; i += gridDim.x * blockDim.x) {
        float4 v = x[i];
        m = fmaxf(m, fmaxf(fmaxf(fabsf(v.x), fabsf(v.y)), fmaxf(fabsf(v.z), fabsf(v.w))));
    }
    red[threadIdx.x] = m;
    __syncthreads();
    for (int s = 128; s > 0; s >>= 1) {
        if (threadIdx.x < s) red[threadIdx.x] = fmaxf(red[threadIdx.x], red[threadIdx.x + s]);
        __syncthreads();
    }
    if (threadIdx.x == 0) atomicMax(&g_amax[slot0 + blockIdx.y], __float_as_uint(red[0]));
}

__device__ __forceinline__ void split_bf16(float x, __nv_bfloat16& h, __nv_bfloat16& l) {
    h = __float2bfloat16(x);
    l = __float2bfloat16(x - __bfloat162float(h));
}

// batched: quantize + transpose W[h,d,e] -> B[n=h*64+e][k=d] as exact-bf16 q values.
__global__ void quant_w_t3_kernel(const float* __restrict__ W0, const float* __restrict__ W1,
                                  const float* __restrict__ W2,
                                  __nv_bfloat16* __restrict__ B0,
                                  __nv_bfloat16* __restrict__ B1,
                                  __nv_bfloat16* __restrict__ B2) {
    __shared__ float t[32][33];
    int op = blockIdx.y >> 1;
    int ey = blockIdx.y & 1;
    const float* W = (op == 0) ? W0 : (op == 1) ? W1 : W2;
    __nv_bfloat16* B = (op == 0) ? B0 : (op == 1) ? B1 : B2;
    float amax = __uint_as_float(g_amax[op]);
    int h = blockIdx.z;
    int d = blockIdx.x * 32 + threadIdx.y;
    int e = ey * 32 + threadIdx.x;
    t[threadIdx.y][threadIdx.x] = quant_q(W[(size_t)h * DD * DHD + d * DHD + e], amax);
    __syncthreads();
    int n = h * DHD + ey * 32 + threadIdx.y;
    int k = blockIdx.x * 32 + threadIdx.x;
    B[(size_t)n * DD + k] = __float2bfloat16(t[threadIdx.x][threadIdx.y]);  // exact
}

// transpose WO[he][d] -> B[n=d][k=he], split (no qdq)
__global__ void wo_t_kernel(const float* __restrict__ W,
                            __nv_bfloat16* __restrict__ Bh, __nv_bfloat16* __restrict__ Bl) {
    __shared__ float t[32][33];
    int he = blockIdx.y * 32 + threadIdx.y;
    int d  = blockIdx.x * 32 + threadIdx.x;
    t[threadIdx.y][threadIdx.x] = W[(size_t)he * DD + d];
    __syncthreads();
    int n = blockIdx.x * 32 + threadIdx.y;
    int k = blockIdx.y * 32 + threadIdx.x;
    __nv_bfloat16 hi, lo;
    split_bf16(t[threadIdx.x][threadIdx.y], hi, lo);
    Bh[(size_t)n * NC + k] = hi;
    Bl[(size_t)n * NC + k] = lo;
}

// batched bias qdq (full qdq, fp32 output)
__global__ void quant_b3_kernel(const float* __restrict__ b0, const float* __restrict__ b1,
                                const float* __restrict__ b2,
                                float* __restrict__ o0, float* __restrict__ o1, float* __restrict__ o2) {
    int which = blockIdx.y;
    const float* b = (which == 0) ? b0 : (which == 1) ? b1 : b2;
    float* o = (which == 0) ? o0 : (which == 1) ? o1 : o2;
    int idx = blockIdx.x * 256 + threadIdx.x;
    if (idx >= NC) return;
    float amax = __uint_as_float(g_amax[3 + which]);
    o[idx] = qdq(b[idx], amax);
}

// batched fp32 -> bf16 hi/lo split
__global__ void split3_kernel(const float4* __restrict__ x0, const float4* __restrict__ x1,
                              const float4* __restrict__ x2,
                              __nv_bfloat162* __restrict__ h0, __nv_bfloat162* __restrict__ l0,
                              __nv_bfloat162* __restrict__ h1, __nv_bfloat162* __restrict__ l1,
                              __nv_bfloat162* __restrict__ h2, __nv_bfloat162* __restrict__ l2,
                              int n4) {
    int which = blockIdx.y;
    const float4* x = (which == 0) ? x0 : (which == 1) ? x1 : x2;
    __nv_bfloat162* hi = (which == 0) ? h0 : (which == 1) ? h1 : h2;
    __nv_bfloat162* lo = (which == 0) ? l0 : (which == 1) ? l1 : l2;
    int i = blockIdx.x * 256 + threadIdx.x;
    if (i >= n4) return;
    float4 v = x[i];
    __nv_bfloat16 a0, a1, a2, a3, b0, b1, b2, b3;
    split_bf16(v.x, a0, b0);
    split_bf16(v.y, a1, b1);
    split_bf16(v.z, a2, b2);
    split_bf16(v.w, a3, b3);
    hi[2*i]   = __nv_bfloat162(a0, a1);
    hi[2*i+1] = __nv_bfloat162(a2, a3);
    lo[2*i]   = __nv_bfloat162(b0, b1);
    lo[2*i+1] = __nv_bfloat162(b2, b3);
}

// ---------------------------------------------------------------- rotary table
__global__ void sincos_kernel() {
    int idx = blockIdx.x * 256 + threadIdx.x;
    if (idx >= SS * 32) return;
    int pos = idx >> 5, i = idx & 31;
    float invf = (float)g_invf[i];
    float ang  = (float)pos * invf;
    double a = (double)ang;
    double k = rint(a * 0.15915494309189535);         // 1/(2*pi)
    float r = (float)(a - k * 6.283185307179586);
    g_sin[idx] = sinf(r);
    g_cos[idx] = cosf(r);
}

// ---------------------------------------------------------------- GEMM common
#define KC 32
#define PK 40
#define TILE_B (128 * PK * 2)         // 10240
#define STAGE4_B (4 * TILE_B)         // 40960 (output gemm: Ah,Al,Bh,Bl)
#define TGEMM_SMEM (2 * STAGE4_B)     // 81920
#define STAGE3_B (3 * TILE_B)         // 30720 (qkv gemm: Ah,Al,B)
#define QKV_SMEM (3 * STAGE3_B)       // 92160, 3-stage pipeline

__device__ __forceinline__ void store_bf2(__nv_bfloat16* Oh, __nv_bfloat16* Ol,
                                          size_t row, int col, float a, float b) {
    __nv_bfloat16 ha, la, hb, lb;
    split_bf16(a, ha, la);
    split_bf16(b, hb, lb);
    __nv_bfloat162 H(ha, hb), L(la, lb);
    *(uint32_t*)&Oh[row * NC + col] = *(uint32_t*)&H;
    *(uint32_t*)&Ol[row * NC + col] = *(uint32_t*)&L;
}

// ---------------------------------------------------------------- fused QKV GEMM
// B operand = exact quantized q values; epilogue applies invscale = amax/448,
// then bias, rotary (Q/K), split to bf16 hi/lo. 2 MMA passes (Ah*B, Al*B).
struct QKVParams {
    const __nv_bfloat16 *Ah[3], *Al[3], *B[3];
    const float* bias[3];
    __nv_bfloat16 *Oh[3], *Ol[3];
};

__global__ void __launch_bounds__(256) qkv_gemm_kernel(QKVParams P) {
    extern __shared__ char sm[];
    uint32_t sb = smem_u32(sm);
    int tid = threadIdx.x;
    int lane = tid & 31, wid = tid >> 5;
    int wm = wid & 3, wn = wid >> 2;
    int bm = blockIdx.y, bn = blockIdx.x;
    int op = blockIdx.z;

    const char* srcs[3] = {
        (const char*)(P.Ah[op] + (size_t)bm * 128 * DD),
        (const char*)(P.Al[op] + (size_t)bm * 128 * DD),
        (const char*)(P.B[op]  + (size_t)bn * 128 * DD) };

    auto fill = [&](int s, int kc) {
        uint32_t base = sb + s * STAGE3_B;
        size_t koff = (size_t)kc * KC * 2;
#pragma unroll
        for (int t = tid; t < 1536; t += 256) {
            int arr = t >> 9;
            int idx = t & 511;
            int row = idx >> 2, c = idx & 3;
            CP_ASYNC16(base + arr * TILE_B + row * (PK * 2) + c * 16,
                       srcs[arr] + (size_t)row * DD * 2 + koff + c * 16);
        }
        CP_COMMIT();
    };

    float acc[2][8][4];
#pragma unroll
    for (int i = 0; i < 2; i++)
#pragma unroll
        for (int j = 0; j < 8; j++)
#pragma unroll
            for (int r = 0; r < 4; r++) acc[i][j][r] = 0.0f;

    int a_row = (lane & 7) + ((lane >> 3) & 1) * 8;
    int a_k   = (lane >> 4) * 8;
    int b_n   = ((lane >> 4) * 8) + (lane & 7);
    int b_k   = ((lane >> 3) & 1) * 8;

    const int nk = DD / KC;
    fill(0, 0);
    fill(1, 1);
    fill(2, 2);

    for (int c = 0; c < nk; c++) {
        if (c + 2 < nk) CP_WAIT2(); else if (c + 1 < nk) CP_WAIT1(); else CP_WAIT0();
        __syncthreads();

        uint32_t stb = sb + (c % 3) * STAGE3_B;
        uint32_t As_h = stb;
        uint32_t As_l = stb + TILE_B;
        uint32_t Bs   = stb + 2 * TILE_B;

#pragma unroll
        for (int kk = 0; kk < 2; kk++) {
            uint32_t ah[2][4], al[2][4];
#pragma unroll
            for (int i = 0; i < 2; i++) {
                uint32_t off = ((wm * 32 + i * 16 + a_row) * PK + kk * 16 + a_k) * 2;
                LDSM_X4(ah[i][0], ah[i][1], ah[i][2], ah[i][3], As_h + off);
                LDSM_X4(al[i][0], al[i][1], al[i][2], al[i][3], As_l + off);
            }
#pragma unroll
            for (int jj = 0; jj < 4; jj++) {
                uint32_t boff = ((wn * 64 + jj * 16 + b_n) * PK + kk * 16 + b_k) * 2;
                uint32_t bq[4];
                LDSM_X4(bq[0], bq[1], bq[2], bq[3], Bs + boff);
#pragma unroll
                for (int i = 0; i < 2; i++) {
                    MMA_BF16(acc[i][2 * jj],     ah[i], bq[0], bq[1]);
                    MMA_BF16(acc[i][2 * jj + 1], ah[i], bq[2], bq[3]);
                    MMA_BF16(acc[i][2 * jj],     al[i], bq[0], bq[1]);
                    MMA_BF16(acc[i][2 * jj + 1], al[i], bq[2], bq[3]);
                }
            }
        }
        __syncthreads();
        if (c + 3 < nk) fill((c + 3) % 3, c + 3);
    }

    const float* bias = P.bias[op];
    __nv_bfloat16* Oh = P.Oh[op];
    __nv_bfloat16* Ol = P.Ol[op];
    float invscale = fmaxf(__uint_as_float(g_amax[op]), 1e-12f) / 448.0f;

    if (op < 2) {
        float osc = (op == 0) ? 0.125f * LOG2E : 1.0f;
#pragma unroll
        for (int i = 0; i < 2; i++) {
            int r0 = bm * 128 + wm * 32 + i * 16 + (lane >> 2);
            int pos = r0 & (SS - 1);
#pragma unroll
            for (int j = 0; j < 4; j++) {
                int e = j * 8 + (lane & 3) * 2;
                int n0 = bn * 128 + wn * 64 + e;
                float bx0 = bias[n0],      bx1 = bias[n0 + 1];
                float bx2 = bias[n0 + 32], bx3 = bias[n0 + 33];
                float2 c0 = *(const float2*)&g_cos[pos * 32 + e];
                float2 s0 = *(const float2*)&g_sin[pos * 32 + e];
                float2 c8 = *(const float2*)&g_cos[(pos + 8) * 32 + e];
                float2 s8 = *(const float2*)&g_sin[(pos + 8) * 32 + e];
                float x0  = acc[i][j][0] * invscale + bx0,     x0b = acc[i][j][1] * invscale + bx1;
                float x1  = acc[i][j + 4][0] * invscale + bx2, x1b = acc[i][j + 4][1] * invscale + bx3;
                store_bf2(Oh, Ol, (size_t)r0, n0,
                          (x0 * c0.x - x1 * s0.x) * osc, (x0b * c0.y - x1b * s0.y) * osc);
                store_bf2(Oh, Ol, (size_t)r0, n0 + 32,
                          (x1 * c0.x + x0 * s0.x) * osc, (x1b * c0.y + x0b * s0.y) * osc);
                float u0  = acc[i][j][2] * invscale + bx0,     u0b = acc[i][j][3] * invscale + bx1;
                float u1  = acc[i][j + 4][2] * invscale + bx2, u1b = acc[i][j + 4][3] * invscale + bx3;
                store_bf2(Oh, Ol, (size_t)(r0 + 8), n0,
                          (u0 * c8.x - u1 * s8.x) * osc, (u0b * c8.y - u1b * s8.y) * osc);
                store_bf2(Oh, Ol, (size_t)(r0 + 8), n0 + 32,
                          (u1 * c8.x + u0 * s8.x) * osc, (u1b * c8.y + u0b * s8.y) * osc);
            }
        }
    } else {
#pragma unroll
        for (int i = 0; i < 2; i++) {
            int r0 = bm * 128 + wm * 32 + i * 16 + (lane >> 2);
#pragma unroll
            for (int j = 0; j < 8; j++) {
                int n0 = bn * 128 + wn * 64 + j * 8 + (lane & 3) * 2;
                float bx = bias[n0], by = bias[n0 + 1];
                store_bf2(Oh, Ol, (size_t)r0,       n0,
                          acc[i][j][0] * invscale + bx, acc[i][j][1] * invscale + by);
                store_bf2(Oh, Ol, (size_t)(r0 + 8), n0,
                          acc[i][j][2] * invscale + bx, acc[i][j][3] * invscale + by);
            }
        }
    }
}

// ---------------------------------------------------------------- output GEMM (fp32 out, 3-pass)
__global__ void __launch_bounds__(256) tgemm_kernel(
        const __nv_bfloat16* __restrict__ Ah, const __nv_bfloat16* __restrict__ Al,
        const __nv_bfloat16* __restrict__ Bh, const __nv_bfloat16* __restrict__ Bl,
        const float* __restrict__ bias, float* __restrict__ C,
        int M, int N, int K) {
    extern __shared__ char sm[];
    uint32_t sb = smem_u32(sm);
    int tid = threadIdx.x;
    int lane = tid & 31, wid = tid >> 5;
    int wm = wid & 3, wn = wid >> 2;
    int bm = blockIdx.y, bn = blockIdx.x;

    const char* srcs[4] = {
        (const char*)(Ah + (size_t)bm * 128 * K),
        (const char*)(Al + (size_t)bm * 128 * K),
        (const char*)(Bh + (size_t)bn * 128 * K),
        (const char*)(Bl + (size_t)bn * 128 * K) };

    auto fill = [&](int s, int kc) {
        uint32_t base = sb + s * STAGE4_B;
        size_t koff = (size_t)kc * KC * 2;
#pragma unroll
        for (int t = tid; t < 2048; t += 256) {
            int arr = t >> 9;
            int idx = t & 511;
            int row = idx >> 2, c = idx & 3;
            CP_ASYNC16(base + arr * TILE_B + row * (PK * 2) + c * 16,
                       srcs[arr] + (size_t)row * K * 2 + koff + c * 16);
        }
        CP_COMMIT();
    };

    float acc[2][8][4];
#pragma unroll
    for (int i = 0; i < 2; i++)
#pragma unroll
        for (int j = 0; j < 8; j++)
#pragma unroll
            for (int r = 0; r < 4; r++) acc[i][j][r] = 0.0f;

    int a_row = (lane & 7) + ((lane >> 3) & 1) * 8;
    int a_k   = (lane >> 4) * 8;
    int b_n   = ((lane >> 4) * 8) + (lane & 7);
    int b_k   = ((lane >> 3) & 1) * 8;

    int nk = K / KC;
    fill(0, 0);
    fill(1, 1);

    for (int c = 0; c < nk; c++) {
        int s = c & 1;
        if (c + 1 < nk) CP_WAIT1(); else CP_WAIT0();
        __syncthreads();

        uint32_t stb = sb + s * STAGE4_B;
        uint32_t As_h = stb;
        uint32_t As_l = stb + TILE_B;
        uint32_t Bs_h = stb + 2 * TILE_B;
        uint32_t Bs_l = stb + 3 * TILE_B;

#pragma unroll
        for (int kk = 0; kk < 2; kk++) {
            uint32_t ah[2][4], al[2][4];
#pragma unroll
            for (int i = 0; i < 2; i++) {
                uint32_t off = ((wm * 32 + i * 16 + a_row) * PK + kk * 16 + a_k) * 2;
                LDSM_X4(ah[i][0], ah[i][1], ah[i][2], ah[i][3], As_h + off);
                LDSM_X4(al[i][0], al[i][1], al[i][2], al[i][3], As_l + off);
            }
#pragma unroll
            for (int jj = 0; jj < 4; jj++) {
                uint32_t boff = ((wn * 64 + jj * 16 + b_n) * PK + kk * 16 + b_k) * 2;
                uint32_t bh[4], bl[4];
                LDSM_X4(bh[0], bh[1], bh[2], bh[3], Bs_h + boff);
                LDSM_X4(bl[0], bl[1], bl[2], bl[3], Bs_l + boff);
#pragma unroll
                for (int i = 0; i < 2; i++) {
                    MMA_BF16(acc[i][2 * jj],     ah[i], bh[0], bh[1]);
                    MMA_BF16(acc[i][2 * jj + 1], ah[i], bh[2], bh[3]);
                    MMA_BF16(acc[i][2 * jj],     ah[i], bl[0], bl[1]);
                    MMA_BF16(acc[i][2 * jj + 1], ah[i], bl[2], bl[3]);
                    MMA_BF16(acc[i][2 * jj],     al[i], bh[0], bh[1]);
                    MMA_BF16(acc[i][2 * jj + 1], al[i], bh[2], bh[3]);
                }
            }
        }
        __syncthreads();
        if (c + 2 < nk) fill(s, c + 2);
    }

#pragma unroll
    for (int i = 0; i < 2; i++) {
        int r0 = bm * 128 + wm * 32 + i * 16 + (lane >> 2);
#pragma unroll
        for (int j = 0; j < 8; j++) {
            int c0 = bn * 128 + wn * 64 + j * 8 + (lane & 3) * 2;
            float bx = bias[c0], by = bias[c0 + 1];
            float2 v0 = make_float2(acc[i][j][0] + bx, acc[i][j][1] + by);
            float2 v1 = make_float2(acc[i][j][2] + bx, acc[i][j][3] + by);
            *(float2*)&C[(size_t)r0 * N + c0] = v0;
            *(float2*)&C[(size_t)(r0 + 8) * N + c0] = v1;
        }
    }
}

// ---------------------------------------------------------------- tensor-core flash attention
#define APD 72
#define QT_B (128 * APD * 2)
#define KT_B (64 * APD * 2)
#define AT_SMEM (2 * QT_B + 2 * 4 * KT_B)

__global__ void __launch_bounds__(256) attn_tc_kernel(
        const __nv_bfloat16* __restrict__ Qh, const __nv_bfloat16* __restrict__ Ql,
        const __nv_bfloat16* __restrict__ Kh, const __nv_bfloat16* __restrict__ Kl,
        const __nv_bfloat16* __restrict__ Vh, const __nv_bfloat16* __restrict__ Vl,
        __nv_bfloat16* __restrict__ Zh, __nv_bfloat16* __restrict__ Zl) {
    extern __shared__ char sm[];
    uint32_t sb = smem_u32(sm);
    int tid = threadIdx.x, lane = tid & 31, wid = tid >> 5;

    int qt = (SS / 128 - 1) - blockIdx.x;   // heavy tiles first
    int h = blockIdx.y, b = blockIdx.z;
    int q0 = qt * 128;
    int nt = qt * 2 + 2;

    const char* gQ[2] = {
        (const char*)(Qh + ((size_t)b * SS + q0) * NC + h * DHD),
        (const char*)(Ql + ((size_t)b * SS + q0) * NC + h * DHD) };
    const char* gKV[4] = {
        (const char*)(Kh + (size_t)b * SS * NC + h * DHD),
        (const char*)(Kl + (size_t)b * SS * NC + h * DHD),
        (const char*)(Vh + (size_t)b * SS * NC + h * DHD),
        (const char*)(Vl + (size_t)b * SS * NC + h * DHD) };

    auto fillKV = [&](int s, int kt) {
        uint32_t base = sb + 2 * QT_B + s * 4 * KT_B;
        size_t roff = (size_t)(kt * 64) * (NC * 2);
#pragma unroll
        for (int t = tid; t < 2048; t += 256) {
            int arr = t >> 9, idx = t & 511;
            int row = idx >> 3, c = idx & 7;
            CP_ASYNC16(base + arr * KT_B + row * 144 + c * 16,
                       gKV[arr] + roff + (size_t)row * (NC * 2) + c * 16);
        }
        CP_COMMIT();
    };

#pragma unroll
    for (int t = tid; t < 2048; t += 256) {
        int arr = t >> 10, idx = t & 1023;
        int row = idx >> 3, c = idx & 7;
        CP_ASYNC16(sb + arr * QT_B + row * 144 + c * 16,
                   gQ[arr] + (size_t)row * (NC * 2) + c * 16);
    }
    fillKV(0, 0);

    float zacc[8][4];
#pragma unroll
    for (int j = 0; j < 8; j++)
#pragma unroll
        for (int r = 0; r < 4; r++) zacc[j][r] = 0.0f;
    float m0 = -1e30f, m1 = -1e30f, l0 = 0.0f, l1 = 0.0f;

    int a_row = (lane & 7) + ((lane >> 3) & 1) * 8;
    int a_k   = (lane >> 4) * 8;
    int b_n   = ((lane >> 4) * 8) + (lane & 7);
    int b_k   = ((lane >> 3) & 1) * 8;
    int v_r   = lane & 15;
    int v_c   = (lane >> 4) * 8;

    CP_WAIT0();
    __syncthreads();

    uint32_t qh_f[4][4], ql_f[4][4];
#pragma unroll
    for (int kc = 0; kc < 4; kc++) {
        uint32_t off = (wid * 16 + a_row) * 144 + (kc * 16 + a_k) * 2;
        LDSM_X4(qh_f[kc][0], qh_f[kc][1], qh_f[kc][2], qh_f[kc][3], sb + off);
        LDSM_X4(ql_f[kc][0], ql_f[kc][1], ql_f[kc][2], ql_f[kc][3], sb + QT_B + off);
    }

    int rbase = q0 + wid * 16 + (lane >> 2);

    for (int t = 0; t < nt; t++) {
        if (t + 1 < nt) fillKV((t + 1) & 1, t + 1);

        uint32_t sbK = sb + 2 * QT_B + (t & 1) * 4 * KT_B;
        int k0 = t * 64;

        float s[8][4];
#pragma unroll
        for (int j = 0; j < 8; j++)
#pragma unroll
            for (int r = 0; r < 4; r++) s[j][r] = 0.0f;

#pragma unroll
        for (int kc = 0; kc < 4; kc++) {
#pragma unroll
            for (int jj = 0; jj < 4; jj++) {
                uint32_t boff = (jj * 16 + b_n) * 144 + (kc * 16 + b_k) * 2;
                uint32_t kh[4], kl[4];
                LDSM_X4(kh[0], kh[1], kh[2], kh[3], sbK + boff);
                LDSM_X4(kl[0], kl[1], kl[2], kl[3], sbK + KT_B + boff);
                MMA_BF16(s[2 * jj],     qh_f[kc], kh[0], kh[1]);
                MMA_BF16(s[2 * jj + 1], qh_f[kc], kh[2], kh[3]);
                MMA_BF16(s[2 * jj],     qh_f[kc], kl[0], kl[1]);
                MMA_BF16(s[2 * jj + 1], qh_f[kc], kl[2], kl[3]);
                MMA_BF16(s[2 * jj],     ql_f[kc], kh[0], kh[1]);
                MMA_BF16(s[2 * jj + 1], ql_f[kc], kh[2], kh[3]);
            }
        }

        if (k0 + 63 > q0 + wid * 16) {
#pragma unroll
            for (int j = 0; j < 8; j++) {
                int kg = k0 + j * 8 + (lane & 3) * 2;
                if (kg > rbase)         s[j][0] = -1e30f;
                if (kg + 1 > rbase)     s[j][1] = -1e30f;
                if (kg > rbase + 8)     s[j][2] = -1e30f;
                if (kg + 1 > rbase + 8) s[j][3] = -1e30f;
            }
        }

        float rm0 = -1e30f, rm1 = -1e30f;
#pragma unroll
        for (int j = 0; j < 8; j++) {
            rm0 = fmaxf(rm0, fmaxf(s[j][0], s[j][1]));
            rm1 = fmaxf(rm1, fmaxf(s[j][2], s[j][3]));
        }
        rm0 = fmaxf(rm0, __shfl_xor_sync(0xffffffffu, rm0, 1));
        rm0 = fmaxf(rm0, __shfl_xor_sync(0xffffffffu, rm0, 2));
        rm1 = fmaxf(rm1, __shfl_xor_sync(0xffffffffu, rm1, 1));
        rm1 = fmaxf(rm1, __shfl_xor_sync(0xffffffffu, rm1, 2));
        float mn0 = fmaxf(m0, rm0), mn1 = fmaxf(m1, rm1);
        float cr0 = ex2a(m0 - mn0), cr1 = ex2a(m1 - mn1);
        float rs0 = 0.0f, rs1 = 0.0f;
#pragma unroll
        for (int j = 0; j < 8; j++) {
            s[j][0] = ex2a(s[j][0] - mn0);
            s[j][1] = ex2a(s[j][1] - mn0);
            s[j][2] = ex2a(s[j][2] - mn1);
            s[j][3] = ex2a(s[j][3] - mn1);
            rs0 += s[j][0] + s[j][1];
            rs1 += s[j][2] + s[j][3];
        }
        rs0 += __shfl_xor_sync(0xffffffffu, rs0, 1);
        rs0 += __shfl_xor_sync(0xffffffffu, rs0, 2);
        rs1 += __shfl_xor_sync(0xffffffffu, rs1, 1);
        rs1 += __shfl_xor_sync(0xffffffffu, rs1, 2);
        l0 = l0 * cr0 + rs0; l1 = l1 * cr1 + rs1;
        m0 = mn0; m1 = mn1;
#pragma unroll
        for (int j = 0; j < 8; j++) {
            zacc[j][0] *= cr0; zacc[j][1] *= cr0;
            zacc[j][2] *= cr1; zacc[j][3] *= cr1;
        }

        uint32_t ph[4][4], pl[4][4];
#pragma unroll
        for (int kc = 0; kc < 4; kc++) {
#pragma unroll
            for (int half = 0; half < 2; half++) {
                int j = 2 * kc + half;
                __nv_bfloat16 h0, lo0, h1, lo1, h2, lo2, h3, lo3;
                split_bf16(s[j][0], h0, lo0); split_bf16(s[j][1], h1, lo1);
                split_bf16(s[j][2], h2, lo2); split_bf16(s[j][3], h3, lo3);
                __nv_bfloat162 H01(h0, h1), H23(h2, h3), L01(lo0, lo1), L23(lo2, lo3);
                ph[kc][half * 2]     = *(uint32_t*)&H01;
                ph[kc][half * 2 + 1] = *(uint32_t*)&H23;
                pl[kc][half * 2]     = *(uint32_t*)&L01;
                pl[kc][half * 2 + 1] = *(uint32_t*)&L23;
            }
        }

#pragma unroll
        for (int kc = 0; kc < 4; kc++) {
#pragma unroll
            for (int jj = 0; jj < 4; jj++) {
                uint32_t voff = (kc * 16 + v_r) * 144 + (jj * 16 + v_c) * 2;
                uint32_t vh[4], vl[4];
                LDSM_X4_T(vh[0], vh[1], vh[2], vh[3], sbK + 2 * KT_B + voff);
                LDSM_X4_T(vl[0], vl[1], vl[2], vl[3], sbK + 3 * KT_B + voff);
                MMA_BF16(zacc[2 * jj],     ph[kc], vh[0], vh[1]);
                MMA_BF16(zacc[2 * jj + 1], ph[kc], vh[2], vh[3]);
                MMA_BF16(zacc[2 * jj],     ph[kc], vl[0], vl[1]);
                MMA_BF16(zacc[2 * jj + 1], ph[kc], vl[2], vl[3]);
                MMA_BF16(zacc[2 * jj],     pl[kc], vh[0], vh[1]);
                MMA_BF16(zacc[2 * jj + 1], pl[kc], vh[2], vh[3]);
            }
        }

        if (t + 1 < nt) {
            CP_WAIT0();
            __syncthreads();
        }
    }

    float inv0 = 1.0f / l0, inv1 = 1.0f / l1;
    size_t row0 = (size_t)b * SS + q0 + wid * 16 + (lane >> 2);
#pragma unroll
    for (int j = 0; j < 8; j++) {
        int col = h * DHD + j * 8 + (lane & 3) * 2;
        store_bf2(Zh, Zl, row0,     col, zacc[j][0] * inv0, zacc[j][1] * inv0);
        store_bf2(Zh, Zl, row0 + 8, col, zacc[j][2] * inv1, zacc[j][3] * inv1);
    }
}

// ---------------------------------------------------------------- launch
extern "C" void kernel_launch(void* const* d_in, const int* in_sizes, int n_in,
                              void* d_out, int out_size) {
    const float* Xq  = (const float*)d_in[0];
    const float* Xk  = (const float*)d_in[1];
    const float* Xv  = (const float*)d_in[2];
    const float* WQ  = (const float*)d_in[3];
    const float* WK  = (const float*)d_in[4];
    const float* WV  = (const float*)d_in[5];
    const float* WO  = (const float*)d_in[6];
    const float* bQ  = (const float*)d_in[7];
    const float* bK  = (const float*)d_in[8];
    const float* bV  = (const float*)d_in[9];
    const float* bO  = (const float*)d_in[10];
    float* out = (float*)d_out;

    static bool init = false;
    static __nv_bfloat16 *pWq, *pWk, *pWv, *pWoh, *pWol;
    static __nv_bfloat16 *pXqh, *pXql, *pXkh, *pXkl, *pXvh, *pXvl, *pzh, *pzl;
    static __nv_bfloat16 *pqh, *pql, *pkh, *pkl, *pvh, *pvl;
    static float *pbq, *pbk, *pbv;
    if (!init) {
        cudaGetSymbolAddress((void**)&pWq, g_Wq);
        cudaGetSymbolAddress((void**)&pWk, g_Wk);
        cudaGetSymbolAddress((void**)&pWv, g_Wv);
        cudaGetSymbolAddress((void**)&pWoh, g_Woh); cudaGetSymbolAddress((void**)&pWol, g_Wol);
        cudaGetSymbolAddress((void**)&pXqh, g_Xqh); cudaGetSymbolAddress((void**)&pXql, g_Xql);
        cudaGetSymbolAddress((void**)&pXkh, g_Xkh); cudaGetSymbolAddress((void**)&pXkl, g_Xkl);
        cudaGetSymbolAddress((void**)&pXvh, g_Xvh); cudaGetSymbolAddress((void**)&pXvl, g_Xvl);
        cudaGetSymbolAddress((void**)&pzh,  g_zh);  cudaGetSymbolAddress((void**)&pzl,  g_zl);
        cudaGetSymbolAddress((void**)&pqh, g_qh);   cudaGetSymbolAddress((void**)&pql, g_ql);
        cudaGetSymbolAddress((void**)&pkh, g_kh);   cudaGetSymbolAddress((void**)&pkl, g_kl);
        cudaGetSymbolAddress((void**)&pvh, g_vh);   cudaGetSymbolAddress((void**)&pvl, g_vl);
        cudaGetSymbolAddress((void**)&pbq, g_bq); cudaGetSymbolAddress((void**)&pbk, g_bk);
        cudaGetSymbolAddress((void**)&pbv, g_bv);
        cudaFuncSetAttribute(tgemm_kernel, cudaFuncAttributeMaxDynamicSharedMemorySize, TGEMM_SMEM);
        cudaFuncSetAttribute(qkv_gemm_kernel, cudaFuncAttributeMaxDynamicSharedMemorySize, QKV_SMEM);
        cudaFuncSetAttribute(attn_tc_kernel, cudaFuncAttributeMaxDynamicSharedMemorySize, AT_SMEM);
        init = true;
    }

    // 1) amax + invf table (batched)
    reset_kernel<<<1, 32>>>();
    amax3_kernel<<<dim3(256, 3), 256>>>((const float4*)WQ, (const float4*)WK, (const float4*)WV, WN / 4, 0);
    amax3_kernel<<<dim3(1, 3), 256>>>((const float4*)bQ, (const float4*)bK, (const float4*)bV, NC / 4, 3);

    // 2) rotary table
    sincos_kernel<<<SS * 32 / 256, 256>>>();

    // 3) weight quantize (exact bf16 q) + transpose; WO split; bias qdq
    quant_w_t3_kernel<<<dim3(DD / 32, 6, HH), dim3(32, 32)>>>(WQ, WK, WV, pWq, pWk, pWv);
    wo_t_kernel<<<dim3(DD / 32, NC / 32), dim3(32, 32)>>>(WO, pWoh, pWol);
    quant_b3_kernel<<<dim3(4, 3), 256>>>(bQ, bK, bV, pbq, pbk, pbv);

    // 4) input split (batched)
    int n4 = (MR * DD) / 4;
    split3_kernel<<<dim3((n4 + 255) / 256, 3), 256>>>(
        (const float4*)Xq, (const float4*)Xk, (const float4*)Xv,
        (__nv_bfloat162*)pXqh, (__nv_bfloat162*)pXql,
        (__nv_bfloat162*)pXkh, (__nv_bfloat162*)pXkl,
        (__nv_bfloat162*)pXvh, (__nv_bfloat162*)pXvl, n4);

    // 5) fused QKV projection (2-pass exact-weight GEMM) + invscale + bias + rotary + split
    QKVParams P;
    P.Ah[0] = pXqh; P.Al[0] = pXql; P.B[0] = pWq; P.bias[0] = pbq; P.Oh[0] = pqh; P.Ol[0] = pql;
    P.Ah[1] = pXkh; P.Al[1] = pXkl; P.B[1] = pWk; P.bias[1] = pbk; P.Oh[1] = pkh; P.Ol[1] = pkl;
    P.Ah[2] = pXvh; P.Al[2] = pXvl; P.B[2] = pWv; P.bias[2] = pbv; P.Oh[2] = pvh; P.Ol[2] = pvl;
    qkv_gemm_kernel<<<dim3(NC / 128, MR / 128, 3), 256, QKV_SMEM>>>(P);

    // 6) tensor-core flash attention -> z hi/lo
    dim3 ag(SS / 128, HH, BB);
    attn_tc_kernel<<<ag, 256, AT_SMEM>>>(pqh, pql, pkh, pkl, pvh, pvl, pzh, pzl);

    // 7) output projection (3-pass split, WO unquantized)
    dim3 gg(DD / 128, MR / 128);
    tgemm_kernel<<<gg, 256, TGEMM_SMEM>>>(pzh, pzl, pWoh, pWol, bO, out, MR, DD, NC);
}

// round 13
// speedup vs baseline: 2.4126x; 1.1574x over previous
#include <cuda_runtime.h>
#include <cuda_fp16.h>
#include <math.h>
#include <stdint.h>

// Problem constants
#define BB   2
#define SS   2048
#define DD   1024
#define HH   16
#define DHD  64
#define MR   (BB*SS)        // 4096
#define NC   (HH*DHD)       // 1024
#define WN   (HH*DD*DHD)    // 1048576
#define LOG2E 1.4426950408889634f

// ---------------------------------------------------------------- helpers
__device__ __forceinline__ uint32_t smem_u32(const void* p) {
    uint32_t a;
    asm("{ .reg .u64 t; cvta.to.shared.u64 t, %1; cvt.u32.u64 %0, t; }" : "=r"(a) : "l"(p));
    return a;
}

#define CP_ASYNC16(dst, src) asm volatile("cp.async.cg.shared.global [%0], [%1], 16;" :: "r"(dst), "l"(src))
#define CP_COMMIT()  asm volatile("cp.async.commit_group;" ::: "memory")
#define CP_WAIT2()   asm volatile("cp.async.wait_group 2;" ::: "memory")
#define CP_WAIT1()   asm volatile("cp.async.wait_group 1;" ::: "memory")
#define CP_WAIT0()   asm volatile("cp.async.wait_group 0;" ::: "memory")

#define LDSM_X4(r0, r1, r2, r3, addr) \
    asm volatile("ldmatrix.sync.aligned.m8n8.x4.shared.b16 {%0,%1,%2,%3}, [%4];" \
                 : "=r"(r0), "=r"(r1), "=r"(r2), "=r"(r3) : "r"(addr))

#define LDSM_X4_T(r0, r1, r2, r3, addr) \
    asm volatile("ldmatrix.sync.aligned.m8n8.x4.trans.shared.b16 {%0,%1,%2,%3}, [%4];" \
                 : "=r"(r0), "=r"(r1), "=r"(r2), "=r"(r3) : "r"(addr))

#define MMA_F16(c, a, b0, b1) \
    asm volatile("mma.sync.aligned.m16n8k16.row.col.f32.f16.f16.f32 " \
                 "{%0,%1,%2,%3}, {%4,%5,%6,%7}, {%8,%9}, {%0,%1,%2,%3};" \
                 : "+f"((c)[0]), "+f"((c)[1]), "+f"((c)[2]), "+f"((c)[3]) \
                 : "r"((a)[0]), "r"((a)[1]), "r"((a)[2]), "r"((a)[3]), "r"(b0), "r"(b1))

// fast exp2 (args <= 0 in our use; -1e30 underflows to 0)
__device__ __forceinline__ float ex2a(float x) {
    float y;
    asm("ex2.approx.ftz.f32 %0, %1;" : "=f"(y) : "f"(x));
    return y;
}

// fp32 -> fp16 hi/lo split
__device__ __forceinline__ void split_h(float x, __half& h, __half& l) {
    h = __float2half_rn(x);
    l = __float2half_rn(x - __half2float(h));
}

// ---------------------------------------------------------------- scratch
__device__ unsigned g_amax[6];
__device__ double g_invf[32];
__device__ __half g_Wq[DD*NC];                  // quantized q values (exact fp16)
__device__ __half g_Wk[DD*NC];
__device__ __half g_Wv[DD*NC];
__device__ __half g_Wo[NC*DD];                  // WO single fp16
__device__ __half g_Xqh[(size_t)MR*DD], g_Xql[(size_t)MR*DD];
__device__ __half g_Xkh[(size_t)MR*DD], g_Xkl[(size_t)MR*DD];
__device__ __half g_Xvh[(size_t)MR*DD], g_Xvl[(size_t)MR*DD];
__device__ __half g_qh[(size_t)MR*NC], g_ql[(size_t)MR*NC];
__device__ __half g_k[(size_t)MR*NC];           // k single
__device__ __half g_v[(size_t)MR*NC];           // v single
__device__ __half g_zh[(size_t)MR*NC], g_zl[(size_t)MR*NC];
__device__ float g_bq[NC], g_bk[NC], g_bv[NC];
__device__ float g_sin[SS*32], g_cos[SS*32];

// ---------------------------------------------------------------- qdq
__device__ __forceinline__ float qdq(float w, float amax) {
    float scale = 448.0f / fmaxf(amax, 1e-12f);
    float v = w * scale;
    float a = fabsf(v);
    int ex;
    frexpf(fmaxf(a, 1e-30f), &ex);
    float e = fminf(fmaxf((float)(ex - 1), -6.0f), 8.0f);
    float step = exp2f(e - 3.0f);
    float q = rintf(v / step) * step;
    q = fminf(fmaxf(q, -448.0f), 448.0f);
    return q / scale;
}

// quantize only (returns q; <=5 significant bits -> exact in fp16)
__device__ __forceinline__ float quant_q(float w, float amax) {
    float scale = 448.0f / fmaxf(amax, 1e-12f);
    float v = w * scale;
    float a = fabsf(v);
    int ex;
    frexpf(fmaxf(a, 1e-30f), &ex);
    float e = fminf(fmaxf((float)(ex - 1), -6.0f), 8.0f);
    float step = exp2f(e - 3.0f);
    float q = rintf(v / step) * step;
    return fminf(fmaxf(q, -448.0f), 448.0f);
}

__global__ void reset_kernel() {
    if (threadIdx.x < 6) g_amax[threadIdx.x] = 0u;
    if (threadIdx.x < 32)
        g_invf[threadIdx.x] = pow(10000.0, -(double)threadIdx.x / 32.0);
}

__global__ void amax3_kernel(const float4* __restrict__ a, const float4* __restrict__ b,
                             const float4* __restrict__ c, int n4, int slot0) {
    __shared__ float red[256];
    const float4* x = (blockIdx.y == 0) ? a : (blockIdx.y == 1) ? b : c;
    float m = 0.0f;
    for (int i = blockIdx.x * blockDim.x + threadIdx.x; i < n4; i += gridDim.x * blockDim.x) {
        float4 v = x[i];
        m = fmaxf(m, fmaxf(fmaxf(fabsf(v.x), fabsf(v.y)), fmaxf(fabsf(v.z), fabsf(v.w))));
    }
    red[threadIdx.x] = m;
    __syncthreads();
    for (int s = 128; s > 0; s >>= 1) {
        if (threadIdx.x < s) red[threadIdx.x] = fmaxf(red[threadIdx.x], red[threadIdx.x + s]);
        __syncthreads();
    }
    if (threadIdx.x == 0) atomicMax(&g_amax[slot0 + blockIdx.y], __float_as_uint(red[0]));
}

// batched: quantize + transpose W[h,d,e] -> B[n=h*64+e][k=d] (exact fp16 q)
__global__ void quant_w_t3_kernel(const float* __restrict__ W0, const float* __restrict__ W1,
                                  const float* __restrict__ W2,
                                  __half* __restrict__ B0, __half* __restrict__ B1,
                                  __half* __restrict__ B2) {
    __shared__ float t[32][33];
    int op = blockIdx.y >> 1;
    int ey = blockIdx.y & 1;
    const float* W = (op == 0) ? W0 : (op == 1) ? W1 : W2;
    __half* B = (op == 0) ? B0 : (op == 1) ? B1 : B2;
    float amax = __uint_as_float(g_amax[op]);
    int h = blockIdx.z;
    int d = blockIdx.x * 32 + threadIdx.y;
    int e = ey * 32 + threadIdx.x;
    t[threadIdx.y][threadIdx.x] = quant_q(W[(size_t)h * DD * DHD + d * DHD + e], amax);
    __syncthreads();
    int n = h * DHD + ey * 32 + threadIdx.y;
    int k = blockIdx.x * 32 + threadIdx.x;
    B[(size_t)n * DD + k] = __float2half_rn(t[threadIdx.x][threadIdx.y]);  // exact
}

// transpose WO[he][d] -> B[n=d][k=he], single fp16
__global__ void wo_t_kernel(const float* __restrict__ W, __half* __restrict__ B) {
    __shared__ float t[32][33];
    int he = blockIdx.y * 32 + threadIdx.y;
    int d  = blockIdx.x * 32 + threadIdx.x;
    t[threadIdx.y][threadIdx.x] = W[(size_t)he * DD + d];
    __syncthreads();
    int n = blockIdx.x * 32 + threadIdx.y;
    int k = blockIdx.y * 32 + threadIdx.x;
    B[(size_t)n * NC + k] = __float2half_rn(t[threadIdx.x][threadIdx.y]);
}

// batched bias qdq (fp32 out)
__global__ void quant_b3_kernel(const float* __restrict__ b0, const float* __restrict__ b1,
                                const float* __restrict__ b2,
                                float* __restrict__ o0, float* __restrict__ o1, float* __restrict__ o2) {
    int which = blockIdx.y;
    const float* b = (which == 0) ? b0 : (which == 1) ? b1 : b2;
    float* o = (which == 0) ? o0 : (which == 1) ? o1 : o2;
    int idx = blockIdx.x * 256 + threadIdx.x;
    if (idx >= NC) return;
    float amax = __uint_as_float(g_amax[3 + which]);
    o[idx] = qdq(b[idx], amax);
}

// batched fp32 -> fp16 hi/lo split
__global__ void split3_kernel(const float4* __restrict__ x0, const float4* __restrict__ x1,
                              const float4* __restrict__ x2,
                              __half2* __restrict__ h0, __half2* __restrict__ l0,
                              __half2* __restrict__ h1, __half2* __restrict__ l1,
                              __half2* __restrict__ h2, __half2* __restrict__ l2,
                              int n4) {
    int which = blockIdx.y;
    const float4* x = (which == 0) ? x0 : (which == 1) ? x1 : x2;
    __half2* hi = (which == 0) ? h0 : (which == 1) ? h1 : h2;
    __half2* lo = (which == 0) ? l0 : (which == 1) ? l1 : l2;
    int i = blockIdx.x * 256 + threadIdx.x;
    if (i >= n4) return;
    float4 v = x[i];
    __half a0, a1, a2, a3, b0, b1, b2, b3;
    split_h(v.x, a0, b0);
    split_h(v.y, a1, b1);
    split_h(v.z, a2, b2);
    split_h(v.w, a3, b3);
    hi[2*i]   = __halves2half2(a0, a1);
    hi[2*i+1] = __halves2half2(a2, a3);
    lo[2*i]   = __halves2half2(b0, b1);
    lo[2*i+1] = __halves2half2(b2, b3);
}

// ---------------------------------------------------------------- rotary table
__global__ void sincos_kernel() {
    int idx = blockIdx.x * 256 + threadIdx.x;
    if (idx >= SS * 32) return;
    int pos = idx >> 5, i = idx & 31;
    float invf = (float)g_invf[i];
    float ang  = (float)pos * invf;
    double a = (double)ang;
    double k = rint(a * 0.15915494309189535);
    float r = (float)(a - k * 6.283185307179586);
    g_sin[idx] = sinf(r);
    g_cos[idx] = cosf(r);
}

// ---------------------------------------------------------------- GEMM common
// 3-src stage (Ah, Al, B), 3-stage cp.async pipeline, 2 MMA passes.
#define KC 32
#define PK 40
#define TILE_B (128 * PK * 2)         // 10240
#define STAGE3_B (3 * TILE_B)         // 30720
#define GEMM3_SMEM (3 * STAGE3_B)     // 92160

__device__ __forceinline__ void store_h2(__half* O, size_t row, int col, float a, float b) {
    __half2 H = __halves2half2(__float2half_rn(a), __float2half_rn(b));
    *(uint32_t*)&O[row * NC + col] = *(uint32_t*)&H;
}

__device__ __forceinline__ void store_h2_split(__half* Oh, __half* Ol,
                                               size_t row, int col, float a, float b) {
    __half ha, la, hb, lb;
    split_h(a, ha, la);
    split_h(b, hb, lb);
    __half2 H = __halves2half2(ha, hb), L = __halves2half2(la, lb);
    *(uint32_t*)&Oh[row * NC + col] = *(uint32_t*)&H;
    *(uint32_t*)&Ol[row * NC + col] = *(uint32_t*)&L;
}

// ---------------------------------------------------------------- fused QKV GEMM
// B = exact quantized q values (fp16); epilogue: invscale, bias, rotary,
// Q -> split (qh,ql), K -> single, V -> single.
struct QKVParams {
    const __half *Ah[3], *Al[3], *B[3];
    const float* bias[3];
    __half *Oh[3], *Ol[3];    // Ol used only for op 0
};

__global__ void __launch_bounds__(256) qkv_gemm_kernel(QKVParams P) {
    extern __shared__ char sm[];
    uint32_t sb = smem_u32(sm);
    int tid = threadIdx.x;
    int lane = tid & 31, wid = tid >> 5;
    int wm = wid & 3, wn = wid >> 2;
    int bm = blockIdx.y, bn = blockIdx.x;
    int op = blockIdx.z;

    const char* srcs[3] = {
        (const char*)(P.Ah[op] + (size_t)bm * 128 * DD),
        (const char*)(P.Al[op] + (size_t)bm * 128 * DD),
        (const char*)(P.B[op]  + (size_t)bn * 128 * DD) };

    auto fill = [&](int s, int kc) {
        uint32_t base = sb + s * STAGE3_B;
        size_t koff = (size_t)kc * KC * 2;
#pragma unroll
        for (int t = tid; t < 1536; t += 256) {
            int arr = t >> 9;
            int idx = t & 511;
            int row = idx >> 2, c = idx & 3;
            CP_ASYNC16(base + arr * TILE_B + row * (PK * 2) + c * 16,
                       srcs[arr] + (size_t)row * DD * 2 + koff + c * 16);
        }
        CP_COMMIT();
    };

    float acc[2][8][4];
#pragma unroll
    for (int i = 0; i < 2; i++)
#pragma unroll
        for (int j = 0; j < 8; j++)
#pragma unroll
            for (int r = 0; r < 4; r++) acc[i][j][r] = 0.0f;

    int a_row = (lane & 7) + ((lane >> 3) & 1) * 8;
    int a_k   = (lane >> 4) * 8;
    int b_n   = ((lane >> 4) * 8) + (lane & 7);
    int b_k   = ((lane >> 3) & 1) * 8;

    const int nk = DD / KC;
    fill(0, 0);
    fill(1, 1);
    fill(2, 2);

    for (int c = 0; c < nk; c++) {
        if (c + 2 < nk) CP_WAIT2(); else if (c + 1 < nk) CP_WAIT1(); else CP_WAIT0();
        __syncthreads();

        uint32_t stb = sb + (c % 3) * STAGE3_B;
        uint32_t As_h = stb;
        uint32_t As_l = stb + TILE_B;
        uint32_t Bs   = stb + 2 * TILE_B;

#pragma unroll
        for (int kk = 0; kk < 2; kk++) {
            uint32_t ah[2][4], al[2][4];
#pragma unroll
            for (int i = 0; i < 2; i++) {
                uint32_t off = ((wm * 32 + i * 16 + a_row) * PK + kk * 16 + a_k) * 2;
                LDSM_X4(ah[i][0], ah[i][1], ah[i][2], ah[i][3], As_h + off);
                LDSM_X4(al[i][0], al[i][1], al[i][2], al[i][3], As_l + off);
            }
#pragma unroll
            for (int jj = 0; jj < 4; jj++) {
                uint32_t boff = ((wn * 64 + jj * 16 + b_n) * PK + kk * 16 + b_k) * 2;
                uint32_t bq[4];
                LDSM_X4(bq[0], bq[1], bq[2], bq[3], Bs + boff);
#pragma unroll
                for (int i = 0; i < 2; i++) {
                    MMA_F16(acc[i][2 * jj],     ah[i], bq[0], bq[1]);
                    MMA_F16(acc[i][2 * jj + 1], ah[i], bq[2], bq[3]);
                    MMA_F16(acc[i][2 * jj],     al[i], bq[0], bq[1]);
                    MMA_F16(acc[i][2 * jj + 1], al[i], bq[2], bq[3]);
                }
            }
        }
        __syncthreads();
        if (c + 3 < nk) fill((c + 3) % 3, c + 3);
    }

    const float* bias = P.bias[op];
    __half* Oh = P.Oh[op];
    __half* Ol = P.Ol[op];
    float invscale = fmaxf(__uint_as_float(g_amax[op]), 1e-12f) / 448.0f;

    if (op < 2) {
        float osc = (op == 0) ? 0.125f * LOG2E : 1.0f;
#pragma unroll
        for (int i = 0; i < 2; i++) {
            int r0 = bm * 128 + wm * 32 + i * 16 + (lane >> 2);
            int pos = r0 & (SS - 1);
#pragma unroll
            for (int j = 0; j < 4; j++) {
                int e = j * 8 + (lane & 3) * 2;
                int n0 = bn * 128 + wn * 64 + e;
                float bx0 = bias[n0],      bx1 = bias[n0 + 1];
                float bx2 = bias[n0 + 32], bx3 = bias[n0 + 33];
                float2 c0 = *(const float2*)&g_cos[pos * 32 + e];
                float2 s0 = *(const float2*)&g_sin[pos * 32 + e];
                float2 c8 = *(const float2*)&g_cos[(pos + 8) * 32 + e];
                float2 s8 = *(const float2*)&g_sin[(pos + 8) * 32 + e];
                float x0  = acc[i][j][0] * invscale + bx0,     x0b = acc[i][j][1] * invscale + bx1;
                float x1  = acc[i][j + 4][0] * invscale + bx2, x1b = acc[i][j + 4][1] * invscale + bx3;
                float ya0 = (x0 * c0.x - x1 * s0.x) * osc,  ya1 = (x0b * c0.y - x1b * s0.y) * osc;
                float yb0 = (x1 * c0.x + x0 * s0.x) * osc,  yb1 = (x1b * c0.y + x0b * s0.y) * osc;
                float u0  = acc[i][j][2] * invscale + bx0,     u0b = acc[i][j][3] * invscale + bx1;
                float u1  = acc[i][j + 4][2] * invscale + bx2, u1b = acc[i][j + 4][3] * invscale + bx3;
                float va0 = (u0 * c8.x - u1 * s8.x) * osc,  va1 = (u0b * c8.y - u1b * s8.y) * osc;
                float vb0 = (u1 * c8.x + u0 * s8.x) * osc,  vb1 = (u1b * c8.y + u0b * s8.y) * osc;
                if (op == 0) {
                    store_h2_split(Oh, Ol, (size_t)r0,       n0,      ya0, ya1);
                    store_h2_split(Oh, Ol, (size_t)r0,       n0 + 32, yb0, yb1);
                    store_h2_split(Oh, Ol, (size_t)(r0 + 8), n0,      va0, va1);
                    store_h2_split(Oh, Ol, (size_t)(r0 + 8), n0 + 32, vb0, vb1);
                } else {
                    store_h2(Oh, (size_t)r0,       n0,      ya0, ya1);
                    store_h2(Oh, (size_t)r0,       n0 + 32, yb0, yb1);
                    store_h2(Oh, (size_t)(r0 + 8), n0,      va0, va1);
                    store_h2(Oh, (size_t)(r0 + 8), n0 + 32, vb0, vb1);
                }
            }
        }
    } else {
#pragma unroll
        for (int i = 0; i < 2; i++) {
            int r0 = bm * 128 + wm * 32 + i * 16 + (lane >> 2);
#pragma unroll
            for (int j = 0; j < 8; j++) {
                int n0 = bn * 128 + wn * 64 + j * 8 + (lane & 3) * 2;
                float bx = bias[n0], by = bias[n0 + 1];
                store_h2(Oh, (size_t)r0,       n0, acc[i][j][0] * invscale + bx, acc[i][j][1] * invscale + by);
                store_h2(Oh, (size_t)(r0 + 8), n0, acc[i][j][2] * invscale + bx, acc[i][j][3] * invscale + by);
            }
        }
    }
}

// ---------------------------------------------------------------- output GEMM
// C = (zh + zl) * Wo^T + bias. 2 MMA passes, 3-stage pipeline, fp32 out.
__global__ void __launch_bounds__(256) tgemm_kernel(
        const __half* __restrict__ Ah, const __half* __restrict__ Al,
        const __half* __restrict__ B,
        const float* __restrict__ bias, float* __restrict__ C,
        int M, int N, int K) {
    extern __shared__ char sm[];
    uint32_t sb = smem_u32(sm);
    int tid = threadIdx.x;
    int lane = tid & 31, wid = tid >> 5;
    int wm = wid & 3, wn = wid >> 2;
    int bm = blockIdx.y, bn = blockIdx.x;

    const char* srcs[3] = {
        (const char*)(Ah + (size_t)bm * 128 * K),
        (const char*)(Al + (size_t)bm * 128 * K),
        (const char*)(B  + (size_t)bn * 128 * K) };

    auto fill = [&](int s, int kc) {
        uint32_t base = sb + s * STAGE3_B;
        size_t koff = (size_t)kc * KC * 2;
#pragma unroll
        for (int t = tid; t < 1536; t += 256) {
            int arr = t >> 9;
            int idx = t & 511;
            int row = idx >> 2, c = idx & 3;
            CP_ASYNC16(base + arr * TILE_B + row * (PK * 2) + c * 16,
                       srcs[arr] + (size_t)row * K * 2 + koff + c * 16);
        }
        CP_COMMIT();
    };

    float acc[2][8][4];
#pragma unroll
    for (int i = 0; i < 2; i++)
#pragma unroll
        for (int j = 0; j < 8; j++)
#pragma unroll
            for (int r = 0; r < 4; r++) acc[i][j][r] = 0.0f;

    int a_row = (lane & 7) + ((lane >> 3) & 1) * 8;
    int a_k   = (lane >> 4) * 8;
    int b_n   = ((lane >> 4) * 8) + (lane & 7);
    int b_k   = ((lane >> 3) & 1) * 8;

    int nk = K / KC;
    fill(0, 0);
    fill(1, 1);
    fill(2, 2);

    for (int c = 0; c < nk; c++) {
        if (c + 2 < nk) CP_WAIT2(); else if (c + 1 < nk) CP_WAIT1(); else CP_WAIT0();
        __syncthreads();

        uint32_t stb = sb + (c % 3) * STAGE3_B;
        uint32_t As_h = stb;
        uint32_t As_l = stb + TILE_B;
        uint32_t Bs   = stb + 2 * TILE_B;

#pragma unroll
        for (int kk = 0; kk < 2; kk++) {
            uint32_t ah[2][4], al[2][4];
#pragma unroll
            for (int i = 0; i < 2; i++) {
                uint32_t off = ((wm * 32 + i * 16 + a_row) * PK + kk * 16 + a_k) * 2;
                LDSM_X4(ah[i][0], ah[i][1], ah[i][2], ah[i][3], As_h + off);
                LDSM_X4(al[i][0], al[i][1], al[i][2], al[i][3], As_l + off);
            }
#pragma unroll
            for (int jj = 0; jj < 4; jj++) {
                uint32_t boff = ((wn * 64 + jj * 16 + b_n) * PK + kk * 16 + b_k) * 2;
                uint32_t bq[4];
                LDSM_X4(bq[0], bq[1], bq[2], bq[3], Bs + boff);
#pragma unroll
                for (int i = 0; i < 2; i++) {
                    MMA_F16(acc[i][2 * jj],     ah[i], bq[0], bq[1]);
                    MMA_F16(acc[i][2 * jj + 1], ah[i], bq[2], bq[3]);
                    MMA_F16(acc[i][2 * jj],     al[i], bq[0], bq[1]);
                    MMA_F16(acc[i][2 * jj + 1], al[i], bq[2], bq[3]);
                }
            }
        }
        __syncthreads();
        if (c + 3 < nk) fill((c + 3) % 3, c + 3);
    }

#pragma unroll
    for (int i = 0; i < 2; i++) {
        int r0 = bm * 128 + wm * 32 + i * 16 + (lane >> 2);
#pragma unroll
        for (int j = 0; j < 8; j++) {
            int c0 = bn * 128 + wn * 64 + j * 8 + (lane & 3) * 2;
            float bx = bias[c0], by = bias[c0 + 1];
            float2 v0 = make_float2(acc[i][j][0] + bx, acc[i][j][1] + by);
            float2 v1 = make_float2(acc[i][j][2] + bx, acc[i][j][3] + by);
            *(float2*)&C[(size_t)r0 * N + c0] = v0;
            *(float2*)&C[(size_t)(r0 + 8) * N + c0] = v1;
        }
    }
}

// ---------------------------------------------------------------- tensor-core flash attention
// q split fp16 (2-pass QK), k single; p split fp16 (2-pass PV), v single.
#define APD 72
#define QT_B (128 * APD * 2)          // 18432
#define KT_B (64 * APD * 2)           // 9216
#define KV_STAGE (2 * KT_B)           // 18432 (K + V)
#define AT_SMEM (2 * QT_B + 2 * KV_STAGE)   // 73728

__global__ void __launch_bounds__(256) attn_tc_kernel(
        const __half* __restrict__ Qh, const __half* __restrict__ Ql,
        const __half* __restrict__ K, const __half* __restrict__ V,
        __half* __restrict__ Zh, __half* __restrict__ Zl) {
    extern __shared__ char sm[];
    uint32_t sb = smem_u32(sm);
    int tid = threadIdx.x, lane = tid & 31, wid = tid >> 5;

    int qt = (SS / 128 - 1) - blockIdx.x;   // heavy tiles first
    int h = blockIdx.y, b = blockIdx.z;
    int q0 = qt * 128;
    int nt = qt * 2 + 2;

    const char* gQ[2] = {
        (const char*)(Qh + ((size_t)b * SS + q0) * NC + h * DHD),
        (const char*)(Ql + ((size_t)b * SS + q0) * NC + h * DHD) };
    const char* gKV[2] = {
        (const char*)(K + (size_t)b * SS * NC + h * DHD),
        (const char*)(V + (size_t)b * SS * NC + h * DHD) };

    auto fillKV = [&](int s, int kt) {
        uint32_t base = sb + 2 * QT_B + s * KV_STAGE;
        size_t roff = (size_t)(kt * 64) * (NC * 2);
#pragma unroll
        for (int t = tid; t < 1024; t += 256) {
            int arr = t >> 9, idx = t & 511;
            int row = idx >> 3, c = idx & 7;
            CP_ASYNC16(base + arr * KT_B + row * 144 + c * 16,
                       gKV[arr] + roff + (size_t)row * (NC * 2) + c * 16);
        }
        CP_COMMIT();
    };

#pragma unroll
    for (int t = tid; t < 2048; t += 256) {
        int arr = t >> 10, idx = t & 1023;
        int row = idx >> 3, c = idx & 7;
        CP_ASYNC16(sb + arr * QT_B + row * 144 + c * 16,
                   gQ[arr] + (size_t)row * (NC * 2) + c * 16);
    }
    fillKV(0, 0);

    float zacc[8][4];
#pragma unroll
    for (int j = 0; j < 8; j++)
#pragma unroll
        for (int r = 0; r < 4; r++) zacc[j][r] = 0.0f;
    float m0 = -1e30f, m1 = -1e30f, l0 = 0.0f, l1 = 0.0f;

    int a_row = (lane & 7) + ((lane >> 3) & 1) * 8;
    int a_k   = (lane >> 4) * 8;
    int b_n   = ((lane >> 4) * 8) + (lane & 7);
    int b_k   = ((lane >> 3) & 1) * 8;
    int v_r   = lane & 15;
    int v_c   = (lane >> 4) * 8;

    CP_WAIT0();
    __syncthreads();

    uint32_t qh_f[4][4], ql_f[4][4];
#pragma unroll
    for (int kc = 0; kc < 4; kc++) {
        uint32_t off = (wid * 16 + a_row) * 144 + (kc * 16 + a_k) * 2;
        LDSM_X4(qh_f[kc][0], qh_f[kc][1], qh_f[kc][2], qh_f[kc][3], sb + off);
        LDSM_X4(ql_f[kc][0], ql_f[kc][1], ql_f[kc][2], ql_f[kc][3], sb + QT_B + off);
    }

    int rbase = q0 + wid * 16 + (lane >> 2);

    for (int t = 0; t < nt; t++) {
        if (t + 1 < nt) fillKV((t + 1) & 1, t + 1);

        uint32_t sbK = sb + 2 * QT_B + (t & 1) * KV_STAGE;
        int k0 = t * 64;

        float s[8][4];
#pragma unroll
        for (int j = 0; j < 8; j++)
#pragma unroll
            for (int r = 0; r < 4; r++) s[j][r] = 0.0f;

#pragma unroll
        for (int kc = 0; kc < 4; kc++) {
#pragma unroll
            for (int jj = 0; jj < 4; jj++) {
                uint32_t boff = (jj * 16 + b_n) * 144 + (kc * 16 + b_k) * 2;
                uint32_t kf[4];
                LDSM_X4(kf[0], kf[1], kf[2], kf[3], sbK + boff);
                MMA_F16(s[2 * jj],     qh_f[kc], kf[0], kf[1]);
                MMA_F16(s[2 * jj + 1], qh_f[kc], kf[2], kf[3]);
                MMA_F16(s[2 * jj],     ql_f[kc], kf[0], kf[1]);
                MMA_F16(s[2 * jj + 1], ql_f[kc], kf[2], kf[3]);
            }
        }

        if (k0 + 63 > q0 + wid * 16) {
#pragma unroll
            for (int j = 0; j < 8; j++) {
                int kg = k0 + j * 8 + (lane & 3) * 2;
                if (kg > rbase)         s[j][0] = -1e30f;
                if (kg + 1 > rbase)     s[j][1] = -1e30f;
                if (kg > rbase + 8)     s[j][2] = -1e30f;
                if (kg + 1 > rbase + 8) s[j][3] = -1e30f;
            }
        }

        float rm0 = -1e30f, rm1 = -1e30f;
#pragma unroll
        for (int j = 0; j < 8; j++) {
            rm0 = fmaxf(rm0, fmaxf(s[j][0], s[j][1]));
            rm1 = fmaxf(rm1, fmaxf(s[j][2], s[j][3]));
        }
        rm0 = fmaxf(rm0, __shfl_xor_sync(0xffffffffu, rm0, 1));
        rm0 = fmaxf(rm0, __shfl_xor_sync(0xffffffffu, rm0, 2));
        rm1 = fmaxf(rm1, __shfl_xor_sync(0xffffffffu, rm1, 1));
        rm1 = fmaxf(rm1, __shfl_xor_sync(0xffffffffu, rm1, 2));
        float mn0 = fmaxf(m0, rm0), mn1 = fmaxf(m1, rm1);
        float cr0 = ex2a(m0 - mn0), cr1 = ex2a(m1 - mn1);
        float rs0 = 0.0f, rs1 = 0.0f;
#pragma unroll
        for (int j = 0; j < 8; j++) {
            s[j][0] = ex2a(s[j][0] - mn0);
            s[j][1] = ex2a(s[j][1] - mn0);
            s[j][2] = ex2a(s[j][2] - mn1);
            s[j][3] = ex2a(s[j][3] - mn1);
            rs0 += s[j][0] + s[j][1];
            rs1 += s[j][2] + s[j][3];
        }
        rs0 += __shfl_xor_sync(0xffffffffu, rs0, 1);
        rs0 += __shfl_xor_sync(0xffffffffu, rs0, 2);
        rs1 += __shfl_xor_sync(0xffffffffu, rs1, 1);
        rs1 += __shfl_xor_sync(0xffffffffu, rs1, 2);
        l0 = l0 * cr0 + rs0; l1 = l1 * cr1 + rs1;
        m0 = mn0; m1 = mn1;
#pragma unroll
        for (int j = 0; j < 8; j++) {
            zacc[j][0] *= cr0; zacc[j][1] *= cr0;
            zacc[j][2] *= cr1; zacc[j][3] *= cr1;
        }

        // P -> fp16 hi/lo A-fragments (register-resident)
        uint32_t ph[4][4], pl[4][4];
#pragma unroll
        for (int kc = 0; kc < 4; kc++) {
#pragma unroll
            for (int half = 0; half < 2; half++) {
                int j = 2 * kc + half;
                __half h0, lo0, h1, lo1, h2, lo2, h3, lo3;
                split_h(s[j][0], h0, lo0); split_h(s[j][1], h1, lo1);
                split_h(s[j][2], h2, lo2); split_h(s[j][3], h3, lo3);
                __half2 H01 = __halves2half2(h0, h1), H23 = __halves2half2(h2, h3);
                __half2 L01 = __halves2half2(lo0, lo1), L23 = __halves2half2(lo2, lo3);
                ph[kc][half * 2]     = *(uint32_t*)&H01;
                ph[kc][half * 2 + 1] = *(uint32_t*)&H23;
                pl[kc][half * 2]     = *(uint32_t*)&L01;
                pl[kc][half * 2 + 1] = *(uint32_t*)&L23;
            }
        }

#pragma unroll
        for (int kc = 0; kc < 4; kc++) {
#pragma unroll
            for (int jj = 0; jj < 4; jj++) {
                uint32_t voff = (kc * 16 + v_r) * 144 + (jj * 16 + v_c) * 2;
                uint32_t vf[4];
                LDSM_X4_T(vf[0], vf[1], vf[2], vf[3], sbK + KT_B + voff);
                MMA_F16(zacc[2 * jj],     ph[kc], vf[0], vf[1]);
                MMA_F16(zacc[2 * jj + 1], ph[kc], vf[2], vf[3]);
                MMA_F16(zacc[2 * jj],     pl[kc], vf[0], vf[1]);
                MMA_F16(zacc[2 * jj + 1], pl[kc], vf[2], vf[3]);
            }
        }

        if (t + 1 < nt) {
            CP_WAIT0();
            __syncthreads();
        }
    }

    float inv0 = 1.0f / l0, inv1 = 1.0f / l1;
    size_t row0 = (size_t)b * SS + q0 + wid * 16 + (lane >> 2);
#pragma unroll
    for (int j = 0; j < 8; j++) {
        int col = h * DHD + j * 8 + (lane & 3) * 2;
        store_h2_split(Zh, Zl, row0,     col, zacc[j][0] * inv0, zacc[j][1] * inv0);
        store_h2_split(Zh, Zl, row0 + 8, col, zacc[j][2] * inv1, zacc[j][3] * inv1);
    }
}

// ---------------------------------------------------------------- launch
extern "C" void kernel_launch(void* const* d_in, const int* in_sizes, int n_in,
                              void* d_out, int out_size) {
    const float* Xq  = (const float*)d_in[0];
    const float* Xk  = (const float*)d_in[1];
    const float* Xv  = (const float*)d_in[2];
    const float* WQ  = (const float*)d_in[3];
    const float* WK  = (const float*)d_in[4];
    const float* WV  = (const float*)d_in[5];
    const float* WO  = (const float*)d_in[6];
    const float* bQ  = (const float*)d_in[7];
    const float* bK  = (const float*)d_in[8];
    const float* bV  = (const float*)d_in[9];
    const float* bO  = (const float*)d_in[10];
    float* out = (float*)d_out;

    static bool init = false;
    static __half *pWq, *pWk, *pWv, *pWo;
    static __half *pXqh, *pXql, *pXkh, *pXkl, *pXvh, *pXvl, *pzh, *pzl;
    static __half *pqh, *pql, *pk, *pv;
    static float *pbq, *pbk, *pbv;
    if (!init) {
        cudaGetSymbolAddress((void**)&pWq, g_Wq);
        cudaGetSymbolAddress((void**)&pWk, g_Wk);
        cudaGetSymbolAddress((void**)&pWv, g_Wv);
        cudaGetSymbolAddress((void**)&pWo, g_Wo);
        cudaGetSymbolAddress((void**)&pXqh, g_Xqh); cudaGetSymbolAddress((void**)&pXql, g_Xql);
        cudaGetSymbolAddress((void**)&pXkh, g_Xkh); cudaGetSymbolAddress((void**)&pXkl, g_Xkl);
        cudaGetSymbolAddress((void**)&pXvh, g_Xvh); cudaGetSymbolAddress((void**)&pXvl, g_Xvl);
        cudaGetSymbolAddress((void**)&pzh,  g_zh);  cudaGetSymbolAddress((void**)&pzl,  g_zl);
        cudaGetSymbolAddress((void**)&pqh, g_qh);   cudaGetSymbolAddress((void**)&pql, g_ql);
        cudaGetSymbolAddress((void**)&pk, g_k);
        cudaGetSymbolAddress((void**)&pv, g_v);
        cudaGetSymbolAddress((void**)&pbq, g_bq); cudaGetSymbolAddress((void**)&pbk, g_bk);
        cudaGetSymbolAddress((void**)&pbv, g_bv);
        cudaFuncSetAttribute(tgemm_kernel, cudaFuncAttributeMaxDynamicSharedMemorySize, GEMM3_SMEM);
        cudaFuncSetAttribute(qkv_gemm_kernel, cudaFuncAttributeMaxDynamicSharedMemorySize, GEMM3_SMEM);
        cudaFuncSetAttribute(attn_tc_kernel, cudaFuncAttributeMaxDynamicSharedMemorySize, AT_SMEM);
        init = true;
    }

    // 1) amax + invf table
    reset_kernel<<<1, 32>>>();
    amax3_kernel<<<dim3(256, 3), 256>>>((const float4*)WQ, (const float4*)WK, (const float4*)WV, WN / 4, 0);
    amax3_kernel<<<dim3(1, 3), 256>>>((const float4*)bQ, (const float4*)bK, (const float4*)bV, NC / 4, 3);

    // 2) rotary table
    sincos_kernel<<<SS * 32 / 256, 256>>>();

    // 3) weight quantize (exact fp16) + transpose; WO single; bias qdq
    quant_w_t3_kernel<<<dim3(DD / 32, 6, HH), dim3(32, 32)>>>(WQ, WK, WV, pWq, pWk, pWv);
    wo_t_kernel<<<dim3(DD / 32, NC / 32), dim3(32, 32)>>>(WO, pWo);
    quant_b3_kernel<<<dim3(4, 3), 256>>>(bQ, bK, bV, pbq, pbk, pbv);

    // 4) input split (fp16 hi/lo)
    int n4 = (MR * DD) / 4;
    split3_kernel<<<dim3((n4 + 255) / 256, 3), 256>>>(
        (const float4*)Xq, (const float4*)Xk, (const float4*)Xv,
        (__half2*)pXqh, (__half2*)pXql,
        (__half2*)pXkh, (__half2*)pXkl,
        (__half2*)pXvh, (__half2*)pXvl, n4);

    // 5) fused QKV projection (2-pass) + invscale + bias + rotary; q split, k/v single
    QKVParams P;
    P.Ah[0] = pXqh; P.Al[0] = pXql; P.B[0] = pWq; P.bias[0] = pbq; P.Oh[0] = pqh; P.Ol[0] = pql;
    P.Ah[1] = pXkh; P.Al[1] = pXkl; P.B[1] = pWk; P.bias[1] = pbk; P.Oh[1] = pk;  P.Ol[1] = pk;
    P.Ah[2] = pXvh; P.Al[2] = pXvl; P.B[2] = pWv; P.bias[2] = pbv; P.Oh[2] = pv;  P.Ol[2] = pv;
    qkv_gemm_kernel<<<dim3(NC / 128, MR / 128, 3), 256, GEMM3_SMEM>>>(P);

    // 6) tensor-core flash attention (fp16, 2-pass QK + 2-pass PV) -> z hi/lo
    dim3 ag(SS / 128, HH, BB);
    attn_tc_kernel<<<ag, 256, AT_SMEM>>>(pqh, pql, pk, pv, pzh, pzl);

    // 7) output projection (2-pass, WO single fp16)
    dim3 gg(DD / 128, MR / 128);
    tgemm_kernel<<<gg, 256, GEMM3_SMEM>>>(pzh, pzl, pWo, bO, out, MR, DD, NC);
}

// round 15
// speedup vs baseline: 3.0544x; 1.2660x over previous
#include <cuda_runtime.h>
#include <cuda_fp16.h>
#include <math.h>
#include <stdint.h>

// Problem constants
#define BB   2
#define SS   2048
#define DD   1024
#define HH   16
#define DHD  64
#define MR   (BB*SS)        // 4096
#define NC   (HH*DHD)       // 1024
#define WN   (HH*DD*DHD)    // 1048576
#define LOG2E 1.4426950408889634f

// ---------------------------------------------------------------- helpers
__device__ __forceinline__ uint32_t smem_u32(const void* p) {
    uint32_t a;
    asm("{ .reg .u64 t; cvta.to.shared.u64 t, %1; cvt.u32.u64 %0, t; }" : "=r"(a) : "l"(p));
    return a;
}

#define CP_ASYNC16(dst, src) asm volatile("cp.async.cg.shared.global [%0], [%1], 16;" :: "r"(dst), "l"(src))
#define CP_COMMIT()  asm volatile("cp.async.commit_group;" ::: "memory")
#define CP_WAIT2()   asm volatile("cp.async.wait_group 2;" ::: "memory")
#define CP_WAIT1()   asm volatile("cp.async.wait_group 1;" ::: "memory")
#define CP_WAIT0()   asm volatile("cp.async.wait_group 0;" ::: "memory")

#define LDSM_X4(r0, r1, r2, r3, addr) \
    asm volatile("ldmatrix.sync.aligned.m8n8.x4.shared.b16 {%0,%1,%2,%3}, [%4];" \
                 : "=r"(r0), "=r"(r1), "=r"(r2), "=r"(r3) : "r"(addr))

#define LDSM_X4_T(r0, r1, r2, r3, addr) \
    asm volatile("ldmatrix.sync.aligned.m8n8.x4.trans.shared.b16 {%0,%1,%2,%3}, [%4];" \
                 : "=r"(r0), "=r"(r1), "=r"(r2), "=r"(r3) : "r"(addr))

#define MMA_F16(c, a, b0, b1) \
    asm volatile("mma.sync.aligned.m16n8k16.row.col.f32.f16.f16.f32 " \
                 "{%0,%1,%2,%3}, {%4,%5,%6,%7}, {%8,%9}, {%0,%1,%2,%3};" \
                 : "+f"((c)[0]), "+f"((c)[1]), "+f"((c)[2]), "+f"((c)[3]) \
                 : "r"((a)[0]), "r"((a)[1]), "r"((a)[2]), "r"((a)[3]), "r"(b0), "r"(b1))

// fast exp2 (args <= 0; -1e30 underflows to 0)
__device__ __forceinline__ float ex2a(float x) {
    float y;
    asm("ex2.approx.ftz.f32 %0, %1;" : "=f"(y) : "f"(x));
    return y;
}

// fp32 -> fp16 hi/lo split
__device__ __forceinline__ void split_h(float x, __half& h, __half& l) {
    h = __float2half_rn(x);
    l = __float2half_rn(x - __half2float(h));
}

// ---------------------------------------------------------------- scratch
__device__ unsigned g_amax[6];
__device__ double g_invf[32];
__device__ __half g_Wq[DD*NC];                  // quantized q values (exact fp16)
__device__ __half g_Wk[DD*NC];
__device__ __half g_Wv[DD*NC];
__device__ __half g_Wo[NC*DD];                  // WO single fp16
__device__ __half g_Xq[(size_t)MR*DD];          // X single fp16
__device__ __half g_Xk[(size_t)MR*DD];
__device__ __half g_Xv[(size_t)MR*DD];
__device__ __half g_qh[(size_t)MR*NC], g_ql[(size_t)MR*NC];   // q split (QK accuracy)
__device__ __half g_k[(size_t)MR*NC];
__device__ __half g_v[(size_t)MR*NC];
__device__ __half g_z[(size_t)MR*NC];           // z single
__device__ float g_bq[NC], g_bk[NC], g_bv[NC];
__device__ float g_sin[SS*32], g_cos[SS*32];

// ---------------------------------------------------------------- qdq
__device__ __forceinline__ float qdq(float w, float amax) {
    float scale = 448.0f / fmaxf(amax, 1e-12f);
    float v = w * scale;
    float a = fabsf(v);
    int ex;
    frexpf(fmaxf(a, 1e-30f), &ex);
    float e = fminf(fmaxf((float)(ex - 1), -6.0f), 8.0f);
    float step = exp2f(e - 3.0f);
    float q = rintf(v / step) * step;
    q = fminf(fmaxf(q, -448.0f), 448.0f);
    return q / scale;
}

// quantize only (returns q; <=5 significant bits -> exact in fp16)
__device__ __forceinline__ float quant_q(float w, float amax) {
    float scale = 448.0f / fmaxf(amax, 1e-12f);
    float v = w * scale;
    float a = fabsf(v);
    int ex;
    frexpf(fmaxf(a, 1e-30f), &ex);
    float e = fminf(fmaxf((float)(ex - 1), -6.0f), 8.0f);
    float step = exp2f(e - 3.0f);
    float q = rintf(v / step) * step;
    return fminf(fmaxf(q, -448.0f), 448.0f);
}

__global__ void reset_kernel() {
    if (threadIdx.x < 6) g_amax[threadIdx.x] = 0u;
    if (threadIdx.x < 32)
        g_invf[threadIdx.x] = pow(10000.0, -(double)threadIdx.x / 32.0);
}

__global__ void amax3_kernel(const float4* __restrict__ a, const float4* __restrict__ b,
                             const float4* __restrict__ c, int n4, int slot0) {
    __shared__ float red[256];
    const float4* x = (blockIdx.y == 0) ? a : (blockIdx.y == 1) ? b : c;
    float m = 0.0f;
    for (int i = blockIdx.x * blockDim.x + threadIdx.x; i < n4; i += gridDim.x * blockDim.x) {
        float4 v = x[i];
        m = fmaxf(m, fmaxf(fmaxf(fabsf(v.x), fabsf(v.y)), fmaxf(fabsf(v.z), fabsf(v.w))));
    }
    red[threadIdx.x] = m;
    __syncthreads();
    for (int s = 128; s > 0; s >>= 1) {
        if (threadIdx.x < s) red[threadIdx.x] = fmaxf(red[threadIdx.x], red[threadIdx.x + s]);
        __syncthreads();
    }
    if (threadIdx.x == 0) atomicMax(&g_amax[slot0 + blockIdx.y], __float_as_uint(red[0]));
}

// batched: quantize + transpose W[h,d,e] -> B[n=h*64+e][k=d] (exact fp16 q)
__global__ void quant_w_t3_kernel(const float* __restrict__ W0, const float* __restrict__ W1,
                                  const float* __restrict__ W2,
                                  __half* __restrict__ B0, __half* __restrict__ B1,
                                  __half* __restrict__ B2) {
    __shared__ float t[32][33];
    int op = blockIdx.y >> 1;
    int ey = blockIdx.y & 1;
    const float* W = (op == 0) ? W0 : (op == 1) ? W1 : W2;
    __half* B = (op == 0) ? B0 : (op == 1) ? B1 : B2;
    float amax = __uint_as_float(g_amax[op]);
    int h = blockIdx.z;
    int d = blockIdx.x * 32 + threadIdx.y;
    int e = ey * 32 + threadIdx.x;
    t[threadIdx.y][threadIdx.x] = quant_q(W[(size_t)h * DD * DHD + d * DHD + e], amax);
    __syncthreads();
    int n = h * DHD + ey * 32 + threadIdx.y;
    int k = blockIdx.x * 32 + threadIdx.x;
    B[(size_t)n * DD + k] = __float2half_rn(t[threadIdx.x][threadIdx.y]);  // exact
}

// transpose WO[he][d] -> B[n=d][k=he], single fp16
__global__ void wo_t_kernel(const float* __restrict__ W, __half* __restrict__ B) {
    __shared__ float t[32][33];
    int he = blockIdx.y * 32 + threadIdx.y;
    int d  = blockIdx.x * 32 + threadIdx.x;
    t[threadIdx.y][threadIdx.x] = W[(size_t)he * DD + d];
    __syncthreads();
    int n = blockIdx.x * 32 + threadIdx.y;
    int k = blockIdx.y * 32 + threadIdx.x;
    B[(size_t)n * NC + k] = __float2half_rn(t[threadIdx.x][threadIdx.y]);
}

// batched bias qdq (fp32 out)
__global__ void quant_b3_kernel(const float* __restrict__ b0, const float* __restrict__ b1,
                                const float* __restrict__ b2,
                                float* __restrict__ o0, float* __restrict__ o1, float* __restrict__ o2) {
    int which = blockIdx.y;
    const float* b = (which == 0) ? b0 : (which == 1) ? b1 : b2;
    float* o = (which == 0) ? o0 : (which == 1) ? o1 : o2;
    int idx = blockIdx.x * 256 + threadIdx.x;
    if (idx >= NC) return;
    float amax = __uint_as_float(g_amax[3 + which]);
    o[idx] = qdq(b[idx], amax);
}

// batched fp32 -> fp16 convert (single)
__global__ void convert3_kernel(const float4* __restrict__ x0, const float4* __restrict__ x1,
                                const float4* __restrict__ x2,
                                __half2* __restrict__ o0, __half2* __restrict__ o1,
                                __half2* __restrict__ o2, int n4) {
    int which = blockIdx.y;
    const float4* x = (which == 0) ? x0 : (which == 1) ? x1 : x2;
    __half2* o = (which == 0) ? o0 : (which == 1) ? o1 : o2;
    int i = blockIdx.x * 256 + threadIdx.x;
    if (i >= n4) return;
    float4 v = x[i];
    o[2*i]   = __halves2half2(__float2half_rn(v.x), __float2half_rn(v.y));
    o[2*i+1] = __halves2half2(__float2half_rn(v.z), __float2half_rn(v.w));
}

// ---------------------------------------------------------------- rotary table
__global__ void sincos_kernel() {
    int idx = blockIdx.x * 256 + threadIdx.x;
    if (idx >= SS * 32) return;
    int pos = idx >> 5, i = idx & 31;
    float invf = (float)g_invf[i];
    float ang  = (float)pos * invf;
    double a = (double)ang;
    double k = rint(a * 0.15915494309189535);
    float r = (float)(a - k * 6.283185307179586);
    g_sin[idx] = sinf(r);
    g_cos[idx] = cosf(r);
}

// ---------------------------------------------------------------- GEMM common
// 2-src stage (A, B), 3-stage cp.async pipeline, 1 MMA pass.
#define KC 32
#define PK 40
#define TILE_B (128 * PK * 2)         // 10240
#define STAGE2_B (2 * TILE_B)         // 20480
#define GEMM2_SMEM (3 * STAGE2_B)     // 61440

__device__ __forceinline__ void store_h2(__half* O, size_t row, int col, float a, float b) {
    __half2 H = __halves2half2(__float2half_rn(a), __float2half_rn(b));
    *(uint32_t*)&O[row * NC + col] = *(uint32_t*)&H;
}

__device__ __forceinline__ void store_h2_split(__half* Oh, __half* Ol,
                                               size_t row, int col, float a, float b) {
    __half ha, la, hb, lb;
    split_h(a, ha, la);
    split_h(b, hb, lb);
    __half2 H = __halves2half2(ha, hb), L = __halves2half2(la, lb);
    *(uint32_t*)&Oh[row * NC + col] = *(uint32_t*)&H;
    *(uint32_t*)&Ol[row * NC + col] = *(uint32_t*)&L;
}

// ---------------------------------------------------------------- fused QKV GEMM
// A = X single fp16, B = exact quantized q values (fp16); 1 MMA pass.
// Epilogue: invscale, bias, rotary; Q -> split (qh,ql), K/V -> single.
struct QKVParams {
    const __half *A[3], *B[3];
    const float* bias[3];
    __half *Oh[3], *Ol[3];    // Ol used only for op 0
};

__global__ void __launch_bounds__(256) qkv_gemm_kernel(QKVParams P) {
    extern __shared__ char sm[];
    uint32_t sb = smem_u32(sm);
    int tid = threadIdx.x;
    int lane = tid & 31, wid = tid >> 5;
    int wm = wid & 3, wn = wid >> 2;
    int bm = blockIdx.y, bn = blockIdx.x;
    int op = blockIdx.z;

    const char* srcs[2] = {
        (const char*)(P.A[op] + (size_t)bm * 128 * DD),
        (const char*)(P.B[op] + (size_t)bn * 128 * DD) };

    auto fill = [&](int s, int kc) {
        uint32_t base = sb + s * STAGE2_B;
        size_t koff = (size_t)kc * KC * 2;
#pragma unroll
        for (int t = tid; t < 1024; t += 256) {
            int arr = t >> 9;
            int idx = t & 511;
            int row = idx >> 2, c = idx & 3;
            CP_ASYNC16(base + arr * TILE_B + row * (PK * 2) + c * 16,
                       srcs[arr] + (size_t)row * DD * 2 + koff + c * 16);
        }
        CP_COMMIT();
    };

    float acc[2][8][4];
#pragma unroll
    for (int i = 0; i < 2; i++)
#pragma unroll
        for (int j = 0; j < 8; j++)
#pragma unroll
            for (int r = 0; r < 4; r++) acc[i][j][r] = 0.0f;

    int a_row = (lane & 7) + ((lane >> 3) & 1) * 8;
    int a_k   = (lane >> 4) * 8;
    int b_n   = ((lane >> 4) * 8) + (lane & 7);
    int b_k   = ((lane >> 3) & 1) * 8;

    const int nk = DD / KC;
    fill(0, 0);
    fill(1, 1);
    fill(2, 2);

    for (int c = 0; c < nk; c++) {
        if (c + 2 < nk) CP_WAIT2(); else if (c + 1 < nk) CP_WAIT1(); else CP_WAIT0();
        __syncthreads();

        uint32_t stb = sb + (c % 3) * STAGE2_B;
        uint32_t As = stb;
        uint32_t Bs = stb + TILE_B;

#pragma unroll
        for (int kk = 0; kk < 2; kk++) {
            uint32_t af[2][4];
#pragma unroll
            for (int i = 0; i < 2; i++) {
                uint32_t off = ((wm * 32 + i * 16 + a_row) * PK + kk * 16 + a_k) * 2;
                LDSM_X4(af[i][0], af[i][1], af[i][2], af[i][3], As + off);
            }
#pragma unroll
            for (int jj = 0; jj < 4; jj++) {
                uint32_t boff = ((wn * 64 + jj * 16 + b_n) * PK + kk * 16 + b_k) * 2;
                uint32_t bq[4];
                LDSM_X4(bq[0], bq[1], bq[2], bq[3], Bs + boff);
#pragma unroll
                for (int i = 0; i < 2; i++) {
                    MMA_F16(acc[i][2 * jj],     af[i], bq[0], bq[1]);
                    MMA_F16(acc[i][2 * jj + 1], af[i], bq[2], bq[3]);
                }
            }
        }
        __syncthreads();
        if (c + 3 < nk) fill((c + 3) % 3, c + 3);
    }

    const float* bias = P.bias[op];
    __half* Oh = P.Oh[op];
    __half* Ol = P.Ol[op];
    float invscale = fmaxf(__uint_as_float(g_amax[op]), 1e-12f) / 448.0f;

    if (op < 2) {
        float osc = (op == 0) ? 0.125f * LOG2E : 1.0f;
#pragma unroll
        for (int i = 0; i < 2; i++) {
            int r0 = bm * 128 + wm * 32 + i * 16 + (lane >> 2);
            int pos = r0 & (SS - 1);
#pragma unroll
            for (int j = 0; j < 4; j++) {
                int e = j * 8 + (lane & 3) * 2;
                int n0 = bn * 128 + wn * 64 + e;
                float bx0 = bias[n0],      bx1 = bias[n0 + 1];
                float bx2 = bias[n0 + 32], bx3 = bias[n0 + 33];
                float2 c0 = *(const float2*)&g_cos[pos * 32 + e];
                float2 s0 = *(const float2*)&g_sin[pos * 32 + e];
                float2 c8 = *(const float2*)&g_cos[(pos + 8) * 32 + e];
                float2 s8 = *(const float2*)&g_sin[(pos + 8) * 32 + e];
                float x0  = acc[i][j][0] * invscale + bx0,     x0b = acc[i][j][1] * invscale + bx1;
                float x1  = acc[i][j + 4][0] * invscale + bx2, x1b = acc[i][j + 4][1] * invscale + bx3;
                float ya0 = (x0 * c0.x - x1 * s0.x) * osc,  ya1 = (x0b * c0.y - x1b * s0.y) * osc;
                float yb0 = (x1 * c0.x + x0 * s0.x) * osc,  yb1 = (x1b * c0.y + x0b * s0.y) * osc;
                float u0  = acc[i][j][2] * invscale + bx0,     u0b = acc[i][j][3] * invscale + bx1;
                float u1  = acc[i][j + 4][2] * invscale + bx2, u1b = acc[i][j + 4][3] * invscale + bx3;
                float va0 = (u0 * c8.x - u1 * s8.x) * osc,  va1 = (u0b * c8.y - u1b * s8.y) * osc;
                float vb0 = (u1 * c8.x + u0 * s8.x) * osc,  vb1 = (u1b * c8.y + u0b * s8.y) * osc;
                if (op == 0) {
                    store_h2_split(Oh, Ol, (size_t)r0,       n0,      ya0, ya1);
                    store_h2_split(Oh, Ol, (size_t)r0,       n0 + 32, yb0, yb1);
                    store_h2_split(Oh, Ol, (size_t)(r0 + 8), n0,      va0, va1);
                    store_h2_split(Oh, Ol, (size_t)(r0 + 8), n0 + 32, vb0, vb1);
                } else {
                    store_h2(Oh, (size_t)r0,       n0,      ya0, ya1);
                    store_h2(Oh, (size_t)r0,       n0 + 32, yb0, yb1);
                    store_h2(Oh, (size_t)(r0 + 8), n0,      va0, va1);
                    store_h2(Oh, (size_t)(r0 + 8), n0 + 32, vb0, vb1);
                }
            }
        }
    } else {
#pragma unroll
        for (int i = 0; i < 2; i++) {
            int r0 = bm * 128 + wm * 32 + i * 16 + (lane >> 2);
#pragma unroll
            for (int j = 0; j < 8; j++) {
                int n0 = bn * 128 + wn * 64 + j * 8 + (lane & 3) * 2;
                float bx = bias[n0], by = bias[n0 + 1];
                store_h2(Oh, (size_t)r0,       n0, acc[i][j][0] * invscale + bx, acc[i][j][1] * invscale + by);
                store_h2(Oh, (size_t)(r0 + 8), n0, acc[i][j][2] * invscale + bx, acc[i][j][3] * invscale + by);
            }
        }
    }
}

// ---------------------------------------------------------------- output GEMM
// C = z * Wo^T + bias. 1 MMA pass (z single, Wo single), 3-stage, fp32 out.
__global__ void __launch_bounds__(256) tgemm_kernel(
        const __half* __restrict__ A, const __half* __restrict__ B,
        const float* __restrict__ bias, float* __restrict__ C,
        int M, int N, int K) {
    extern __shared__ char sm[];
    uint32_t sb = smem_u32(sm);
    int tid = threadIdx.x;
    int lane = tid & 31, wid = tid >> 5;
    int wm = wid & 3, wn = wid >> 2;
    int bm = blockIdx.y, bn = blockIdx.x;

    const char* srcs[2] = {
        (const char*)(A + (size_t)bm * 128 * K),
        (const char*)(B + (size_t)bn * 128 * K) };

    auto fill = [&](int s, int kc) {
        uint32_t base = sb + s * STAGE2_B;
        size_t koff = (size_t)kc * KC * 2;
#pragma unroll
        for (int t = tid; t < 1024; t += 256) {
            int arr = t >> 9;
            int idx = t & 511;
            int row = idx >> 2, c = idx & 3;
            CP_ASYNC16(base + arr * TILE_B + row * (PK * 2) + c * 16,
                       srcs[arr] + (size_t)row * K * 2 + koff + c * 16);
        }
        CP_COMMIT();
    };

    float acc[2][8][4];
#pragma unroll
    for (int i = 0; i < 2; i++)
#pragma unroll
        for (int j = 0; j < 8; j++)
#pragma unroll
            for (int r = 0; r < 4; r++) acc[i][j][r] = 0.0f;

    int a_row = (lane & 7) + ((lane >> 3) & 1) * 8;
    int a_k   = (lane >> 4) * 8;
    int b_n   = ((lane >> 4) * 8) + (lane & 7);
    int b_k   = ((lane >> 3) & 1) * 8;

    int nk = K / KC;
    fill(0, 0);
    fill(1, 1);
    fill(2, 2);

    for (int c = 0; c < nk; c++) {
        if (c + 2 < nk) CP_WAIT2(); else if (c + 1 < nk) CP_WAIT1(); else CP_WAIT0();
        __syncthreads();

        uint32_t stb = sb + (c % 3) * STAGE2_B;
        uint32_t As = stb;
        uint32_t Bs = stb + TILE_B;

#pragma unroll
        for (int kk = 0; kk < 2; kk++) {
            uint32_t af[2][4];
#pragma unroll
            for (int i = 0; i < 2; i++) {
                uint32_t off = ((wm * 32 + i * 16 + a_row) * PK + kk * 16 + a_k) * 2;
                LDSM_X4(af[i][0], af[i][1], af[i][2], af[i][3], As + off);
            }
#pragma unroll
            for (int jj = 0; jj < 4; jj++) {
                uint32_t boff = ((wn * 64 + jj * 16 + b_n) * PK + kk * 16 + b_k) * 2;
                uint32_t bq[4];
                LDSM_X4(bq[0], bq[1], bq[2], bq[3], Bs + boff);
#pragma unroll
                for (int i = 0; i < 2; i++) {
                    MMA_F16(acc[i][2 * jj],     af[i], bq[0], bq[1]);
                    MMA_F16(acc[i][2 * jj + 1], af[i], bq[2], bq[3]);
                }
            }
        }
        __syncthreads();
        if (c + 3 < nk) fill((c + 3) % 3, c + 3);
    }

#pragma unroll
    for (int i = 0; i < 2; i++) {
        int r0 = bm * 128 + wm * 32 + i * 16 + (lane >> 2);
#pragma unroll
        for (int j = 0; j < 8; j++) {
            int c0 = bn * 128 + wn * 64 + j * 8 + (lane & 3) * 2;
            float bx = bias[c0], by = bias[c0 + 1];
            float2 v0 = make_float2(acc[i][j][0] + bx, acc[i][j][1] + by);
            float2 v1 = make_float2(acc[i][j][2] + bx, acc[i][j][3] + by);
            *(float2*)&C[(size_t)r0 * N + c0] = v0;
            *(float2*)&C[(size_t)(r0 + 8) * N + c0] = v1;
        }
    }
}

// ---------------------------------------------------------------- tensor-core flash attention
// q split fp16 (2-pass QK), k single; p split fp16 (2-pass PV), v single; z single out.
#define APD 72
#define QT_B (128 * APD * 2)          // 18432
#define KT_B (64 * APD * 2)           // 9216
#define KV_STAGE (2 * KT_B)           // 18432 (K + V)
#define AT_SMEM (2 * QT_B + 2 * KV_STAGE)   // 73728

__global__ void __launch_bounds__(256) attn_tc_kernel(
        const __half* __restrict__ Qh, const __half* __restrict__ Ql,
        const __half* __restrict__ K, const __half* __restrict__ V,
        __half* __restrict__ Z) {
    extern __shared__ char sm[];
    uint32_t sb = smem_u32(sm);
    int tid = threadIdx.x, lane = tid & 31, wid = tid >> 5;

    int qt = (SS / 128 - 1) - blockIdx.x;   // heavy tiles first
    int h = blockIdx.y, b = blockIdx.z;
    int q0 = qt * 128;
    int nt = qt * 2 + 2;

    const char* gQ[2] = {
        (const char*)(Qh + ((size_t)b * SS + q0) * NC + h * DHD),
        (const char*)(Ql + ((size_t)b * SS + q0) * NC + h * DHD) };
    const char* gKV[2] = {
        (const char*)(K + (size_t)b * SS * NC + h * DHD),
        (const char*)(V + (size_t)b * SS * NC + h * DHD) };

    auto fillKV = [&](int s, int kt) {
        uint32_t base = sb + 2 * QT_B + s * KV_STAGE;
        size_t roff = (size_t)(kt * 64) * (NC * 2);
#pragma unroll
        for (int t = tid; t < 1024; t += 256) {
            int arr = t >> 9, idx = t & 511;
            int row = idx >> 3, c = idx & 7;
            CP_ASYNC16(base + arr * KT_B + row * 144 + c * 16,
                       gKV[arr] + roff + (size_t)row * (NC * 2) + c * 16);
        }
        CP_COMMIT();
    };

#pragma unroll
    for (int t = tid; t < 2048; t += 256) {
        int arr = t >> 10, idx = t & 1023;
        int row = idx >> 3, c = idx & 7;
        CP_ASYNC16(sb + arr * QT_B + row * 144 + c * 16,
                   gQ[arr] + (size_t)row * (NC * 2) + c * 16);
    }
    fillKV(0, 0);

    float zacc[8][4];
#pragma unroll
    for (int j = 0; j < 8; j++)
#pragma unroll
        for (int r = 0; r < 4; r++) zacc[j][r] = 0.0f;
    float m0 = -1e30f, m1 = -1e30f, l0 = 0.0f, l1 = 0.0f;

    int a_row = (lane & 7) + ((lane >> 3) & 1) * 8;
    int a_k   = (lane >> 4) * 8;
    int b_n   = ((lane >> 4) * 8) + (lane & 7);
    int b_k   = ((lane >> 3) & 1) * 8;
    int v_r   = lane & 15;
    int v_c   = (lane >> 4) * 8;

    CP_WAIT0();
    __syncthreads();

    uint32_t qh_f[4][4], ql_f[4][4];
#pragma unroll
    for (int kc = 0; kc < 4; kc++) {
        uint32_t off = (wid * 16 + a_row) * 144 + (kc * 16 + a_k) * 2;
        LDSM_X4(qh_f[kc][0], qh_f[kc][1], qh_f[kc][2], qh_f[kc][3], sb + off);
        LDSM_X4(ql_f[kc][0], ql_f[kc][1], ql_f[kc][2], ql_f[kc][3], sb + QT_B + off);
    }

    int rbase = q0 + wid * 16 + (lane >> 2);

    for (int t = 0; t < nt; t++) {
        if (t + 1 < nt) fillKV((t + 1) & 1, t + 1);

        uint32_t sbK = sb + 2 * QT_B + (t & 1) * KV_STAGE;
        int k0 = t * 64;

        float s[8][4];
#pragma unroll
        for (int j = 0; j < 8; j++)
#pragma unroll
            for (int r = 0; r < 4; r++) s[j][r] = 0.0f;

#pragma unroll
        for (int kc = 0; kc < 4; kc++) {
#pragma unroll
            for (int jj = 0; jj < 4; jj++) {
                uint32_t boff = (jj * 16 + b_n) * 144 + (kc * 16 + b_k) * 2;
                uint32_t kf[4];
                LDSM_X4(kf[0], kf[1], kf[2], kf[3], sbK + boff);
                MMA_F16(s[2 * jj],     qh_f[kc], kf[0], kf[1]);
                MMA_F16(s[2 * jj + 1], qh_f[kc], kf[2], kf[3]);
                MMA_F16(s[2 * jj],     ql_f[kc], kf[0], kf[1]);
                MMA_F16(s[2 * jj + 1], ql_f[kc], kf[2], kf[3]);
            }
        }

        if (k0 + 63 > q0 + wid * 16) {
#pragma unroll
            for (int j = 0; j < 8; j++) {
                int kg = k0 + j * 8 + (lane & 3) * 2;
                if (kg > rbase)         s[j][0] = -1e30f;
                if (kg + 1 > rbase)     s[j][1] = -1e30f;
                if (kg > rbase + 8)     s[j][2] = -1e30f;
                if (kg + 1 > rbase + 8) s[j][3] = -1e30f;
            }
        }

        float rm0 = -1e30f, rm1 = -1e30f;
#pragma unroll
        for (int j = 0; j < 8; j++) {
            rm0 = fmaxf(rm0, fmaxf(s[j][0], s[j][1]));
            rm1 = fmaxf(rm1, fmaxf(s[j][2], s[j][3]));
        }
        rm0 = fmaxf(rm0, __shfl_xor_sync(0xffffffffu, rm0, 1));
        rm0 = fmaxf(rm0, __shfl_xor_sync(0xffffffffu, rm0, 2));
        rm1 = fmaxf(rm1, __shfl_xor_sync(0xffffffffu, rm1, 1));
        rm1 = fmaxf(rm1, __shfl_xor_sync(0xffffffffu, rm1, 2));
        float mn0 = fmaxf(m0, rm0), mn1 = fmaxf(m1, rm1);
        float cr0 = ex2a(m0 - mn0), cr1 = ex2a(m1 - mn1);
        float rs0 = 0.0f, rs1 = 0.0f;
#pragma unroll
        for (int j = 0; j < 8; j++) {
            s[j][0] = ex2a(s[j][0] - mn0);
            s[j][1] = ex2a(s[j][1] - mn0);
            s[j][2] = ex2a(s[j][2] - mn1);
            s[j][3] = ex2a(s[j][3] - mn1);
            rs0 += s[j][0] + s[j][1];
            rs1 += s[j][2] + s[j][3];
        }
        rs0 += __shfl_xor_sync(0xffffffffu, rs0, 1);
        rs0 += __shfl_xor_sync(0xffffffffu, rs0, 2);
        rs1 += __shfl_xor_sync(0xffffffffu, rs1, 1);
        rs1 += __shfl_xor_sync(0xffffffffu, rs1, 2);
        l0 = l0 * cr0 + rs0; l1 = l1 * cr1 + rs1;
        m0 = mn0; m1 = mn1;
#pragma unroll
        for (int j = 0; j < 8; j++) {
            zacc[j][0] *= cr0; zacc[j][1] *= cr0;
            zacc[j][2] *= cr1; zacc[j][3] *= cr1;
        }

        // P -> fp16 hi/lo A-fragments
        uint32_t ph[4][4], pl[4][4];
#pragma unroll
        for (int kc = 0; kc < 4; kc++) {
#pragma unroll
            for (int half = 0; half < 2; half++) {
                int j = 2 * kc + half;
                __half h0, lo0, h1, lo1, h2, lo2, h3, lo3;
                split_h(s[j][0], h0, lo0); split_h(s[j][1], h1, lo1);
                split_h(s[j][2], h2, lo2); split_h(s[j][3], h3, lo3);
                __half2 H01 = __halves2half2(h0, h1), H23 = __halves2half2(h2, h3);
                __half2 L01 = __halves2half2(lo0, lo1), L23 = __halves2half2(lo2, lo3);
                ph[kc][half * 2]     = *(uint32_t*)&H01;
                ph[kc][half * 2 + 1] = *(uint32_t*)&H23;
                pl[kc][half * 2]     = *(uint32_t*)&L01;
                pl[kc][half * 2 + 1] = *(uint32_t*)&L23;
            }
        }

#pragma unroll
        for (int kc = 0; kc < 4; kc++) {
#pragma unroll
            for (int jj = 0; jj < 4; jj++) {
                uint32_t voff = (kc * 16 + v_r) * 144 + (jj * 16 + v_c) * 2;
                uint32_t vf[4];
                LDSM_X4_T(vf[0], vf[1], vf[2], vf[3], sbK + KT_B + voff);
                MMA_F16(zacc[2 * jj],     ph[kc], vf[0], vf[1]);
                MMA_F16(zacc[2 * jj + 1], ph[kc], vf[2], vf[3]);
                MMA_F16(zacc[2 * jj],     pl[kc], vf[0], vf[1]);
                MMA_F16(zacc[2 * jj + 1], pl[kc], vf[2], vf[3]);
            }
        }

        if (t + 1 < nt) {
            CP_WAIT0();
            __syncthreads();
        }
    }

    float inv0 = 1.0f / l0, inv1 = 1.0f / l1;
    size_t row0 = (size_t)b * SS + q0 + wid * 16 + (lane >> 2);
#pragma unroll
    for (int j = 0; j < 8; j++) {
        int col = h * DHD + j * 8 + (lane & 3) * 2;
        store_h2(Z, row0,     col, zacc[j][0] * inv0, zacc[j][1] * inv0);
        store_h2(Z, row0 + 8, col, zacc[j][2] * inv1, zacc[j][3] * inv1);
    }
}

// ---------------------------------------------------------------- launch
extern "C" void kernel_launch(void* const* d_in, const int* in_sizes, int n_in,
                              void* d_out, int out_size) {
    const float* Xq  = (const float*)d_in[0];
    const float* Xk  = (const float*)d_in[1];
    const float* Xv  = (const float*)d_in[2];
    const float* WQ  = (const float*)d_in[3];
    const float* WK  = (const float*)d_in[4];
    const float* WV  = (const float*)d_in[5];
    const float* WO  = (const float*)d_in[6];
    const float* bQ  = (const float*)d_in[7];
    const float* bK  = (const float*)d_in[8];
    const float* bV  = (const float*)d_in[9];
    const float* bO  = (const float*)d_in[10];
    float* out = (float*)d_out;

    static bool init = false;
    static __half *pWq, *pWk, *pWv, *pWo;
    static __half *pXq, *pXk, *pXv, *pz;
    static __half *pqh, *pql, *pk, *pv;
    static float *pbq, *pbk, *pbv;
    if (!init) {
        cudaGetSymbolAddress((void**)&pWq, g_Wq);
        cudaGetSymbolAddress((void**)&pWk, g_Wk);
        cudaGetSymbolAddress((void**)&pWv, g_Wv);
        cudaGetSymbolAddress((void**)&pWo, g_Wo);
        cudaGetSymbolAddress((void**)&pXq, g_Xq);
        cudaGetSymbolAddress((void**)&pXk, g_Xk);
        cudaGetSymbolAddress((void**)&pXv, g_Xv);
        cudaGetSymbolAddress((void**)&pz,  g_z);
        cudaGetSymbolAddress((void**)&pqh, g_qh);   cudaGetSymbolAddress((void**)&pql, g_ql);
        cudaGetSymbolAddress((void**)&pk, g_k);
        cudaGetSymbolAddress((void**)&pv, g_v);
        cudaGetSymbolAddress((void**)&pbq, g_bq); cudaGetSymbolAddress((void**)&pbk, g_bk);
        cudaGetSymbolAddress((void**)&pbv, g_bv);
        cudaFuncSetAttribute(tgemm_kernel, cudaFuncAttributeMaxDynamicSharedMemorySize, GEMM2_SMEM);
        cudaFuncSetAttribute(qkv_gemm_kernel, cudaFuncAttributeMaxDynamicSharedMemorySize, GEMM2_SMEM);
        cudaFuncSetAttribute(attn_tc_kernel, cudaFuncAttributeMaxDynamicSharedMemorySize, AT_SMEM);
        init = true;
    }

    // 1) amax + invf table
    reset_kernel<<<1, 32>>>();
    amax3_kernel<<<dim3(256, 3), 256>>>((const float4*)WQ, (const float4*)WK, (const float4*)WV, WN / 4, 0);
    amax3_kernel<<<dim3(1, 3), 256>>>((const float4*)bQ, (const float4*)bK, (const float4*)bV, NC / 4, 3);

    // 2) rotary table
    sincos_kernel<<<SS * 32 / 256, 256>>>();

    // 3) weight quantize (exact fp16) + transpose; WO single; bias qdq
    quant_w_t3_kernel<<<dim3(DD / 32, 6, HH), dim3(32, 32)>>>(WQ, WK, WV, pWq, pWk, pWv);
    wo_t_kernel<<<dim3(DD / 32, NC / 32), dim3(32, 32)>>>(WO, pWo);
    quant_b3_kernel<<<dim3(4, 3), 256>>>(bQ, bK, bV, pbq, pbk, pbv);

    // 4) input convert fp32 -> fp16 single
    int n4 = (MR * DD) / 4;
    convert3_kernel<<<dim3((n4 + 255) / 256, 3), 256>>>(
        (const float4*)Xq, (const float4*)Xk, (const float4*)Xv,
        (__half2*)pXq, (__half2*)pXk, (__half2*)pXv, n4);

    // 5) fused QKV projection (1-pass) + invscale + bias + rotary; q split, k/v single
    QKVParams P;
    P.A[0] = pXq; P.B[0] = pWq; P.bias[0] = pbq; P.Oh[0] = pqh; P.Ol[0] = pql;
    P.A[1] = pXk; P.B[1] = pWk; P.bias[1] = pbk; P.Oh[1] = pk;  P.Ol[1] = pk;
    P.A[2] = pXv; P.B[2] = pWv; P.bias[2] = pbv; P.Oh[2] = pv;  P.Ol[2] = pv;
    qkv_gemm_kernel<<<dim3(NC / 128, MR / 128, 3), 256, GEMM2_SMEM>>>(P);

    // 6) tensor-core flash attention -> z single
    dim3 ag(SS / 128, HH, BB);
    attn_tc_kernel<<<ag, 256, AT_SMEM>>>(pqh, pql, pk, pv, pz);

    // 7) output projection (1-pass, z and WO single fp16)
    dim3 gg(DD / 128, MR / 128);
    tgemm_kernel<<<gg, 256, GEMM2_SMEM>>>(pz, pWo, bO, out, MR, DD, NC);
}

// round 17
// speedup vs baseline: 3.7036x; 1.2125x over previous
#include <cuda_runtime.h>
#include <cuda_fp16.h>
#include <math.h>
#include <stdint.h>

// Problem constants
#define BB   2
#define SS   2048
#define DD   1024
#define HH   16
#define DHD  64
#define MR   (BB*SS)        // 4096
#define NC   (HH*DHD)       // 1024
#define WN   (HH*DD*DHD)    // 1048576
#define LOG2E 1.4426950408889634f

// ---------------------------------------------------------------- helpers
__device__ __forceinline__ uint32_t smem_u32(const void* p) {
    uint32_t a;
    asm("{ .reg .u64 t; cvta.to.shared.u64 t, %1; cvt.u32.u64 %0, t; }" : "=r"(a) : "l"(p));
    return a;
}

#define CP_ASYNC16(dst, src) asm volatile("cp.async.cg.shared.global [%0], [%1], 16;" :: "r"(dst), "l"(src))
#define CP_COMMIT()  asm volatile("cp.async.commit_group;" ::: "memory")
#define CP_WAIT2()   asm volatile("cp.async.wait_group 2;" ::: "memory")
#define CP_WAIT1()   asm volatile("cp.async.wait_group 1;" ::: "memory")
#define CP_WAIT0()   asm volatile("cp.async.wait_group 0;" ::: "memory")

#define LDSM_X4(r0, r1, r2, r3, addr) \
    asm volatile("ldmatrix.sync.aligned.m8n8.x4.shared.b16 {%0,%1,%2,%3}, [%4];" \
                 : "=r"(r0), "=r"(r1), "=r"(r2), "=r"(r3) : "r"(addr))

#define LDSM_X4_T(r0, r1, r2, r3, addr) \
    asm volatile("ldmatrix.sync.aligned.m8n8.x4.trans.shared.b16 {%0,%1,%2,%3}, [%4];" \
                 : "=r"(r0), "=r"(r1), "=r"(r2), "=r"(r3) : "r"(addr))

#define MMA_F16(c, a, b0, b1) \
    asm volatile("mma.sync.aligned.m16n8k16.row.col.f32.f16.f16.f32 " \
                 "{%0,%1,%2,%3}, {%4,%5,%6,%7}, {%8,%9}, {%0,%1,%2,%3};" \
                 : "+f"((c)[0]), "+f"((c)[1]), "+f"((c)[2]), "+f"((c)[3]) \
                 : "r"((a)[0]), "r"((a)[1]), "r"((a)[2]), "r"((a)[3]), "r"(b0), "r"(b1))

// fast exp2 (args <= 0; -1e30 underflows to 0)
__device__ __forceinline__ float ex2a(float x) {
    float y;
    asm("ex2.approx.ftz.f32 %0, %1;" : "=f"(y) : "f"(x));
    return y;
}

// ---------------------------------------------------------------- scratch
__device__ unsigned g_amax[6];
__device__ double g_invf[32];
__device__ __half g_Wq[DD*NC];                  // quantized q values (exact fp16)
__device__ __half g_Wk[DD*NC];
__device__ __half g_Wv[DD*NC];
__device__ __half g_Wo[NC*DD];
__device__ __half g_Xq[(size_t)MR*DD];
__device__ __half g_Xk[(size_t)MR*DD];
__device__ __half g_Xv[(size_t)MR*DD];
__device__ __half g_q[(size_t)MR*NC];
__device__ __half g_k[(size_t)MR*NC];
__device__ __half g_v[(size_t)MR*NC];
__device__ __half g_z[(size_t)MR*NC];
__device__ float g_bq[NC], g_bk[NC], g_bv[NC];
__device__ float g_sin[SS*32], g_cos[SS*32];

// ---------------------------------------------------------------- qdq
__device__ __forceinline__ float qdq(float w, float amax) {
    float scale = 448.0f / fmaxf(amax, 1e-12f);
    float v = w * scale;
    float a = fabsf(v);
    int ex;
    frexpf(fmaxf(a, 1e-30f), &ex);
    float e = fminf(fmaxf((float)(ex - 1), -6.0f), 8.0f);
    float step = exp2f(e - 3.0f);
    float q = rintf(v / step) * step;
    q = fminf(fmaxf(q, -448.0f), 448.0f);
    return q / scale;
}

// quantize only (returns q; <=5 significant bits -> exact in fp16)
__device__ __forceinline__ float quant_q(float w, float amax) {
    float scale = 448.0f / fmaxf(amax, 1e-12f);
    float v = w * scale;
    float a = fabsf(v);
    int ex;
    frexpf(fmaxf(a, 1e-30f), &ex);
    float e = fminf(fmaxf((float)(ex - 1), -6.0f), 8.0f);
    float step = exp2f(e - 3.0f);
    float q = rintf(v / step) * step;
    return fminf(fmaxf(q, -448.0f), 448.0f);
}

__global__ void reset_kernel() {
    if (threadIdx.x < 6) g_amax[threadIdx.x] = 0u;
    if (threadIdx.x < 32)
        g_invf[threadIdx.x] = pow(10000.0, -(double)threadIdx.x / 32.0);
}

__global__ void amax3_kernel(const float4* __restrict__ a, const float4* __restrict__ b,
                             const float4* __restrict__ c, int n4, int slot0) {
    __shared__ float red[256];
    const float4* x = (blockIdx.y == 0) ? a : (blockIdx.y == 1) ? b : c;
    float m = 0.0f;
    for (int i = blockIdx.x * blockDim.x + threadIdx.x; i < n4; i += gridDim.x * blockDim.x) {
        float4 v = x[i];
        m = fmaxf(m, fmaxf(fmaxf(fabsf(v.x), fabsf(v.y)), fmaxf(fabsf(v.z), fabsf(v.w))));
    }
    red[threadIdx.x] = m;
    __syncthreads();
    for (int s = 128; s > 0; s >>= 1) {
        if (threadIdx.x < s) red[threadIdx.x] = fmaxf(red[threadIdx.x], red[threadIdx.x + s]);
        __syncthreads();
    }
    if (threadIdx.x == 0) atomicMax(&g_amax[slot0 + blockIdx.y], __float_as_uint(red[0]));
}

// batched: quantize + transpose W[h,d,e] -> B[n=h*64+e][k=d] (exact fp16 q)
__global__ void quant_w_t3_kernel(const float* __restrict__ W0, const float* __restrict__ W1,
                                  const float* __restrict__ W2,
                                  __half* __restrict__ B0, __half* __restrict__ B1,
                                  __half* __restrict__ B2) {
    __shared__ float t[32][33];
    int op = blockIdx.y >> 1;
    int ey = blockIdx.y & 1;
    const float* W = (op == 0) ? W0 : (op == 1) ? W1 : W2;
    __half* B = (op == 0) ? B0 : (op == 1) ? B1 : B2;
    float amax = __uint_as_float(g_amax[op]);
    int h = blockIdx.z;
    int d = blockIdx.x * 32 + threadIdx.y;
    int e = ey * 32 + threadIdx.x;
    t[threadIdx.y][threadIdx.x] = quant_q(W[(size_t)h * DD * DHD + d * DHD + e], amax);
    __syncthreads();
    int n = h * DHD + ey * 32 + threadIdx.y;
    int k = blockIdx.x * 32 + threadIdx.x;
    B[(size_t)n * DD + k] = __float2half_rn(t[threadIdx.x][threadIdx.y]);  // exact
}

// transpose WO[he][d] -> B[n=d][k=he], single fp16
__global__ void wo_t_kernel(const float* __restrict__ W, __half* __restrict__ B) {
    __shared__ float t[32][33];
    int he = blockIdx.y * 32 + threadIdx.y;
    int d  = blockIdx.x * 32 + threadIdx.x;
    t[threadIdx.y][threadIdx.x] = W[(size_t)he * DD + d];
    __syncthreads();
    int n = blockIdx.x * 32 + threadIdx.y;
    int k = blockIdx.y * 32 + threadIdx.x;
    B[(size_t)n * NC + k] = __float2half_rn(t[threadIdx.x][threadIdx.y]);
}

// batched bias qdq (fp32 out)
__global__ void quant_b3_kernel(const float* __restrict__ b0, const float* __restrict__ b1,
                                const float* __restrict__ b2,
                                float* __restrict__ o0, float* __restrict__ o1, float* __restrict__ o2) {
    int which = blockIdx.y;
    const float* b = (which == 0) ? b0 : (which == 1) ? b1 : b2;
    float* o = (which == 0) ? o0 : (which == 1) ? o1 : o2;
    int idx = blockIdx.x * 256 + threadIdx.x;
    if (idx >= NC) return;
    float amax = __uint_as_float(g_amax[3 + which]);
    o[idx] = qdq(b[idx], amax);
}

// batched fp32 -> fp16 convert
__global__ void convert3_kernel(const float4* __restrict__ x0, const float4* __restrict__ x1,
                                const float4* __restrict__ x2,
                                __half2* __restrict__ o0, __half2* __restrict__ o1,
                                __half2* __restrict__ o2, int n4) {
    int which = blockIdx.y;
    const float4* x = (which == 0) ? x0 : (which == 1) ? x1 : x2;
    __half2* o = (which == 0) ? o0 : (which == 1) ? o1 : o2;
    int i = blockIdx.x * 256 + threadIdx.x;
    if (i >= n4) return;
    float4 v = x[i];
    o[2*i]   = __halves2half2(__float2half_rn(v.x), __float2half_rn(v.y));
    o[2*i+1] = __halves2half2(__float2half_rn(v.z), __float2half_rn(v.w));
}

// ---------------------------------------------------------------- rotary table
__global__ void sincos_kernel() {
    int idx = blockIdx.x * 256 + threadIdx.x;
    if (idx >= SS * 32) return;
    int pos = idx >> 5, i = idx & 31;
    float invf = (float)g_invf[i];
    float ang  = (float)pos * invf;
    double a = (double)ang;
    double k = rint(a * 0.15915494309189535);
    float r = (float)(a - k * 6.283185307179586);
    g_sin[idx] = sinf(r);
    g_cos[idx] = cosf(r);
}

// ---------------------------------------------------------------- GEMM common
// 2-src stage (A, B), 3-stage cp.async pipeline, 1 MMA pass.
#define KC 32
#define PK 40
#define TILE_B (128 * PK * 2)         // 10240
#define STAGE2_B (2 * TILE_B)         // 20480
#define GEMM2_SMEM (3 * STAGE2_B)     // 61440

__device__ __forceinline__ void store_h2(__half* O, size_t row, int col, float a, float b) {
    __half2 H = __halves2half2(__float2half_rn(a), __float2half_rn(b));
    *(uint32_t*)&O[row * NC + col] = *(uint32_t*)&H;
}

// ---------------------------------------------------------------- fused QKV GEMM
// A = X single fp16, B = exact quantized q values; 1 MMA pass.
// Epilogue: invscale, bias, rotary (Q/K); all outputs single fp16.
struct QKVParams {
    const __half *A[3], *B[3];
    const float* bias[3];
    __half *O[3];
};

__global__ void __launch_bounds__(256) qkv_gemm_kernel(QKVParams P) {
    extern __shared__ char sm[];
    uint32_t sb = smem_u32(sm);
    int tid = threadIdx.x;
    int lane = tid & 31, wid = tid >> 5;
    int wm = wid & 3, wn = wid >> 2;
    int bm = blockIdx.y, bn = blockIdx.x;
    int op = blockIdx.z;

    const char* srcs[2] = {
        (const char*)(P.A[op] + (size_t)bm * 128 * DD),
        (const char*)(P.B[op] + (size_t)bn * 128 * DD) };

    auto fill = [&](int s, int kc) {
        uint32_t base = sb + s * STAGE2_B;
        size_t koff = (size_t)kc * KC * 2;
#pragma unroll
        for (int t = tid; t < 1024; t += 256) {
            int arr = t >> 9;
            int idx = t & 511;
            int row = idx >> 2, c = idx & 3;
            CP_ASYNC16(base + arr * TILE_B + row * (PK * 2) + c * 16,
                       srcs[arr] + (size_t)row * DD * 2 + koff + c * 16);
        }
        CP_COMMIT();
    };

    float acc[2][8][4];
#pragma unroll
    for (int i = 0; i < 2; i++)
#pragma unroll
        for (int j = 0; j < 8; j++)
#pragma unroll
            for (int r = 0; r < 4; r++) acc[i][j][r] = 0.0f;

    int a_row = (lane & 7) + ((lane >> 3) & 1) * 8;
    int a_k   = (lane >> 4) * 8;
    int b_n   = ((lane >> 4) * 8) + (lane & 7);
    int b_k   = ((lane >> 3) & 1) * 8;

    const int nk = DD / KC;
    fill(0, 0);
    fill(1, 1);
    fill(2, 2);

    for (int c = 0; c < nk; c++) {
        if (c + 2 < nk) CP_WAIT2(); else if (c + 1 < nk) CP_WAIT1(); else CP_WAIT0();
        __syncthreads();

        uint32_t stb = sb + (c % 3) * STAGE2_B;
        uint32_t As = stb;
        uint32_t Bs = stb + TILE_B;

#pragma unroll
        for (int kk = 0; kk < 2; kk++) {
            uint32_t af[2][4];
#pragma unroll
            for (int i = 0; i < 2; i++) {
                uint32_t off = ((wm * 32 + i * 16 + a_row) * PK + kk * 16 + a_k) * 2;
                LDSM_X4(af[i][0], af[i][1], af[i][2], af[i][3], As + off);
            }
#pragma unroll
            for (int jj = 0; jj < 4; jj++) {
                uint32_t boff = ((wn * 64 + jj * 16 + b_n) * PK + kk * 16 + b_k) * 2;
                uint32_t bq[4];
                LDSM_X4(bq[0], bq[1], bq[2], bq[3], Bs + boff);
#pragma unroll
                for (int i = 0; i < 2; i++) {
                    MMA_F16(acc[i][2 * jj],     af[i], bq[0], bq[1]);
                    MMA_F16(acc[i][2 * jj + 1], af[i], bq[2], bq[3]);
                }
            }
        }
        __syncthreads();
        if (c + 3 < nk) fill((c + 3) % 3, c + 3);
    }

    const float* bias = P.bias[op];
    __half* O = P.O[op];
    float invscale = fmaxf(__uint_as_float(g_amax[op]), 1e-12f) / 448.0f;

    if (op < 2) {
        float osc = (op == 0) ? 0.125f * LOG2E : 1.0f;
#pragma unroll
        for (int i = 0; i < 2; i++) {
            int r0 = bm * 128 + wm * 32 + i * 16 + (lane >> 2);
            int pos = r0 & (SS - 1);
#pragma unroll
            for (int j = 0; j < 4; j++) {
                int e = j * 8 + (lane & 3) * 2;
                int n0 = bn * 128 + wn * 64 + e;
                float bx0 = bias[n0],      bx1 = bias[n0 + 1];
                float bx2 = bias[n0 + 32], bx3 = bias[n0 + 33];
                float2 c0 = *(const float2*)&g_cos[pos * 32 + e];
                float2 s0 = *(const float2*)&g_sin[pos * 32 + e];
                float2 c8 = *(const float2*)&g_cos[(pos + 8) * 32 + e];
                float2 s8 = *(const float2*)&g_sin[(pos + 8) * 32 + e];
                float x0  = acc[i][j][0] * invscale + bx0,     x0b = acc[i][j][1] * invscale + bx1;
                float x1  = acc[i][j + 4][0] * invscale + bx2, x1b = acc[i][j + 4][1] * invscale + bx3;
                store_h2(O, (size_t)r0, n0,
                         (x0 * c0.x - x1 * s0.x) * osc, (x0b * c0.y - x1b * s0.y) * osc);
                store_h2(O, (size_t)r0, n0 + 32,
                         (x1 * c0.x + x0 * s0.x) * osc, (x1b * c0.y + x0b * s0.y) * osc);
                float u0  = acc[i][j][2] * invscale + bx0,     u0b = acc[i][j][3] * invscale + bx1;
                float u1  = acc[i][j + 4][2] * invscale + bx2, u1b = acc[i][j + 4][3] * invscale + bx3;
                store_h2(O, (size_t)(r0 + 8), n0,
                         (u0 * c8.x - u1 * s8.x) * osc, (u0b * c8.y - u1b * s8.y) * osc);
                store_h2(O, (size_t)(r0 + 8), n0 + 32,
                         (u1 * c8.x + u0 * s8.x) * osc, (u1b * c8.y + u0b * s8.y) * osc);
            }
        }
    } else {
#pragma unroll
        for (int i = 0; i < 2; i++) {
            int r0 = bm * 128 + wm * 32 + i * 16 + (lane >> 2);
#pragma unroll
            for (int j = 0; j < 8; j++) {
                int n0 = bn * 128 + wn * 64 + j * 8 + (lane & 3) * 2;
                float bx = bias[n0], by = bias[n0 + 1];
                store_h2(O, (size_t)r0,       n0, acc[i][j][0] * invscale + bx, acc[i][j][1] * invscale + by);
                store_h2(O, (size_t)(r0 + 8), n0, acc[i][j][2] * invscale + bx, acc[i][j][3] * invscale + by);
            }
        }
    }
}

// ---------------------------------------------------------------- output GEMM
// C = z * Wo^T + bias. 1 MMA pass, 3-stage, fp32 out.
__global__ void __launch_bounds__(256) tgemm_kernel(
        const __half* __restrict__ A, const __half* __restrict__ B,
        const float* __restrict__ bias, float* __restrict__ C,
        int M, int N, int K) {
    extern __shared__ char sm[];
    uint32_t sb = smem_u32(sm);
    int tid = threadIdx.x;
    int lane = tid & 31, wid = tid >> 5;
    int wm = wid & 3, wn = wid >> 2;
    int bm = blockIdx.y, bn = blockIdx.x;

    const char* srcs[2] = {
        (const char*)(A + (size_t)bm * 128 * K),
        (const char*)(B + (size_t)bn * 128 * K) };

    auto fill = [&](int s, int kc) {
        uint32_t base = sb + s * STAGE2_B;
        size_t koff = (size_t)kc * KC * 2;
#pragma unroll
        for (int t = tid; t < 1024; t += 256) {
            int arr = t >> 9;
            int idx = t & 511;
            int row = idx >> 2, c = idx & 3;
            CP_ASYNC16(base + arr * TILE_B + row * (PK * 2) + c * 16,
                       srcs[arr] + (size_t)row * K * 2 + koff + c * 16);
        }
        CP_COMMIT();
    };

    float acc[2][8][4];
#pragma unroll
    for (int i = 0; i < 2; i++)
#pragma unroll
        for (int j = 0; j < 8; j++)
#pragma unroll
            for (int r = 0; r < 4; r++) acc[i][j][r] = 0.0f;

    int a_row = (lane & 7) + ((lane >> 3) & 1) * 8;
    int a_k   = (lane >> 4) * 8;
    int b_n   = ((lane >> 4) * 8) + (lane & 7);
    int b_k   = ((lane >> 3) & 1) * 8;

    int nk = K / KC;
    fill(0, 0);
    fill(1, 1);
    fill(2, 2);

    for (int c = 0; c < nk; c++) {
        if (c + 2 < nk) CP_WAIT2(); else if (c + 1 < nk) CP_WAIT1(); else CP_WAIT0();
        __syncthreads();

        uint32_t stb = sb + (c % 3) * STAGE2_B;
        uint32_t As = stb;
        uint32_t Bs = stb + TILE_B;

#pragma unroll
        for (int kk = 0; kk < 2; kk++) {
            uint32_t af[2][4];
#pragma unroll
            for (int i = 0; i < 2; i++) {
                uint32_t off = ((wm * 32 + i * 16 + a_row) * PK + kk * 16 + a_k) * 2;
                LDSM_X4(af[i][0], af[i][1], af[i][2], af[i][3], As + off);
            }
#pragma unroll
            for (int jj = 0; jj < 4; jj++) {
                uint32_t boff = ((wn * 64 + jj * 16 + b_n) * PK + kk * 16 + b_k) * 2;
                uint32_t bq[4];
                LDSM_X4(bq[0], bq[1], bq[2], bq[3], Bs + boff);
#pragma unroll
                for (int i = 0; i < 2; i++) {
                    MMA_F16(acc[i][2 * jj],     af[i], bq[0], bq[1]);
                    MMA_F16(acc[i][2 * jj + 1], af[i], bq[2], bq[3]);
                }
            }
        }
        __syncthreads();
        if (c + 3 < nk) fill((c + 3) % 3, c + 3);
    }

#pragma unroll
    for (int i = 0; i < 2; i++) {
        int r0 = bm * 128 + wm * 32 + i * 16 + (lane >> 2);
#pragma unroll
        for (int j = 0; j < 8; j++) {
            int c0 = bn * 128 + wn * 64 + j * 8 + (lane & 3) * 2;
            float bx = bias[c0], by = bias[c0 + 1];
            float2 v0 = make_float2(acc[i][j][0] + bx, acc[i][j][1] + by);
            float2 v1 = make_float2(acc[i][j][2] + bx, acc[i][j][3] + by);
            *(float2*)&C[(size_t)r0 * N + c0] = v0;
            *(float2*)&C[(size_t)(r0 + 8) * N + c0] = v1;
        }
    }
}

// ---------------------------------------------------------------- tensor-core flash attention
// All-single fp16: 1-pass QK, 1-pass PV. q pre-scaled by 0.125*log2e.
#define APD 72
#define QT_B (128 * APD * 2)          // 18432
#define KT_B (64 * APD * 2)           // 9216
#define KV_STAGE (2 * KT_B)           // 18432 (K + V)
#define AT_SMEM (QT_B + 2 * KV_STAGE) // 55296

__global__ void __launch_bounds__(256) attn_tc_kernel(
        const __half* __restrict__ Q,
        const __half* __restrict__ K, const __half* __restrict__ V,
        __half* __restrict__ Z) {
    extern __shared__ char sm[];
    uint32_t sb = smem_u32(sm);
    int tid = threadIdx.x, lane = tid & 31, wid = tid >> 5;

    int qt = (SS / 128 - 1) - blockIdx.x;   // heavy tiles first
    int h = blockIdx.y, b = blockIdx.z;
    int q0 = qt * 128;
    int nt = qt * 2 + 2;

    const char* gQ = (const char*)(Q + ((size_t)b * SS + q0) * NC + h * DHD);
    const char* gKV[2] = {
        (const char*)(K + (size_t)b * SS * NC + h * DHD),
        (const char*)(V + (size_t)b * SS * NC + h * DHD) };

    auto fillKV = [&](int s, int kt) {
        uint32_t base = sb + QT_B + s * KV_STAGE;
        size_t roff = (size_t)(kt * 64) * (NC * 2);
#pragma unroll
        for (int t = tid; t < 1024; t += 256) {
            int arr = t >> 9, idx = t & 511;
            int row = idx >> 3, c = idx & 7;
            CP_ASYNC16(base + arr * KT_B + row * 144 + c * 16,
                       gKV[arr] + roff + (size_t)row * (NC * 2) + c * 16);
        }
        CP_COMMIT();
    };

#pragma unroll
    for (int t = tid; t < 1024; t += 256) {
        int row = t >> 3, c = t & 7;
        CP_ASYNC16(sb + row * 144 + c * 16,
                   gQ + (size_t)row * (NC * 2) + c * 16);
    }
    fillKV(0, 0);

    float zacc[8][4];
#pragma unroll
    for (int j = 0; j < 8; j++)
#pragma unroll
        for (int r = 0; r < 4; r++) zacc[j][r] = 0.0f;
    float m0 = -1e30f, m1 = -1e30f, l0 = 0.0f, l1 = 0.0f;

    int a_row = (lane & 7) + ((lane >> 3) & 1) * 8;
    int a_k   = (lane >> 4) * 8;
    int b_n   = ((lane >> 4) * 8) + (lane & 7);
    int b_k   = ((lane >> 3) & 1) * 8;
    int v_r   = lane & 15;
    int v_c   = (lane >> 4) * 8;

    CP_WAIT0();
    __syncthreads();

    uint32_t q_f[4][4];
#pragma unroll
    for (int kc = 0; kc < 4; kc++) {
        uint32_t off = (wid * 16 + a_row) * 144 + (kc * 16 + a_k) * 2;
        LDSM_X4(q_f[kc][0], q_f[kc][1], q_f[kc][2], q_f[kc][3], sb + off);
    }

    int rbase = q0 + wid * 16 + (lane >> 2);

    for (int t = 0; t < nt; t++) {
        if (t + 1 < nt) fillKV((t + 1) & 1, t + 1);

        uint32_t sbK = sb + QT_B + (t & 1) * KV_STAGE;
        int k0 = t * 64;

        float s[8][4];
#pragma unroll
        for (int j = 0; j < 8; j++)
#pragma unroll
            for (int r = 0; r < 4; r++) s[j][r] = 0.0f;

#pragma unroll
        for (int kc = 0; kc < 4; kc++) {
#pragma unroll
            for (int jj = 0; jj < 4; jj++) {
                uint32_t boff = (jj * 16 + b_n) * 144 + (kc * 16 + b_k) * 2;
                uint32_t kf[4];
                LDSM_X4(kf[0], kf[1], kf[2], kf[3], sbK + boff);
                MMA_F16(s[2 * jj],     q_f[kc], kf[0], kf[1]);
                MMA_F16(s[2 * jj + 1], q_f[kc], kf[2], kf[3]);
            }
        }

        if (k0 + 63 > q0 + wid * 16) {
#pragma unroll
            for (int j = 0; j < 8; j++) {
                int kg = k0 + j * 8 + (lane & 3) * 2;
                if (kg > rbase)         s[j][0] = -1e30f;
                if (kg + 1 > rbase)     s[j][1] = -1e30f;
                if (kg > rbase + 8)     s[j][2] = -1e30f;
                if (kg + 1 > rbase + 8) s[j][3] = -1e30f;
            }
        }

        float rm0 = -1e30f, rm1 = -1e30f;
#pragma unroll
        for (int j = 0; j < 8; j++) {
            rm0 = fmaxf(rm0, fmaxf(s[j][0], s[j][1]));
            rm1 = fmaxf(rm1, fmaxf(s[j][2], s[j][3]));
        }
        rm0 = fmaxf(rm0, __shfl_xor_sync(0xffffffffu, rm0, 1));
        rm0 = fmaxf(rm0, __shfl_xor_sync(0xffffffffu, rm0, 2));
        rm1 = fmaxf(rm1, __shfl_xor_sync(0xffffffffu, rm1, 1));
        rm1 = fmaxf(rm1, __shfl_xor_sync(0xffffffffu, rm1, 2));
        float mn0 = fmaxf(m0, rm0), mn1 = fmaxf(m1, rm1);
        float cr0 = ex2a(m0 - mn0), cr1 = ex2a(m1 - mn1);
        float rs0 = 0.0f, rs1 = 0.0f;
#pragma unroll
        for (int j = 0; j < 8; j++) {
            s[j][0] = ex2a(s[j][0] - mn0);
            s[j][1] = ex2a(s[j][1] - mn0);
            s[j][2] = ex2a(s[j][2] - mn1);
            s[j][3] = ex2a(s[j][3] - mn1);
            rs0 += s[j][0] + s[j][1];
            rs1 += s[j][2] + s[j][3];
        }
        rs0 += __shfl_xor_sync(0xffffffffu, rs0, 1);
        rs0 += __shfl_xor_sync(0xffffffffu, rs0, 2);
        rs1 += __shfl_xor_sync(0xffffffffu, rs1, 1);
        rs1 += __shfl_xor_sync(0xffffffffu, rs1, 2);
        l0 = l0 * cr0 + rs0; l1 = l1 * cr1 + rs1;
        m0 = mn0; m1 = mn1;
#pragma unroll
        for (int j = 0; j < 8; j++) {
            zacc[j][0] *= cr0; zacc[j][1] *= cr0;
            zacc[j][2] *= cr1; zacc[j][3] *= cr1;
        }

        // P -> fp16 A-fragments (single)
        uint32_t pf[4][4];
#pragma unroll
        for (int kc = 0; kc < 4; kc++) {
#pragma unroll
            for (int half = 0; half < 2; half++) {
                int j = 2 * kc + half;
                __half2 H01 = __halves2half2(__float2half_rn(s[j][0]), __float2half_rn(s[j][1]));
                __half2 H23 = __halves2half2(__float2half_rn(s[j][2]), __float2half_rn(s[j][3]));
                pf[kc][half * 2]     = *(uint32_t*)&H01;
                pf[kc][half * 2 + 1] = *(uint32_t*)&H23;
            }
        }

#pragma unroll
        for (int kc = 0; kc < 4; kc++) {
#pragma unroll
            for (int jj = 0; jj < 4; jj++) {
                uint32_t voff = (kc * 16 + v_r) * 144 + (jj * 16 + v_c) * 2;
                uint32_t vf[4];
                LDSM_X4_T(vf[0], vf[1], vf[2], vf[3], sbK + KT_B + voff);
                MMA_F16(zacc[2 * jj],     pf[kc], vf[0], vf[1]);
                MMA_F16(zacc[2 * jj + 1], pf[kc], vf[2], vf[3]);
            }
        }

        if (t + 1 < nt) {
            CP_WAIT0();
            __syncthreads();
        }
    }

    float inv0 = 1.0f / l0, inv1 = 1.0f / l1;
    size_t row0 = (size_t)b * SS + q0 + wid * 16 + (lane >> 2);
#pragma unroll
    for (int j = 0; j < 8; j++) {
        int col = h * DHD + j * 8 + (lane & 3) * 2;
        store_h2(Z, row0,     col, zacc[j][0] * inv0, zacc[j][1] * inv0);
        store_h2(Z, row0 + 8, col, zacc[j][2] * inv1, zacc[j][3] * inv1);
    }
}

// ---------------------------------------------------------------- launch
extern "C" void kernel_launch(void* const* d_in, const int* in_sizes, int n_in,
                              void* d_out, int out_size) {
    const float* Xq  = (const float*)d_in[0];
    const float* Xk  = (const float*)d_in[1];
    const float* Xv  = (const float*)d_in[2];
    const float* WQ  = (const float*)d_in[3];
    const float* WK  = (const float*)d_in[4];
    const float* WV  = (const float*)d_in[5];
    const float* WO  = (const float*)d_in[6];
    const float* bQ  = (const float*)d_in[7];
    const float* bK  = (const float*)d_in[8];
    const float* bV  = (const float*)d_in[9];
    const float* bO  = (const float*)d_in[10];
    float* out = (float*)d_out;

    static bool init = false;
    static __half *pWq, *pWk, *pWv, *pWo;
    static __half *pXq, *pXk, *pXv, *pz;
    static __half *pq, *pk, *pv;
    static float *pbq, *pbk, *pbv;
    if (!init) {
        cudaGetSymbolAddress((void**)&pWq, g_Wq);
        cudaGetSymbolAddress((void**)&pWk, g_Wk);
        cudaGetSymbolAddress((void**)&pWv, g_Wv);
        cudaGetSymbolAddress((void**)&pWo, g_Wo);
        cudaGetSymbolAddress((void**)&pXq, g_Xq);
        cudaGetSymbolAddress((void**)&pXk, g_Xk);
        cudaGetSymbolAddress((void**)&pXv, g_Xv);
        cudaGetSymbolAddress((void**)&pz,  g_z);
        cudaGetSymbolAddress((void**)&pq, g_q);
        cudaGetSymbolAddress((void**)&pk, g_k);
        cudaGetSymbolAddress((void**)&pv, g_v);
        cudaGetSymbolAddress((void**)&pbq, g_bq); cudaGetSymbolAddress((void**)&pbk, g_bk);
        cudaGetSymbolAddress((void**)&pbv, g_bv);
        cudaFuncSetAttribute(tgemm_kernel, cudaFuncAttributeMaxDynamicSharedMemorySize, GEMM2_SMEM);
        cudaFuncSetAttribute(qkv_gemm_kernel, cudaFuncAttributeMaxDynamicSharedMemorySize, GEMM2_SMEM);
        cudaFuncSetAttribute(attn_tc_kernel, cudaFuncAttributeMaxDynamicSharedMemorySize, AT_SMEM);
        init = true;
    }

    // 1) amax + invf table
    reset_kernel<<<1, 32>>>();
    amax3_kernel<<<dim3(256, 3), 256>>>((const float4*)WQ, (const float4*)WK, (const float4*)WV, WN / 4, 0);
    amax3_kernel<<<dim3(1, 3), 256>>>((const float4*)bQ, (const float4*)bK, (const float4*)bV, NC / 4, 3);

    // 2) rotary table
    sincos_kernel<<<SS * 32 / 256, 256>>>();

    // 3) weight quantize (exact fp16) + transpose; WO single; bias qdq
    quant_w_t3_kernel<<<dim3(DD / 32, 6, HH), dim3(32, 32)>>>(WQ, WK, WV, pWq, pWk, pWv);
    wo_t_kernel<<<dim3(DD / 32, NC / 32), dim3(32, 32)>>>(WO, pWo);
    quant_b3_kernel<<<dim3(4, 3), 256>>>(bQ, bK, bV, pbq, pbk, pbv);

    // 4) input convert fp32 -> fp16
    int n4 = (MR * DD) / 4;
    convert3_kernel<<<dim3((n4 + 255) / 256, 3), 256>>>(
        (const float4*)Xq, (const float4*)Xk, (const float4*)Xv,
        (__half2*)pXq, (__half2*)pXk, (__half2*)pXv, n4);

    // 5) fused QKV projection (1-pass) + invscale + bias + rotary; all single fp16
    QKVParams P;
    P.A[0] = pXq; P.B[0] = pWq; P.bias[0] = pbq; P.O[0] = pq;
    P.A[1] = pXk; P.B[1] = pWk; P.bias[1] = pbk; P.O[1] = pk;
    P.A[2] = pXv; P.B[2] = pWv; P.bias[2] = pbv; P.O[2] = pv;
    qkv_gemm_kernel<<<dim3(NC / 128, MR / 128, 3), 256, GEMM2_SMEM>>>(P);

    // 6) tensor-core flash attention (1-pass QK, 1-pass PV) -> z single
    dim3 ag(SS / 128, HH, BB);
    attn_tc_kernel<<<ag, 256, AT_SMEM>>>(pq, pk, pv, pz);

    // 7) output projection (1-pass)
    dim3 gg(DD / 128, MR / 128);
    tgemm_kernel<<<gg, 256, GEMM2_SMEM>>>(pz, pWo, bO, out, MR, DD, NC);
}